// round 1
// baseline (speedup 1.0000x reference)
#include <cuda_runtime.h>
#include <math.h>

// ---------------------------------------------------------------------------
// Problem constants
// ---------------------------------------------------------------------------
#define HW     4096          // 64*64
#define NB     8
#define OUT_A_ELEMS (8 * 256 * 4096)   // "a" output
// output layout: a [8,256,64,64] followed by w [8,256]

// ---------------------------------------------------------------------------
// Scratch (static device globals -- no allocation allowed)
// ---------------------------------------------------------------------------
__device__ float g_txup[8 * 256 * 4096];   // upsampled tx          33.5 MB
__device__ float g_sum [8 * 256];          // stage-A GAP accumulator
__device__ float g_w   [8 * 256];          // normalized channel weights
__device__ float g_b1  [8 * 256 * 4096];   // relu(W_U@sx2)*w       33.5 MB
__device__ float g_b2  [8 * 128 * 4096];   // relu(W_V@b1)          16.8 MB
__device__ float g_a1  [8 * 128 * 4096];   // relu(W_a1@bcat)       16.8 MB
__device__ float g_apod[8 * 640 * 4096];   // sigmoid(...)*bcat     83.9 MB

// ---------------------------------------------------------------------------
// Kernel 1: bilinear upsample x2, align_corners=True  (32x32 -> 64x64)
// one block per (n,c) plane
// ---------------------------------------------------------------------------
__global__ __launch_bounds__(256) void upsample_k(const float* __restrict__ tx)
{
    __shared__ float s[1024];
    const int bc = blockIdx.x;                 // n*256 + c
    const float* src = tx + (size_t)bc * 1024;
    for (int idx = threadIdx.x; idx < 1024; idx += 256) s[idx] = src[idx];
    __syncthreads();

    float* dst = g_txup + (size_t)bc * 4096;
    const float step = 31.0f / 63.0f;
#pragma unroll
    for (int rpt = 0; rpt < 16; rpt++) {
        int opix = rpt * 256 + threadIdx.x;
        int y = opix >> 6, x = opix & 63;
        float fy = y * step;  int y0 = (int)fy;  float wy = fy - y0;
        int y1 = min(y0 + 1, 31);
        float fx = x * step;  int x0 = (int)fx;  float wx = fx - x0;
        int x1 = min(x0 + 1, 31);
        float top = s[y0 * 32 + x0] * (1.f - wx) + s[y0 * 32 + x1] * wx;
        float bot = s[y1 * 32 + x0] * (1.f - wx) + s[y1 * 32 + x1] * wx;
        dst[opix] = top * (1.f - wy) + bot * wy;
    }
}

// ---------------------------------------------------------------------------
// Kernel 2: zero the GAP accumulator
// ---------------------------------------------------------------------------
__global__ void zero_sum_k()
{
    g_sum[blockIdx.x * 256 + threadIdx.x] = 0.f;
}

// ---------------------------------------------------------------------------
// Generic tiled 1x1-conv GEMM body.
//   block = 256 threads, 32 pixels x OCTILE output channels
//   thread = RO output channels x 4 pixels (RO = OCTILE/32)
//   K loop in chunks of 16, weights + activations staged in smem.
// Input channels gathered virtually from up to 3 sources (concat support).
// MODE 0: relu(acc+b), sum over pixels, atomicAdd into out[n*256+oc]  (stage A)
// MODE 1: relu(acc+b) * scale[n*256+oc] -> out                        (b1)
// MODE 2: relu(acc+b) -> out                                          (b2, a1)
// MODE 3: sigmoid(acc+b) * bcat_gather(e0|e1|e2) -> out               (a2 * bcat)
// ---------------------------------------------------------------------------
template<int CIN, int OCTILE, int MODE>
__device__ __forceinline__ void conv1x1_body(
    const float* __restrict__ s0, int c0,
    const float* __restrict__ s1, int c1,
    const float* __restrict__ s2,
    const float* __restrict__ W,
    const float* __restrict__ bias,
    const float* __restrict__ scale,
    const float* __restrict__ e0,
    const float* __restrict__ e1,
    const float* __restrict__ e2,
    float* __restrict__ out)
{
    constexpr int RO = OCTILE / 32;
    __shared__ __align__(16) float Wc[OCTILE * 17];
    __shared__ __align__(16) float Xc[16 * 32];

    const int tid = threadIdx.x;
    const int n   = blockIdx.z;
    const int p0  = blockIdx.x * 32;
    const int ocb = blockIdx.y * OCTILE;
    const int COUT = gridDim.y * OCTILE;
    const int c2 = CIN - c0 - c1;
    const int tx8 = tid & 7, ty = tid >> 3;

    float acc[RO][4];
#pragma unroll
    for (int j = 0; j < RO; j++) {
        acc[j][0] = 0.f; acc[j][1] = 0.f; acc[j][2] = 0.f; acc[j][3] = 0.f;
    }

    for (int k0 = 0; k0 < CIN; k0 += 16) {
        // stage weight chunk: [OCTILE][16]
#pragma unroll
        for (int idx = tid; idx < OCTILE * 16; idx += 256) {
            int oc = idx >> 4, k = idx & 15;
            Wc[oc * 17 + k] = W[(size_t)(ocb + oc) * CIN + k0 + k];
        }
        // stage activation chunk: [16][32] gathered from concat sources
#pragma unroll
        for (int idx = tid; idx < 512; idx += 256) {
            int k = idx >> 5, px = idx & 31;
            int c = k0 + k;
            float v;
            if (c < c0)
                v = s0[((size_t)n * c0 + c) * HW + p0 + px];
            else if (c < c0 + c1)
                v = s1[((size_t)n * c1 + (c - c0)) * HW + p0 + px];
            else
                v = s2[((size_t)n * c2 + (c - c0 - c1)) * HW + p0 + px];
            Xc[k * 32 + px] = v;
        }
        __syncthreads();

#pragma unroll
        for (int k = 0; k < 16; k++) {
            float4 xv = *reinterpret_cast<const float4*>(&Xc[k * 32 + tx8 * 4]);
#pragma unroll
            for (int j = 0; j < RO; j++) {
                float wv = Wc[(ty * RO + j) * 17 + k];
                acc[j][0] = fmaf(wv, xv.x, acc[j][0]);
                acc[j][1] = fmaf(wv, xv.y, acc[j][1]);
                acc[j][2] = fmaf(wv, xv.z, acc[j][2]);
                acc[j][3] = fmaf(wv, xv.w, acc[j][3]);
            }
        }
        __syncthreads();
    }

    // epilogue
    if (MODE == 0) {
#pragma unroll
        for (int j = 0; j < RO; j++) {
            int oc = ty * RO + j;
            float bz = bias[ocb + oc];
            float s = fmaxf(acc[j][0] + bz, 0.f) + fmaxf(acc[j][1] + bz, 0.f)
                    + fmaxf(acc[j][2] + bz, 0.f) + fmaxf(acc[j][3] + bz, 0.f);
            s += __shfl_xor_sync(0xffffffffu, s, 1);
            s += __shfl_xor_sync(0xffffffffu, s, 2);
            s += __shfl_xor_sync(0xffffffffu, s, 4);
            if (tx8 == 0) atomicAdd(&out[n * 256 + ocb + oc], s);
        }
    } else {
#pragma unroll
        for (int j = 0; j < RO; j++) {
            int goc = ocb + ty * RO + j;
            float bz = bias[goc];
            float v0 = acc[j][0] + bz, v1 = acc[j][1] + bz;
            float v2 = acc[j][2] + bz, v3 = acc[j][3] + bz;
            float4 r;
            if (MODE == 1) {
                float sc = scale[n * 256 + goc];
                r.x = fmaxf(v0, 0.f) * sc; r.y = fmaxf(v1, 0.f) * sc;
                r.z = fmaxf(v2, 0.f) * sc; r.w = fmaxf(v3, 0.f) * sc;
            } else if (MODE == 2) {
                r.x = fmaxf(v0, 0.f); r.y = fmaxf(v1, 0.f);
                r.z = fmaxf(v2, 0.f); r.w = fmaxf(v3, 0.f);
            } else { // MODE 3
                float sg0 = 1.f / (1.f + expf(-v0));
                float sg1 = 1.f / (1.f + expf(-v1));
                float sg2 = 1.f / (1.f + expf(-v2));
                float sg3 = 1.f / (1.f + expf(-v3));
                const float* bp;
                if (goc < 128)       bp = e0 + ((size_t)n * 128 + goc) * HW;
                else if (goc < 384)  bp = e1 + ((size_t)n * 256 + (goc - 128)) * HW;
                else                 bp = e2 + ((size_t)n * 256 + (goc - 384)) * HW;
                int pix = p0 + tx8 * 4;
                r.x = sg0 * bp[pix + 0]; r.y = sg1 * bp[pix + 1];
                r.z = sg2 * bp[pix + 2]; r.w = sg3 * bp[pix + 3];
            }
            *reinterpret_cast<float4*>(
                &out[((size_t)n * COUT + goc) * HW + p0 + tx8 * 4]) = r;
        }
    }
}

// ----- thin wrappers binding global scratch ---------------------------------
__global__ __launch_bounds__(256) void k_stageA(
    const float* __restrict__ sx1, const float* __restrict__ t_hx,
    const float* __restrict__ W, const float* __restrict__ bias)
{
    conv1x1_body<768, 256, 0>(sx1, 256, t_hx, 256, g_txup,
                              W, bias, nullptr, nullptr, nullptr, nullptr, g_sum);
}

__global__ __launch_bounds__(256) void k_b1(
    const float* __restrict__ sx2,
    const float* __restrict__ W, const float* __restrict__ bias)
{
    conv1x1_body<256, 256, 1>(sx2, 256, nullptr, 0, nullptr,
                              W, bias, g_w, nullptr, nullptr, nullptr, g_b1);
}

__global__ __launch_bounds__(256) void k_b2(
    const float* __restrict__ W, const float* __restrict__ bias)
{
    conv1x1_body<256, 128, 2>(g_b1, 256, nullptr, 0, nullptr,
                              W, bias, nullptr, nullptr, nullptr, nullptr, g_b2);
}

__global__ __launch_bounds__(256) void k_a1(
    const float* __restrict__ t_hx,
    const float* __restrict__ W, const float* __restrict__ bias)
{
    conv1x1_body<640, 128, 2>(g_b2, 128, t_hx, 256, g_txup,
                              W, bias, nullptr, nullptr, nullptr, nullptr, g_a1);
}

__global__ __launch_bounds__(256) void k_a2(
    const float* __restrict__ t_hx,
    const float* __restrict__ W, const float* __restrict__ bias)
{
    conv1x1_body<128, 128, 3>(g_a1, 128, nullptr, 0, nullptr,
                              W, bias, nullptr, g_b2, t_hx, g_txup, g_apod);
}

// ---------------------------------------------------------------------------
// Kernel: head (squeeze-excite MLP + L2 normalize). One block per sample.
// Also writes the "w" output tail.
// ---------------------------------------------------------------------------
__global__ __launch_bounds__(256) void head_k(
    const float* __restrict__ Wt2, const float* __restrict__ Wt3,
    float* __restrict__ outw)
{
    const int n = blockIdx.x, tid = threadIdx.x;
    __shared__ float w1[256], w2[64], red[256];

    w1[tid] = g_sum[n * 256 + tid] * (1.f / 4096.f);
    __syncthreads();

    if (tid < 64) {
        float s = 0.f;
#pragma unroll 8
        for (int k = 0; k < 256; k++) s = fmaf(Wt2[tid * 256 + k], w1[k], s);
        w2[tid] = fmaxf(s, 0.f);
    }
    __syncthreads();

    float s = 0.f;
#pragma unroll
    for (int e = 0; e < 64; e++) s = fmaf(Wt3[tid * 64 + e], w2[e], s);

    red[tid] = s * s;
    __syncthreads();
    for (int off = 128; off > 0; off >>= 1) {
        if (tid < off) red[tid] += red[tid + off];
        __syncthreads();
    }
    float nv = sqrtf(red[0]);
    float wv = s / fmaxf(nv, 1e-12f);
    g_w[n * 256 + tid] = wv;
    outw[n * 256 + tid] = wv;
}

// ---------------------------------------------------------------------------
// Kernel: 3x3 conv 640->256, pad 1, relu.
//   block: 64 output channels x (2 rows x 64 px), 256 threads
//   thread: 4 oc x 8 px register tile -> FMA-issue bound
//   K loop: 8 input channels per chunk; input rows + weights staged in smem
// ---------------------------------------------------------------------------
__global__ __launch_bounds__(256) void conv3_k(
    const float* __restrict__ Wot, const float* __restrict__ bot,
    float* __restrict__ out)
{
    __shared__ float Sin[8][4][68];    // [cin][row][x+1]
    __shared__ float Wc[64 * 73];      // [oc][cin*9+k], padded pitch

    const int tid = threadIdx.x;
    const int n   = blockIdx.z;
    const int ocb = blockIdx.y * 64;
    const int y0  = blockIdx.x * 2;

    const int g  = tid & 15;           // pixel group
    const int ty = tid >> 4;           // oc group (0..15)
    const int r  = g >> 3;             // row within tile (0..1)
    const int xb = (g & 7) * 8;        // x base (0..56)

    float acc[4][8];
#pragma unroll
    for (int j = 0; j < 4; j++)
#pragma unroll
        for (int i = 0; i < 8; i++) acc[j][i] = 0.f;

    const float* ap = g_apod + (size_t)n * 640 * HW;

    for (int cc = 0; cc < 640; cc += 8) {
        // stage input: 8 ch x 4 rows (y0-1..y0+2) x 66 (x=-1..64), zero-padded
        for (int idx = tid; idx < 8 * 4 * 66; idx += 256) {
            int c   = idx / 264;
            int rem = idx - c * 264;
            int rr  = rem / 66;
            int xx  = rem - rr * 66 - 1;
            int iy  = y0 - 1 + rr;
            float v = 0.f;
            if ((unsigned)iy < 64u && (unsigned)xx < 64u)
                v = ap[(size_t)(cc + c) * HW + iy * 64 + xx];
            Sin[c][rr][xx + 1] = v;
        }
        // stage weights: 64 oc x (8 cin * 9) contiguous per oc
        for (int idx = tid; idx < 64 * 72; idx += 256) {
            int oc = idx / 72, q = idx - oc * 72;
            Wc[oc * 73 + q] = Wot[(size_t)(ocb + oc) * 5760 + cc * 9 + q];
        }
        __syncthreads();

#pragma unroll
        for (int c = 0; c < 8; c++) {
#pragma unroll
            for (int ky = 0; ky < 3; ky++) {
                float xs[10];
#pragma unroll
                for (int i = 0; i < 10; i++) xs[i] = Sin[c][r + ky][xb + i];
#pragma unroll
                for (int kx = 0; kx < 3; kx++) {
#pragma unroll
                    for (int j = 0; j < 4; j++) {
                        float wv = Wc[(ty * 4 + j) * 73 + c * 9 + ky * 3 + kx];
#pragma unroll
                        for (int i = 0; i < 8; i++)
                            acc[j][i] = fmaf(wv, xs[kx + i], acc[j][i]);
                    }
                }
            }
        }
        __syncthreads();
    }

    const int oy = y0 + r;
#pragma unroll
    for (int j = 0; j < 4; j++) {
        int oc = ocb + ty * 4 + j;
        float bv = bot[oc];
        float4 lo, hi;
        lo.x = fmaxf(acc[j][0] + bv, 0.f); lo.y = fmaxf(acc[j][1] + bv, 0.f);
        lo.z = fmaxf(acc[j][2] + bv, 0.f); lo.w = fmaxf(acc[j][3] + bv, 0.f);
        hi.x = fmaxf(acc[j][4] + bv, 0.f); hi.y = fmaxf(acc[j][5] + bv, 0.f);
        hi.z = fmaxf(acc[j][6] + bv, 0.f); hi.w = fmaxf(acc[j][7] + bv, 0.f);
        float* op = out + ((size_t)(n * 256 + oc) * 64 + oy) * 64 + xb;
        *reinterpret_cast<float4*>(op)     = lo;
        *reinterpret_cast<float4*>(op + 4) = hi;
    }
}

// ---------------------------------------------------------------------------
// Launch
// ---------------------------------------------------------------------------
extern "C" void kernel_launch(void* const* d_in, const int* in_sizes, int n_in,
                              void* d_out, int out_size)
{
    const float* sx1  = (const float*)d_in[0];
    const float* sx2  = (const float*)d_in[1];
    const float* t_hx = (const float*)d_in[2];
    const float* tx   = (const float*)d_in[3];
    const float* W_t1 = (const float*)d_in[4];
    const float* b_t1 = (const float*)d_in[5];
    const float* W_t2 = (const float*)d_in[6];
    const float* W_t3 = (const float*)d_in[7];
    const float* W_U  = (const float*)d_in[8];
    const float* b_U  = (const float*)d_in[9];
    const float* W_V  = (const float*)d_in[10];
    const float* b_V  = (const float*)d_in[11];
    const float* W_a1 = (const float*)d_in[12];
    const float* b_a1 = (const float*)d_in[13];
    const float* W_a2 = (const float*)d_in[14];
    const float* b_a2 = (const float*)d_in[15];
    const float* W_ot = (const float*)d_in[16];
    const float* b_ot = (const float*)d_in[17];
    float* out = (float*)d_out;

    // 1. upsample tx -> g_txup
    upsample_k<<<2048, 256>>>(tx);
    // 2. zero GAP accumulator
    zero_sum_k<<<8, 256>>>();
    // 3. stage A: relu(W_t1 @ [sx1;t_hx;txup] + b_t1), GAP -> g_sum
    k_stageA<<<dim3(128, 1, 8), 256>>>(sx1, t_hx, W_t1, b_t1);
    // 4. head MLP + L2 normalize -> g_w, writes w output tail
    head_k<<<8, 256>>>(W_t2, W_t3, out + OUT_A_ELEMS);
    // 5. b1 = relu(W_U @ sx2 + b_U) * w
    k_b1<<<dim3(128, 1, 8), 256>>>(sx2, W_U, b_U);
    // 6. b2 = relu(W_V @ b1 + b_V)
    k_b2<<<dim3(128, 1, 8), 256>>>(W_V, b_V);
    // 7. a1 = relu(W_a1 @ [b2;t_hx;txup] + b_a1)
    k_a1<<<dim3(128, 1, 8), 256>>>(t_hx, W_a1, b_a1);
    // 8. apod = sigmoid(W_a2 @ a1 + b_a2) * [b2;t_hx;txup]
    k_a2<<<dim3(128, 5, 8), 256>>>(t_hx, W_a2, b_a2);
    // 9. a = relu(conv3x3(apod, W_ot) + b_ot) -> main output
    conv3_k<<<dim3(32, 4, 8), 256>>>(W_ot, b_ot, out);
}

// round 5
// speedup vs baseline: 1.3750x; 1.3750x over previous
#include <cuda_runtime.h>
#include <cuda_bf16.h>
#include <math.h>
#include <stdint.h>

// ---------------------------------------------------------------------------
// Problem constants
// ---------------------------------------------------------------------------
#define HW     4096          // 64*64
#define NB     8
#define OUT_A_ELEMS (8 * 256 * 4096)   // "a" output
// output layout: a [8,256,64,64] followed by w [8,256]

// ---------------------------------------------------------------------------
// Scratch (static device globals -- no allocation allowed)
// ---------------------------------------------------------------------------
__device__ float g_txup[8 * 256 * 4096];   // upsampled tx          33.5 MB
__device__ float g_sum [8 * 256];          // stage-A GAP accumulator
__device__ float g_w   [8 * 256];          // normalized channel weights
__device__ float g_b1  [8 * 256 * 4096];   // relu(W_U@sx2)*w       33.5 MB
__device__ float g_b2  [8 * 128 * 4096];   // relu(W_V@b1)          16.8 MB
__device__ float g_a1  [8 * 128 * 4096];   // relu(W_a1@bcat)       16.8 MB
__device__ float g_apod[8 * 640 * 4096];   // sigmoid(...)*bcat     83.9 MB

// bf16 hi/lo splits for the tensor-core conv3x3
__device__ __align__(16) __nv_bfloat16 g_aT_h[8ULL * 4096 * 640]; // act chan-last hi
__device__ __align__(16) __nv_bfloat16 g_aT_l[8ULL * 4096 * 640]; // act chan-last lo
__device__ __align__(16) __nv_bfloat16 g_wh[256 * 5760];          // weights tap-major hi
__device__ __align__(16) __nv_bfloat16 g_wl[256 * 5760];          // weights tap-major lo

// ---------------------------------------------------------------------------
// helpers
// ---------------------------------------------------------------------------
__device__ __forceinline__ uint32_t smem_to_u32(const void* p) {
    uint32_t a;
    asm("{ .reg .u64 t; cvta.to.shared.u64 t, %1; cvt.u32.u64 %0, t; }"
        : "=r"(a) : "l"(p));
    return a;
}

__device__ __forceinline__ void cp16(uint32_t dst, const void* src, uint32_t bytes) {
    asm volatile("cp.async.cg.shared.global [%0], [%1], 16, %2;"
                 :: "r"(dst), "l"(src), "r"(bytes) : "memory");
}
__device__ __forceinline__ void cp_commit() {
    asm volatile("cp.async.commit_group;" ::: "memory");
}
template<int N>
__device__ __forceinline__ void cp_wait() {
    asm volatile("cp.async.wait_group %0;" :: "n"(N) : "memory");
}

__device__ __forceinline__ void ldm_x4(uint32_t (&r)[4], uint32_t addr) {
    asm volatile("ldmatrix.sync.aligned.m8n8.x4.shared.b16 {%0,%1,%2,%3}, [%4];"
                 : "=r"(r[0]), "=r"(r[1]), "=r"(r[2]), "=r"(r[3]) : "r"(addr));
}

__device__ __forceinline__ void mma_bf16(float (&c)[4], const uint32_t (&a)[4],
                                         uint32_t b0, uint32_t b1) {
    asm volatile(
        "mma.sync.aligned.m16n8k16.row.col.f32.bf16.bf16.f32 "
        "{%0,%1,%2,%3}, {%4,%5,%6,%7}, {%8,%9}, {%0,%1,%2,%3};"
        : "+f"(c[0]), "+f"(c[1]), "+f"(c[2]), "+f"(c[3])
        : "r"(a[0]), "r"(a[1]), "r"(a[2]), "r"(a[3]), "r"(b0), "r"(b1));
}

// ---------------------------------------------------------------------------
// Kernel 1: bilinear upsample x2, align_corners=True  (32x32 -> 64x64)
// ---------------------------------------------------------------------------
__global__ __launch_bounds__(256) void upsample_k(const float* __restrict__ tx)
{
    __shared__ float s[1024];
    const int bc = blockIdx.x;                 // n*256 + c
    const float* src = tx + (size_t)bc * 1024;
    for (int idx = threadIdx.x; idx < 1024; idx += 256) s[idx] = src[idx];
    __syncthreads();

    float* dst = g_txup + (size_t)bc * 4096;
    const float step = 31.0f / 63.0f;
#pragma unroll
    for (int rpt = 0; rpt < 16; rpt++) {
        int opix = rpt * 256 + threadIdx.x;
        int y = opix >> 6, x = opix & 63;
        float fy = y * step;  int y0 = (int)fy;  float wy = fy - y0;
        int y1 = min(y0 + 1, 31);
        float fx = x * step;  int x0 = (int)fx;  float wx = fx - x0;
        int x1 = min(x0 + 1, 31);
        float top = s[y0 * 32 + x0] * (1.f - wx) + s[y0 * 32 + x1] * wx;
        float bot = s[y1 * 32 + x0] * (1.f - wx) + s[y1 * 32 + x1] * wx;
        dst[opix] = top * (1.f - wy) + bot * wy;
    }
}

__global__ void zero_sum_k()
{
    g_sum[blockIdx.x * 256 + threadIdx.x] = 0.f;
}

// ---------------------------------------------------------------------------
// Generic tiled 1x1-conv GEMM body (unchanged from R1 -- known correct)
// ---------------------------------------------------------------------------
template<int CIN, int OCTILE, int MODE>
__device__ __forceinline__ void conv1x1_body(
    const float* __restrict__ s0, int c0,
    const float* __restrict__ s1, int c1,
    const float* __restrict__ s2,
    const float* __restrict__ W,
    const float* __restrict__ bias,
    const float* __restrict__ scale,
    const float* __restrict__ e0,
    const float* __restrict__ e1,
    const float* __restrict__ e2,
    float* __restrict__ out)
{
    constexpr int RO = OCTILE / 32;
    __shared__ __align__(16) float Wc[OCTILE * 17];
    __shared__ __align__(16) float Xc[16 * 32];

    const int tid = threadIdx.x;
    const int n   = blockIdx.z;
    const int p0  = blockIdx.x * 32;
    const int ocb = blockIdx.y * OCTILE;
    const int COUT = gridDim.y * OCTILE;
    const int c2 = CIN - c0 - c1;
    const int tx8 = tid & 7, ty = tid >> 3;

    float acc[RO][4];
#pragma unroll
    for (int j = 0; j < RO; j++) {
        acc[j][0] = 0.f; acc[j][1] = 0.f; acc[j][2] = 0.f; acc[j][3] = 0.f;
    }

    for (int k0 = 0; k0 < CIN; k0 += 16) {
#pragma unroll
        for (int idx = tid; idx < OCTILE * 16; idx += 256) {
            int oc = idx >> 4, k = idx & 15;
            Wc[oc * 17 + k] = W[(size_t)(ocb + oc) * CIN + k0 + k];
        }
#pragma unroll
        for (int idx = tid; idx < 512; idx += 256) {
            int k = idx >> 5, px = idx & 31;
            int c = k0 + k;
            float v;
            if (c < c0)
                v = s0[((size_t)n * c0 + c) * HW + p0 + px];
            else if (c < c0 + c1)
                v = s1[((size_t)n * c1 + (c - c0)) * HW + p0 + px];
            else
                v = s2[((size_t)n * c2 + (c - c0 - c1)) * HW + p0 + px];
            Xc[k * 32 + px] = v;
        }
        __syncthreads();

#pragma unroll
        for (int k = 0; k < 16; k++) {
            float4 xv = *reinterpret_cast<const float4*>(&Xc[k * 32 + tx8 * 4]);
#pragma unroll
            for (int j = 0; j < RO; j++) {
                float wv = Wc[(ty * RO + j) * 17 + k];
                acc[j][0] = fmaf(wv, xv.x, acc[j][0]);
                acc[j][1] = fmaf(wv, xv.y, acc[j][1]);
                acc[j][2] = fmaf(wv, xv.z, acc[j][2]);
                acc[j][3] = fmaf(wv, xv.w, acc[j][3]);
            }
        }
        __syncthreads();
    }

    if (MODE == 0) {
#pragma unroll
        for (int j = 0; j < RO; j++) {
            int oc = ty * RO + j;
            float bz = bias[ocb + oc];
            float s = fmaxf(acc[j][0] + bz, 0.f) + fmaxf(acc[j][1] + bz, 0.f)
                    + fmaxf(acc[j][2] + bz, 0.f) + fmaxf(acc[j][3] + bz, 0.f);
            s += __shfl_xor_sync(0xffffffffu, s, 1);
            s += __shfl_xor_sync(0xffffffffu, s, 2);
            s += __shfl_xor_sync(0xffffffffu, s, 4);
            if (tx8 == 0) atomicAdd(&out[n * 256 + ocb + oc], s);
        }
    } else {
#pragma unroll
        for (int j = 0; j < RO; j++) {
            int goc = ocb + ty * RO + j;
            float bz = bias[goc];
            float v0 = acc[j][0] + bz, v1 = acc[j][1] + bz;
            float v2 = acc[j][2] + bz, v3 = acc[j][3] + bz;
            float4 r;
            if (MODE == 1) {
                float sc = scale[n * 256 + goc];
                r.x = fmaxf(v0, 0.f) * sc; r.y = fmaxf(v1, 0.f) * sc;
                r.z = fmaxf(v2, 0.f) * sc; r.w = fmaxf(v3, 0.f) * sc;
            } else if (MODE == 2) {
                r.x = fmaxf(v0, 0.f); r.y = fmaxf(v1, 0.f);
                r.z = fmaxf(v2, 0.f); r.w = fmaxf(v3, 0.f);
            } else { // MODE 3
                float sg0 = 1.f / (1.f + expf(-v0));
                float sg1 = 1.f / (1.f + expf(-v1));
                float sg2 = 1.f / (1.f + expf(-v2));
                float sg3 = 1.f / (1.f + expf(-v3));
                const float* bp;
                if (goc < 128)       bp = e0 + ((size_t)n * 128 + goc) * HW;
                else if (goc < 384)  bp = e1 + ((size_t)n * 256 + (goc - 128)) * HW;
                else                 bp = e2 + ((size_t)n * 256 + (goc - 384)) * HW;
                int pix = p0 + tx8 * 4;
                r.x = sg0 * bp[pix + 0]; r.y = sg1 * bp[pix + 1];
                r.z = sg2 * bp[pix + 2]; r.w = sg3 * bp[pix + 3];
            }
            *reinterpret_cast<float4*>(
                &out[((size_t)n * COUT + goc) * HW + p0 + tx8 * 4]) = r;
        }
    }
}

__global__ __launch_bounds__(256) void k_stageA(
    const float* __restrict__ sx1, const float* __restrict__ t_hx,
    const float* __restrict__ W, const float* __restrict__ bias)
{
    conv1x1_body<768, 256, 0>(sx1, 256, t_hx, 256, g_txup,
                              W, bias, nullptr, nullptr, nullptr, nullptr, g_sum);
}

__global__ __launch_bounds__(256) void k_b1(
    const float* __restrict__ sx2,
    const float* __restrict__ W, const float* __restrict__ bias)
{
    conv1x1_body<256, 256, 1>(sx2, 256, nullptr, 0, nullptr,
                              W, bias, g_w, nullptr, nullptr, nullptr, g_b1);
}

__global__ __launch_bounds__(256) void k_b2(
    const float* __restrict__ W, const float* __restrict__ bias)
{
    conv1x1_body<256, 128, 2>(g_b1, 256, nullptr, 0, nullptr,
                              W, bias, nullptr, nullptr, nullptr, nullptr, g_b2);
}

__global__ __launch_bounds__(256) void k_a1(
    const float* __restrict__ t_hx,
    const float* __restrict__ W, const float* __restrict__ bias)
{
    conv1x1_body<640, 128, 2>(g_b2, 128, t_hx, 256, g_txup,
                              W, bias, nullptr, nullptr, nullptr, nullptr, g_a1);
}

__global__ __launch_bounds__(256) void k_a2(
    const float* __restrict__ t_hx,
    const float* __restrict__ W, const float* __restrict__ bias)
{
    conv1x1_body<128, 128, 3>(g_a1, 128, nullptr, 0, nullptr,
                              W, bias, nullptr, g_b2, t_hx, g_txup, g_apod);
}

// ---------------------------------------------------------------------------
// Head (squeeze-excite MLP + L2 normalize); writes "w" output tail
// ---------------------------------------------------------------------------
__global__ __launch_bounds__(256) void head_k(
    const float* __restrict__ Wt2, const float* __restrict__ Wt3,
    float* __restrict__ outw)
{
    const int n = blockIdx.x, tid = threadIdx.x;
    __shared__ float w1[256], w2[64], red[256];

    w1[tid] = g_sum[n * 256 + tid] * (1.f / 4096.f);
    __syncthreads();

    if (tid < 64) {
        float s = 0.f;
#pragma unroll 8
        for (int k = 0; k < 256; k++) s = fmaf(Wt2[tid * 256 + k], w1[k], s);
        w2[tid] = fmaxf(s, 0.f);
    }
    __syncthreads();

    float s = 0.f;
#pragma unroll
    for (int e = 0; e < 64; e++) s = fmaf(Wt3[tid * 64 + e], w2[e], s);

    red[tid] = s * s;
    __syncthreads();
    for (int off = 128; off > 0; off >>= 1) {
        if (tid < off) red[tid] += red[tid + off];
        __syncthreads();
    }
    float nv = sqrtf(red[0]);
    float wv = s / fmaxf(nv, 1e-12f);
    g_w[n * 256 + tid] = wv;
    outw[n * 256 + tid] = wv;
}

// ---------------------------------------------------------------------------
// bf16 split conversions for the tensor-core conv
// ---------------------------------------------------------------------------
// weights: [oc][c][ky][kx] fp32 -> tap-major [oc][tap*640 + c] bf16 hi/lo
__global__ __launch_bounds__(256) void cvt_w_k(const float* __restrict__ W)
{
    const int oc = blockIdx.x;
    for (int t = threadIdx.x; t < 5760; t += 256) {
        int c = t / 9, tap = t - c * 9;
        float v = W[(size_t)oc * 5760 + t];
        __nv_bfloat16 h = __float2bfloat16(v);
        __nv_bfloat16 l = __float2bfloat16(v - __bfloat162float(h));
        size_t o = (size_t)oc * 5760 + (size_t)tap * 640 + c;
        g_wh[o] = h; g_wl[o] = l;
    }
}

// activations: g_apod [n][640][4096] fp32 -> channel-last [n][4096][640] bf16 hi/lo
__global__ __launch_bounds__(256) void cvt_act_k()
{
    __shared__ float t[64][65];
    const int n = blockIdx.z, c0 = blockIdx.y * 64, p0 = blockIdx.x * 64;
    const float* src = g_apod + ((size_t)n * 640 + c0) * HW + p0;
    for (int it = threadIdx.x; it < 4096; it += 256) {
        int c = it >> 6, px = it & 63;
        t[c][px] = src[(size_t)c * HW + px];
    }
    __syncthreads();
    for (int it = threadIdx.x; it < 4096; it += 256) {
        int px = it >> 6, c = it & 63;
        float v = t[c][px];
        __nv_bfloat16 h = __float2bfloat16(v);
        __nv_bfloat16 l = __float2bfloat16(v - __bfloat162float(h));
        size_t o = ((size_t)n * HW + p0 + px) * 640 + c0 + c;
        g_aT_h[o] = h; g_aT_l[o] = l;
    }
}

// ---------------------------------------------------------------------------
// mma.sync conv3x3: implicit GEMM, bf16x3 compensated split
//   C[oc, px] = sum_k W[oc,k] * im2col[px,k],  K = 5760 tap-major
//   CTA tile: 128 oc x 128 px; 16 warps, warp tile 32x32 (4x4 warp grid)
//   K chunks of 32, cp.async double-buffered.
//   smem tiles: [128 rows][40 bf16] (80B stride -- conflict-free ldmatrix/LDS)
// ---------------------------------------------------------------------------
#define TILE_B   10240                 // one 128x40-bf16 tile
#define STAGE_B  (4 * TILE_B)          // Ah, Al, Bh, Bl
#define CONV_SMEM (2 * STAGE_B)        // 81920 bytes

__global__ __launch_bounds__(512) void mma_conv3_k(
    const float* __restrict__ bot, float* __restrict__ out)
{
    extern __shared__ __align__(128) char smem[];
    const uint32_t sb = smem_to_u32(smem);

    const int tid  = threadIdx.x;
    const int lane = tid & 31;
    const int wid  = tid >> 5;
    const int wm   = wid & 3;          // 4 m-groups of 32 oc
    const int wn   = wid >> 2;         // 4 n-groups of 32 px
    const int n    = blockIdx.z;
    const int ocb  = blockIdx.y * 128;
    const int p0   = blockIdx.x * 128; // 2 output rows

    float acc[2][4][4];
#pragma unroll
    for (int mi = 0; mi < 2; mi++)
#pragma unroll
        for (int ni = 0; ni < 4; ni++)
#pragma unroll
            for (int r = 0; r < 4; r++) acc[mi][ni][r] = 0.f;

    // ---- staging lambda-equivalent -------------------------------------
    // chunk c: tap = c/20, cslice = (c%20)*32; A linear k0 = c*32
    auto stage = [&](int chunk) {
        const uint32_t base = sb + (chunk & 1) * STAGE_B;
        const int tap = chunk / 20;
        const int dy = tap / 3 - 1, dx = tap % 3 - 1;
        const int c0 = (chunk - tap * 20) * 32;
        const int k0 = chunk * 32;
        // A: 1024 16B ops (hi+lo), rows=oc
#pragma unroll
        for (int it = tid; it < 1024; it += 512) {
            int half = it >> 9, row = (it >> 2) & 127, seg = it & 3;
            const __nv_bfloat16* w = half ? g_wl : g_wh;
            cp16(base + half * TILE_B + row * 80 + seg * 16,
                 w + (size_t)(ocb + row) * 5760 + k0 + seg * 8, 16);
        }
        // B: 1024 16B ops (hi+lo), rows=px, halo -> zfill
#pragma unroll
        for (int it = tid; it < 1024; it += 512) {
            int half = it >> 9, row = (it >> 2) & 127, seg = it & 3;
            int p = p0 + row;
            int iy = (p >> 6) + dy, ix = (p & 63) + dx;
            bool ok = ((unsigned)iy < 64u) && ((unsigned)ix < 64u);
            const __nv_bfloat16* a = half ? g_aT_l : g_aT_h;
            const __nv_bfloat16* src = ok
                ? a + ((size_t)(n * HW + iy * 64 + ix)) * 640 + c0 + seg * 8
                : a;                                    // dummy valid addr
            cp16(base + (2 + half) * TILE_B + row * 80 + seg * 16,
                 src, ok ? 16u : 0u);
        }
    };

    stage(0);
    cp_commit();

    const int NCHUNK = 180;
    for (int i = 0; i < NCHUNK; i++) {
        if (i + 1 < NCHUNK) { stage(i + 1); cp_commit(); }
        if (i + 1 < NCHUNK) cp_wait<1>(); else cp_wait<0>();
        __syncthreads();

        const uint32_t base = sb + (i & 1) * STAGE_B;
        const uint32_t aAh = base;
        const uint32_t aAl = base + TILE_B;
        const uint32_t aBh = base + 2 * TILE_B;
        const uint32_t aBl = base + 3 * TILE_B;

#pragma unroll
        for (int ks = 0; ks < 2; ks++) {
            const int kb = ks * 32;            // 16 bf16 = 32 bytes
            // A fragments (hi and lo), 2 x m16 per warp
            uint32_t ah[2][4], al[2][4];
#pragma unroll
            for (int mi = 0; mi < 2; mi++) {
                uint32_t ro = (uint32_t)(wm * 32 + mi * 16 + (lane & 15)) * 80
                            + (uint32_t)(lane >> 4) * 16 + kb;
                ldm_x4(ah[mi], aAh + ro);
                ldm_x4(al[mi], aAl + ro);
            }
            // B fragments: 4 x n8 per warp, 2 regs each, hi and lo
#pragma unroll
            for (int ni = 0; ni < 4; ni++) {
                uint32_t ro = (uint32_t)(wn * 32 + ni * 8 + (lane >> 2)) * 80
                            + kb + (uint32_t)(lane & 3) * 4;
                uint32_t bh0 = *(const uint32_t*)(smem + (aBh + ro      - sb));
                uint32_t bh1 = *(const uint32_t*)(smem + (aBh + ro + 16 - sb));
                uint32_t bl0 = *(const uint32_t*)(smem + (aBl + ro      - sb));
                uint32_t bl1 = *(const uint32_t*)(smem + (aBl + ro + 16 - sb));
#pragma unroll
                for (int mi = 0; mi < 2; mi++) {
                    mma_bf16(acc[mi][ni], ah[mi], bh0, bh1);
                    mma_bf16(acc[mi][ni], ah[mi], bl0, bl1);
                    mma_bf16(acc[mi][ni], al[mi], bh0, bh1);
                }
            }
        }
        __syncthreads();
    }

    // ---- epilogue: bias + relu, direct coalesced-ish float2 stores -----
    const size_t nb = (size_t)n * 256 * HW;
#pragma unroll
    for (int mi = 0; mi < 2; mi++) {
        int r0 = ocb + wm * 32 + mi * 16 + (lane >> 2);
        float bv0 = bot[r0], bv1 = bot[r0 + 8];
#pragma unroll
        for (int ni = 0; ni < 4; ni++) {
            int px = p0 + wn * 32 + ni * 8 + (lane & 3) * 2;
            float2 v0, v1;
            v0.x = fmaxf(acc[mi][ni][0] + bv0, 0.f);
            v0.y = fmaxf(acc[mi][ni][1] + bv0, 0.f);
            v1.x = fmaxf(acc[mi][ni][2] + bv1, 0.f);
            v1.y = fmaxf(acc[mi][ni][3] + bv1, 0.f);
            *(float2*)(out + nb + (size_t)r0 * HW + px)       = v0;
            *(float2*)(out + nb + (size_t)(r0 + 8) * HW + px) = v1;
        }
    }
}

// ---------------------------------------------------------------------------
// Launch
// ---------------------------------------------------------------------------
extern "C" void kernel_launch(void* const* d_in, const int* in_sizes, int n_in,
                              void* d_out, int out_size)
{
    const float* sx1  = (const float*)d_in[0];
    const float* sx2  = (const float*)d_in[1];
    const float* t_hx = (const float*)d_in[2];
    const float* tx   = (const float*)d_in[3];
    const float* W_t1 = (const float*)d_in[4];
    const float* b_t1 = (const float*)d_in[5];
    const float* W_t2 = (const float*)d_in[6];
    const float* W_t3 = (const float*)d_in[7];
    const float* W_U  = (const float*)d_in[8];
    const float* b_U  = (const float*)d_in[9];
    const float* W_V  = (const float*)d_in[10];
    const float* b_V  = (const float*)d_in[11];
    const float* W_a1 = (const float*)d_in[12];
    const float* b_a1 = (const float*)d_in[13];
    const float* W_a2 = (const float*)d_in[14];
    const float* b_a2 = (const float*)d_in[15];
    const float* W_ot = (const float*)d_in[16];
    const float* b_ot = (const float*)d_in[17];
    float* out = (float*)d_out;

    cudaFuncSetAttribute(mma_conv3_k, cudaFuncAttributeMaxDynamicSharedMemorySize,
                         CONV_SMEM);

    // weight bf16 split (independent of activations)
    cvt_w_k<<<256, 256>>>(W_ot);
    // 1. upsample tx -> g_txup
    upsample_k<<<2048, 256>>>(tx);
    // 2. zero GAP accumulator
    zero_sum_k<<<8, 256>>>();
    // 3. stage A: relu(W_t1 @ [sx1;t_hx;txup] + b_t1), GAP -> g_sum
    k_stageA<<<dim3(128, 1, 8), 256>>>(sx1, t_hx, W_t1, b_t1);
    // 4. head MLP + L2 normalize -> g_w, writes w output tail
    head_k<<<8, 256>>>(W_t2, W_t3, out + OUT_A_ELEMS);
    // 5. b1 = relu(W_U @ sx2 + b_U) * w
    k_b1<<<dim3(128, 1, 8), 256>>>(sx2, W_U, b_U);
    // 6. b2 = relu(W_V @ b1 + b_V)
    k_b2<<<dim3(128, 1, 8), 256>>>(W_V, b_V);
    // 7. a1 = relu(W_a1 @ [b2;t_hx;txup] + b_a1)
    k_a1<<<dim3(128, 1, 8), 256>>>(t_hx, W_a1, b_a1);
    // 8. apod = sigmoid(W_a2 @ a1 + b_a2) * [b2;t_hx;txup]
    k_a2<<<dim3(128, 5, 8), 256>>>(t_hx, W_a2, b_a2);
    // 9. bf16 hi/lo channel-last split of apod
    cvt_act_k<<<dim3(64, 10, 8), 256>>>();
    // 10. tensor-core conv3x3 + bias + relu -> main output
    mma_conv3_k<<<dim3(32, 2, 8), 512, CONV_SMEM>>>(b_ot, out);
}

// round 6
// speedup vs baseline: 1.9538x; 1.4210x over previous
#include <cuda_runtime.h>
#include <cuda_bf16.h>
#include <math.h>
#include <stdint.h>

// ---------------------------------------------------------------------------
// Problem constants
// ---------------------------------------------------------------------------
#define HW     4096          // 64*64
#define NB     8
#define OUT_A_ELEMS (8 * 256 * 4096)   // "a" output
// output layout: a [8,256,64,64] followed by w [8,256]

typedef __nv_bfloat16 bf16;

// ---------------------------------------------------------------------------
// Scratch (static device globals -- no allocation allowed)
// ---------------------------------------------------------------------------
__device__ float g_txup[8 * 256 * 4096];   // upsampled tx (fp32)   33.5 MB
__device__ float g_sum [8 * 256];          // stage-A GAP accumulator
__device__ float g_w   [8 * 256];          // normalized channel weights

// channel-last bf16 hi/lo activation planes [n*4096][C]
__device__ __align__(16) bf16 g_x1h [8ULL * 4096 * 256], g_x1l [8ULL * 4096 * 256];
__device__ __align__(16) bf16 g_thxh[8ULL * 4096 * 256], g_thxl[8ULL * 4096 * 256];
__device__ __align__(16) bf16 g_txuh[8ULL * 4096 * 256], g_txul[8ULL * 4096 * 256];
__device__ __align__(16) bf16 g_x2h [8ULL * 4096 * 256], g_x2l [8ULL * 4096 * 256];
__device__ __align__(16) bf16 g_b1h [8ULL * 4096 * 256], g_b1l [8ULL * 4096 * 256];
__device__ __align__(16) bf16 g_b2h [8ULL * 4096 * 128], g_b2l [8ULL * 4096 * 128];
__device__ __align__(16) bf16 g_a1h [8ULL * 4096 * 128], g_a1l [8ULL * 4096 * 128];
__device__ __align__(16) bf16 g_aT_h[8ULL * 4096 * 640], g_aT_l[8ULL * 4096 * 640];

// weight bf16 hi/lo splits (row-major [O][K] -- GEMM A operands)
__device__ __align__(16) bf16 g_wt1h[256 * 768], g_wt1l[256 * 768];
__device__ __align__(16) bf16 g_wUh [256 * 256], g_wUl [256 * 256];
__device__ __align__(16) bf16 g_wVh [128 * 256], g_wVl [128 * 256];
__device__ __align__(16) bf16 g_wa1h[128 * 640], g_wa1l[128 * 640];
__device__ __align__(16) bf16 g_wa2h[640 * 128], g_wa2l[640 * 128];
// conv3x3 weights, tap-major [oc][tap*640+c]
__device__ __align__(16) bf16 g_wh[256 * 5760], g_wl[256 * 5760];

// ---------------------------------------------------------------------------
// helpers
// ---------------------------------------------------------------------------
__device__ __forceinline__ uint32_t smem_to_u32(const void* p) {
    uint32_t a;
    asm("{ .reg .u64 t; cvta.to.shared.u64 t, %1; cvt.u32.u64 %0, t; }"
        : "=r"(a) : "l"(p));
    return a;
}

__device__ __forceinline__ void cp16(uint32_t dst, const void* src, uint32_t bytes) {
    asm volatile("cp.async.cg.shared.global [%0], [%1], 16, %2;"
                 :: "r"(dst), "l"(src), "r"(bytes) : "memory");
}
__device__ __forceinline__ void cp_commit() {
    asm volatile("cp.async.commit_group;" ::: "memory");
}
template<int N>
__device__ __forceinline__ void cp_wait() {
    asm volatile("cp.async.wait_group %0;" :: "n"(N) : "memory");
}

__device__ __forceinline__ void ldm_x4(uint32_t (&r)[4], uint32_t addr) {
    asm volatile("ldmatrix.sync.aligned.m8n8.x4.shared.b16 {%0,%1,%2,%3}, [%4];"
                 : "=r"(r[0]), "=r"(r[1]), "=r"(r[2]), "=r"(r[3]) : "r"(addr));
}

__device__ __forceinline__ void mma_bf16(float (&c)[4], const uint32_t (&a)[4],
                                         uint32_t b0, uint32_t b1) {
    asm volatile(
        "mma.sync.aligned.m16n8k16.row.col.f32.bf16.bf16.f32 "
        "{%0,%1,%2,%3}, {%4,%5,%6,%7}, {%8,%9}, {%0,%1,%2,%3};"
        : "+f"(c[0]), "+f"(c[1]), "+f"(c[2]), "+f"(c[3])
        : "r"(a[0]), "r"(a[1]), "r"(a[2]), "r"(a[3]), "r"(b0), "r"(b1));
}

// ---------------------------------------------------------------------------
// bilinear upsample x2, align_corners=True (32x32 -> 64x64), fp32 out
// ---------------------------------------------------------------------------
__global__ __launch_bounds__(256) void upsample_k(const float* __restrict__ tx)
{
    __shared__ float s[1024];
    const int bc = blockIdx.x;
    const float* src = tx + (size_t)bc * 1024;
    for (int idx = threadIdx.x; idx < 1024; idx += 256) s[idx] = src[idx];
    __syncthreads();

    float* dst = g_txup + (size_t)bc * 4096;
    const float step = 31.0f / 63.0f;
#pragma unroll
    for (int rpt = 0; rpt < 16; rpt++) {
        int opix = rpt * 256 + threadIdx.x;
        int y = opix >> 6, x = opix & 63;
        float fy = y * step;  int y0 = (int)fy;  float wy = fy - y0;
        int y1 = min(y0 + 1, 31);
        float fx = x * step;  int x0 = (int)fx;  float wx = fx - x0;
        int x1 = min(x0 + 1, 31);
        float top = s[y0 * 32 + x0] * (1.f - wx) + s[y0 * 32 + x1] * wx;
        float bot = s[y1 * 32 + x0] * (1.f - wx) + s[y1 * 32 + x1] * wx;
        dst[opix] = top * (1.f - wy) + bot * wy;
    }
}

__global__ void zero_sum_k()
{
    g_sum[blockIdx.x * 256 + threadIdx.x] = 0.f;
}

// ---------------------------------------------------------------------------
// transpose + bf16 hi/lo split: [n][C][4096] fp32 -> [n*4096][C] bf16 x2
// ---------------------------------------------------------------------------
__device__ __forceinline__ void cvtT_body(const float* __restrict__ src,
                                          bf16* __restrict__ dh,
                                          bf16* __restrict__ dl, int C)
{
    __shared__ float t[64][65];
    const int n = blockIdx.z, c0 = blockIdx.y * 64, p0 = blockIdx.x * 64;
    const float* sp = src + ((size_t)n * C + c0) * HW + p0;
    for (int it = threadIdx.x; it < 4096; it += 256) {
        int c = it >> 6, px = it & 63;
        t[c][px] = sp[(size_t)c * HW + px];
    }
    __syncthreads();
    for (int it = threadIdx.x; it < 4096; it += 256) {
        int px = it >> 6, c = it & 63;
        float v = t[c][px];
        bf16 h = __float2bfloat16(v);
        bf16 l = __float2bfloat16(v - __bfloat162float(h));
        size_t o = ((size_t)n * HW + p0 + px) * C + c0 + c;
        dh[o] = h; dl[o] = l;
    }
}

__global__ __launch_bounds__(256) void cvt_sx1_k(const float* __restrict__ s)
{ cvtT_body(s, g_x1h, g_x1l, 256); }
__global__ __launch_bounds__(256) void cvt_thx_k(const float* __restrict__ s)
{ cvtT_body(s, g_thxh, g_thxl, 256); }
__global__ __launch_bounds__(256) void cvt_sx2_k(const float* __restrict__ s)
{ cvtT_body(s, g_x2h, g_x2l, 256); }
__global__ __launch_bounds__(256) void cvt_txu_k()
{ cvtT_body(g_txup, g_txuh, g_txul, 256); }

// ---------------------------------------------------------------------------
// weight splits: all 5 GEMM weights, plus conv tap-major reorder
// ---------------------------------------------------------------------------
__global__ __launch_bounds__(256) void split_all_k(
    const float* __restrict__ a, const float* __restrict__ b,
    const float* __restrict__ c, const float* __restrict__ d,
    const float* __restrict__ e)
{
    const float* src; bf16 *h, *l; int nel;
    switch (blockIdx.y) {
        case 0:  src = a; h = g_wt1h; l = g_wt1l; nel = 256 * 768; break;
        case 1:  src = b; h = g_wUh;  l = g_wUl;  nel = 256 * 256; break;
        case 2:  src = c; h = g_wVh;  l = g_wVl;  nel = 128 * 256; break;
        case 3:  src = d; h = g_wa1h; l = g_wa1l; nel = 128 * 640; break;
        default: src = e; h = g_wa2h; l = g_wa2l; nel = 640 * 128; break;
    }
    for (int i = blockIdx.x * 256 + threadIdx.x; i < nel; i += gridDim.x * 256) {
        float v = src[i];
        bf16 hi = __float2bfloat16(v);
        h[i] = hi;
        l[i] = __float2bfloat16(v - __bfloat162float(hi));
    }
}

// conv weights: [oc][c][ky][kx] fp32 -> tap-major [oc][tap*640 + c] bf16 hi/lo
__global__ __launch_bounds__(256) void cvt_w_k(const float* __restrict__ W)
{
    const int oc = blockIdx.x;
    for (int t = threadIdx.x; t < 5760; t += 256) {
        int c = t / 9, tap = t - c * 9;
        float v = W[(size_t)oc * 5760 + t];
        bf16 h = __float2bfloat16(v);
        bf16 l = __float2bfloat16(v - __bfloat162float(h));
        size_t o = (size_t)oc * 5760 + (size_t)tap * 640 + c;
        g_wh[o] = h; g_wl[o] = l;
    }
}

// ---------------------------------------------------------------------------
// Head (squeeze-excite MLP + L2 normalize); writes "w" output tail
// ---------------------------------------------------------------------------
__global__ __launch_bounds__(256) void head_k(
    const float* __restrict__ Wt2, const float* __restrict__ Wt3,
    float* __restrict__ outw)
{
    const int n = blockIdx.x, tid = threadIdx.x;
    __shared__ float w1[256], w2[64], red[256];

    w1[tid] = g_sum[n * 256 + tid] * (1.f / 4096.f);
    __syncthreads();

    if (tid < 64) {
        float s = 0.f;
#pragma unroll 8
        for (int k = 0; k < 256; k++) s = fmaf(Wt2[tid * 256 + k], w1[k], s);
        w2[tid] = fmaxf(s, 0.f);
    }
    __syncthreads();

    float s = 0.f;
#pragma unroll
    for (int e = 0; e < 64; e++) s = fmaf(Wt3[tid * 64 + e], w2[e], s);

    red[tid] = s * s;
    __syncthreads();
    for (int off = 128; off > 0; off >>= 1) {
        if (tid < off) red[tid] += red[tid + off];
        __syncthreads();
    }
    float nv = sqrtf(red[0]);
    float wv = s / fmaxf(nv, 1e-12f);
    g_w[n * 256 + tid] = wv;
    outw[n * 256 + tid] = wv;
}

// ---------------------------------------------------------------------------
// Unified mma.sync 1x1-conv GEMM, bf16x3 compensated split.
//   C[oc, px] = sum_k W[oc,k] * X[px,k]
//   CTA 128oc x 128px, 16 warps 32x32, K chunks of 32, cp.async dbl-buffered.
//   B gathered from up to 3 channel-last segments (boundaries 32-aligned).
// MODE 0: relu(acc+bias), GAP-sum over px, atomicAdd -> g_sum
// MODE 1: relu(acc+bias) * g_w[n,oc]       -> channel-last hi/lo
// MODE 2: relu(acc+bias)                   -> channel-last hi/lo
// MODE 3: sigmoid(acc+bias) * bcat[px,oc]  -> channel-last hi/lo (bcat = b2|thx|txu)
// ---------------------------------------------------------------------------
#define TILE_B   10240                 // one 128x40-bf16 tile
#define STAGE_B  (4 * TILE_B)          // Ah, Al, Bh, Bl
#define GEMM_SMEM (2 * STAGE_B)        // 81920 bytes

template<int MODE>
__device__ __forceinline__ void gemm_body(
    int K, int COUT,
    const bf16* __restrict__ s0h, const bf16* __restrict__ s0l, int st0,
    const bf16* __restrict__ s1h, const bf16* __restrict__ s1l, int st1,
    const bf16* __restrict__ s2h, const bf16* __restrict__ s2l, int st2,
    int kb0, int kb1,
    const bf16* __restrict__ wh, const bf16* __restrict__ wl,
    const float* __restrict__ bias,
    bf16* __restrict__ oh, bf16* __restrict__ ol)
{
    extern __shared__ __align__(128) char smem[];
    const uint32_t sb = smem_to_u32(smem);

    const int tid  = threadIdx.x;
    const int lane = tid & 31;
    const int wid  = tid >> 5;
    const int wm   = wid & 3;
    const int wn   = wid >> 2;
    const int n    = blockIdx.z;
    const int ocb  = blockIdx.y * 128;
    const int p0   = blockIdx.x * 128;

    float acc[2][4][4];
#pragma unroll
    for (int mi = 0; mi < 2; mi++)
#pragma unroll
        for (int ni = 0; ni < 4; ni++)
#pragma unroll
            for (int r = 0; r < 4; r++) acc[mi][ni][r] = 0.f;

    auto stage = [&](int chunk) {
        const uint32_t base = sb + (chunk & 1) * STAGE_B;
        const int k0 = chunk * 32;
        const bf16 *sh, *sl; int stride, ks;
        if (k0 < kb0)      { sh = s0h; sl = s0l; stride = st0; ks = 0;   }
        else if (k0 < kb1) { sh = s1h; sl = s1l; stride = st1; ks = kb0; }
        else               { sh = s2h; sl = s2l; stride = st2; ks = kb1; }
        const int c0 = k0 - ks;
#pragma unroll
        for (int it = tid; it < 1024; it += 512) {
            int half = it >> 9, row = (it >> 2) & 127, seg = it & 3;
            const bf16* w = half ? wl : wh;
            cp16(base + half * TILE_B + row * 80 + seg * 16,
                 w + (size_t)(ocb + row) * K + k0 + seg * 8, 16);
        }
#pragma unroll
        for (int it = tid; it < 1024; it += 512) {
            int half = it >> 9, row = (it >> 2) & 127, seg = it & 3;
            const bf16* a = half ? sl : sh;
            cp16(base + (2 + half) * TILE_B + row * 80 + seg * 16,
                 a + ((size_t)n * HW + p0 + row) * stride + c0 + seg * 8, 16);
        }
    };

    const int NC = K >> 5;
    stage(0);
    cp_commit();

    for (int i = 0; i < NC; i++) {
        if (i + 1 < NC) { stage(i + 1); cp_commit(); cp_wait<1>(); }
        else            cp_wait<0>();
        __syncthreads();

        const uint32_t base = sb + (i & 1) * STAGE_B;
        const uint32_t aAh = base;
        const uint32_t aAl = base + TILE_B;
        const uint32_t aBh = base + 2 * TILE_B;
        const uint32_t aBl = base + 3 * TILE_B;

#pragma unroll
        for (int ks = 0; ks < 2; ks++) {
            const int kb = ks * 32;
            uint32_t ah[2][4], al[2][4];
#pragma unroll
            for (int mi = 0; mi < 2; mi++) {
                uint32_t ro = (uint32_t)(wm * 32 + mi * 16 + (lane & 15)) * 80
                            + (uint32_t)(lane >> 4) * 16 + kb;
                ldm_x4(ah[mi], aAh + ro);
                ldm_x4(al[mi], aAl + ro);
            }
#pragma unroll
            for (int ni = 0; ni < 4; ni++) {
                uint32_t ro = (uint32_t)(wn * 32 + ni * 8 + (lane >> 2)) * 80
                            + kb + (uint32_t)(lane & 3) * 4;
                uint32_t bh0 = *(const uint32_t*)(smem + (aBh + ro      - sb));
                uint32_t bh1 = *(const uint32_t*)(smem + (aBh + ro + 16 - sb));
                uint32_t bl0 = *(const uint32_t*)(smem + (aBl + ro      - sb));
                uint32_t bl1 = *(const uint32_t*)(smem + (aBl + ro + 16 - sb));
#pragma unroll
                for (int mi = 0; mi < 2; mi++) {
                    mma_bf16(acc[mi][ni], ah[mi], bh0, bh1);
                    mma_bf16(acc[mi][ni], ah[mi], bl0, bl1);
                    mma_bf16(acc[mi][ni], al[mi], bh0, bh1);
                }
            }
        }
        __syncthreads();
    }

    if (MODE == 0) {
        // GAP reduce: relu(acc+bias), sum over px, atomicAdd per oc
#pragma unroll
        for (int mi = 0; mi < 2; mi++) {
            int r0 = ocb + wm * 32 + mi * 16 + (lane >> 2);
            float b0 = bias[r0], b1 = bias[r0 + 8];
            float s0 = 0.f, s1 = 0.f;
#pragma unroll
            for (int ni = 0; ni < 4; ni++) {
                s0 += fmaxf(acc[mi][ni][0] + b0, 0.f) + fmaxf(acc[mi][ni][1] + b0, 0.f);
                s1 += fmaxf(acc[mi][ni][2] + b1, 0.f) + fmaxf(acc[mi][ni][3] + b1, 0.f);
            }
            s0 += __shfl_xor_sync(0xffffffffu, s0, 1);
            s0 += __shfl_xor_sync(0xffffffffu, s0, 2);
            s1 += __shfl_xor_sync(0xffffffffu, s1, 1);
            s1 += __shfl_xor_sync(0xffffffffu, s1, 2);
            if ((lane & 3) == 0) {
                atomicAdd(&g_sum[n * 256 + r0],     s0);
                atomicAdd(&g_sum[n * 256 + r0 + 8], s1);
            }
        }
        return;
    }

    // transpose epilogue: per-warp 32x32 patch in (reused) smem
    __syncthreads();
    float* patch = (float*)smem + wid * (32 * 33);
#pragma unroll
    for (int mi = 0; mi < 2; mi++)
#pragma unroll
        for (int ni = 0; ni < 4; ni++) {
            int r = mi * 16 + (lane >> 2);
            int p = ni * 8 + (lane & 3) * 2;
            patch[r * 33 + p]           = acc[mi][ni][0];
            patch[r * 33 + p + 1]       = acc[mi][ni][1];
            patch[(r + 8) * 33 + p]     = acc[mi][ni][2];
            patch[(r + 8) * 33 + p + 1] = acc[mi][ni][3];
        }
    __syncwarp();

    const int pxg = p0 + wn * 32 + lane;
    const int oc0 = ocb + wm * 32;

    // mode-3 gather segment (oc-slab aligned; boundaries 128/384)
    const bf16 *gh = nullptr, *gl = nullptr; int gst = 0, gks = 0;
    if (MODE == 3) {
        if (oc0 < 128)      { gh = g_b2h;  gl = g_b2l;  gst = 128; gks = 0;   }
        else if (oc0 < 384) { gh = g_thxh; gl = g_thxl; gst = 256; gks = 128; }
        else                { gh = g_txuh; gl = g_txul; gst = 256; gks = 384; }
    }

    bf16 hh[32], ll[32];
#pragma unroll
    for (int j = 0; j < 32; j++) {
        float v = patch[j * 33 + lane] + bias[oc0 + j];
        if (MODE == 1)      v = fmaxf(v, 0.f) * g_w[n * 256 + oc0 + j];
        else if (MODE == 2) v = fmaxf(v, 0.f);
        else {              // MODE 3
            float sg = 1.f / (1.f + expf(-v));
            size_t gi = ((size_t)n * HW + pxg) * gst + (oc0 - gks) + j;
            v = sg * (__bfloat162float(gh[gi]) + __bfloat162float(gl[gi]));
        }
        bf16 h = __float2bfloat16(v);
        hh[j] = h;
        ll[j] = __float2bfloat16(v - __bfloat162float(h));
    }
    size_t o = ((size_t)n * HW + pxg) * COUT + oc0;
#pragma unroll
    for (int q = 0; q < 4; q++) {
        *(uint4*)(oh + o + q * 8) = ((const uint4*)hh)[q];
        *(uint4*)(ol + o + q * 8) = ((const uint4*)ll)[q];
    }
}

// ----- wrappers binding global scratch --------------------------------------
__global__ __launch_bounds__(512) void g_stageA_k(const float* __restrict__ bias)
{
    gemm_body<0>(768, 256, g_x1h, g_x1l, 256, g_thxh, g_thxl, 256,
                 g_txuh, g_txul, 256, 256, 512,
                 g_wt1h, g_wt1l, bias, nullptr, nullptr);
}
__global__ __launch_bounds__(512) void g_b1_k(const float* __restrict__ bias)
{
    gemm_body<1>(256, 256, g_x2h, g_x2l, 256, nullptr, nullptr, 0,
                 nullptr, nullptr, 0, 256, 256,
                 g_wUh, g_wUl, bias, g_b1h, g_b1l);
}
__global__ __launch_bounds__(512) void g_b2_k(const float* __restrict__ bias)
{
    gemm_body<2>(256, 128, g_b1h, g_b1l, 256, nullptr, nullptr, 0,
                 nullptr, nullptr, 0, 256, 256,
                 g_wVh, g_wVl, bias, g_b2h, g_b2l);
}
__global__ __launch_bounds__(512) void g_a1_k(const float* __restrict__ bias)
{
    gemm_body<2>(640, 128, g_b2h, g_b2l, 128, g_thxh, g_thxl, 256,
                 g_txuh, g_txul, 256, 128, 384,
                 g_wa1h, g_wa1l, bias, g_a1h, g_a1l);
}
__global__ __launch_bounds__(512) void g_a2_k(const float* __restrict__ bias)
{
    gemm_body<3>(128, 640, g_a1h, g_a1l, 128, nullptr, nullptr, 0,
                 nullptr, nullptr, 0, 128, 128,
                 g_wa2h, g_wa2l, bias, g_aT_h, g_aT_l);
}

// ---------------------------------------------------------------------------
// mma.sync conv3x3 (unchanged from R4 -- known correct)
// ---------------------------------------------------------------------------
__global__ __launch_bounds__(512) void mma_conv3_k(
    const float* __restrict__ bot, float* __restrict__ out)
{
    extern __shared__ __align__(128) char smem[];
    const uint32_t sb = smem_to_u32(smem);

    const int tid  = threadIdx.x;
    const int lane = tid & 31;
    const int wid  = tid >> 5;
    const int wm   = wid & 3;
    const int wn   = wid >> 2;
    const int n    = blockIdx.z;
    const int ocb  = blockIdx.y * 128;
    const int p0   = blockIdx.x * 128;

    float acc[2][4][4];
#pragma unroll
    for (int mi = 0; mi < 2; mi++)
#pragma unroll
        for (int ni = 0; ni < 4; ni++)
#pragma unroll
            for (int r = 0; r < 4; r++) acc[mi][ni][r] = 0.f;

    auto stage = [&](int chunk) {
        const uint32_t base = sb + (chunk & 1) * STAGE_B;
        const int tap = chunk / 20;
        const int dy = tap / 3 - 1, dx = tap % 3 - 1;
        const int c0 = (chunk - tap * 20) * 32;
        const int k0 = chunk * 32;
#pragma unroll
        for (int it = tid; it < 1024; it += 512) {
            int half = it >> 9, row = (it >> 2) & 127, seg = it & 3;
            const bf16* w = half ? g_wl : g_wh;
            cp16(base + half * TILE_B + row * 80 + seg * 16,
                 w + (size_t)(ocb + row) * 5760 + k0 + seg * 8, 16);
        }
#pragma unroll
        for (int it = tid; it < 1024; it += 512) {
            int half = it >> 9, row = (it >> 2) & 127, seg = it & 3;
            int p = p0 + row;
            int iy = (p >> 6) + dy, ix = (p & 63) + dx;
            bool ok = ((unsigned)iy < 64u) && ((unsigned)ix < 64u);
            const bf16* a = half ? g_aT_l : g_aT_h;
            const bf16* src = ok
                ? a + ((size_t)(n * HW + iy * 64 + ix)) * 640 + c0 + seg * 8
                : a;
            cp16(base + (2 + half) * TILE_B + row * 80 + seg * 16,
                 src, ok ? 16u : 0u);
        }
    };

    stage(0);
    cp_commit();

    const int NCHUNK = 180;
    for (int i = 0; i < NCHUNK; i++) {
        if (i + 1 < NCHUNK) { stage(i + 1); cp_commit(); cp_wait<1>(); }
        else                cp_wait<0>();
        __syncthreads();

        const uint32_t base = sb + (i & 1) * STAGE_B;
        const uint32_t aAh = base;
        const uint32_t aAl = base + TILE_B;
        const uint32_t aBh = base + 2 * TILE_B;
        const uint32_t aBl = base + 3 * TILE_B;

#pragma unroll
        for (int ks = 0; ks < 2; ks++) {
            const int kb = ks * 32;
            uint32_t ah[2][4], al[2][4];
#pragma unroll
            for (int mi = 0; mi < 2; mi++) {
                uint32_t ro = (uint32_t)(wm * 32 + mi * 16 + (lane & 15)) * 80
                            + (uint32_t)(lane >> 4) * 16 + kb;
                ldm_x4(ah[mi], aAh + ro);
                ldm_x4(al[mi], aAl + ro);
            }
#pragma unroll
            for (int ni = 0; ni < 4; ni++) {
                uint32_t ro = (uint32_t)(wn * 32 + ni * 8 + (lane >> 2)) * 80
                            + kb + (uint32_t)(lane & 3) * 4;
                uint32_t bh0 = *(const uint32_t*)(smem + (aBh + ro      - sb));
                uint32_t bh1 = *(const uint32_t*)(smem + (aBh + ro + 16 - sb));
                uint32_t bl0 = *(const uint32_t*)(smem + (aBl + ro      - sb));
                uint32_t bl1 = *(const uint32_t*)(smem + (aBl + ro + 16 - sb));
#pragma unroll
                for (int mi = 0; mi < 2; mi++) {
                    mma_bf16(acc[mi][ni], ah[mi], bh0, bh1);
                    mma_bf16(acc[mi][ni], ah[mi], bl0, bl1);
                    mma_bf16(acc[mi][ni], al[mi], bh0, bh1);
                }
            }
        }
        __syncthreads();
    }

    const size_t nb = (size_t)n * 256 * HW;
#pragma unroll
    for (int mi = 0; mi < 2; mi++) {
        int r0 = ocb + wm * 32 + mi * 16 + (lane >> 2);
        float bv0 = bot[r0], bv1 = bot[r0 + 8];
#pragma unroll
        for (int ni = 0; ni < 4; ni++) {
            int px = p0 + wn * 32 + ni * 8 + (lane & 3) * 2;
            float2 v0, v1;
            v0.x = fmaxf(acc[mi][ni][0] + bv0, 0.f);
            v0.y = fmaxf(acc[mi][ni][1] + bv0, 0.f);
            v1.x = fmaxf(acc[mi][ni][2] + bv1, 0.f);
            v1.y = fmaxf(acc[mi][ni][3] + bv1, 0.f);
            *(float2*)(out + nb + (size_t)r0 * HW + px)       = v0;
            *(float2*)(out + nb + (size_t)(r0 + 8) * HW + px) = v1;
        }
    }
}

// ---------------------------------------------------------------------------
// Launch
// ---------------------------------------------------------------------------
extern "C" void kernel_launch(void* const* d_in, const int* in_sizes, int n_in,
                              void* d_out, int out_size)
{
    const float* sx1  = (const float*)d_in[0];
    const float* sx2  = (const float*)d_in[1];
    const float* t_hx = (const float*)d_in[2];
    const float* tx   = (const float*)d_in[3];
    const float* W_t1 = (const float*)d_in[4];
    const float* b_t1 = (const float*)d_in[5];
    const float* W_t2 = (const float*)d_in[6];
    const float* W_t3 = (const float*)d_in[7];
    const float* W_U  = (const float*)d_in[8];
    const float* b_U  = (const float*)d_in[9];
    const float* W_V  = (const float*)d_in[10];
    const float* b_V  = (const float*)d_in[11];
    const float* W_a1 = (const float*)d_in[12];
    const float* b_a1 = (const float*)d_in[13];
    const float* W_a2 = (const float*)d_in[14];
    const float* b_a2 = (const float*)d_in[15];
    const float* W_ot = (const float*)d_in[16];
    const float* b_ot = (const float*)d_in[17];
    float* out = (float*)d_out;

    cudaFuncSetAttribute(g_stageA_k, cudaFuncAttributeMaxDynamicSharedMemorySize, GEMM_SMEM);
    cudaFuncSetAttribute(g_b1_k,     cudaFuncAttributeMaxDynamicSharedMemorySize, GEMM_SMEM);
    cudaFuncSetAttribute(g_b2_k,     cudaFuncAttributeMaxDynamicSharedMemorySize, GEMM_SMEM);
    cudaFuncSetAttribute(g_a1_k,     cudaFuncAttributeMaxDynamicSharedMemorySize, GEMM_SMEM);
    cudaFuncSetAttribute(g_a2_k,     cudaFuncAttributeMaxDynamicSharedMemorySize, GEMM_SMEM);
    cudaFuncSetAttribute(mma_conv3_k, cudaFuncAttributeMaxDynamicSharedMemorySize, GEMM_SMEM);

    // weight conversions
    split_all_k<<<dim3(96, 5), 256>>>(W_t1, W_U, W_V, W_a1, W_a2);
    cvt_w_k<<<256, 256>>>(W_ot);
    // upsample + activation conversions
    upsample_k<<<2048, 256>>>(tx);
    cvt_sx1_k<<<dim3(64, 4, 8), 256>>>(sx1);
    cvt_thx_k<<<dim3(64, 4, 8), 256>>>(t_hx);
    cvt_sx2_k<<<dim3(64, 4, 8), 256>>>(sx2);
    cvt_txu_k<<<dim3(64, 4, 8), 256>>>();
    zero_sum_k<<<8, 256>>>();
    // stage A GEMM + GAP
    g_stageA_k<<<dim3(32, 2, 8), 512, GEMM_SMEM>>>(b_t1);
    // head MLP + normalize
    head_k<<<8, 256>>>(W_t2, W_t3, out + OUT_A_ELEMS);
    // b1 = relu(W_U@sx2 + b)*w
    g_b1_k<<<dim3(32, 2, 8), 512, GEMM_SMEM>>>(b_U);
    // b2 = relu(W_V@b1 + b)
    g_b2_k<<<dim3(32, 1, 8), 512, GEMM_SMEM>>>(b_V);
    // a1 = relu(W_a1@[b2;thx;txu] + b)
    g_a1_k<<<dim3(32, 1, 8), 512, GEMM_SMEM>>>(b_a1);
    // apod = sigmoid(W_a2@a1 + b) * bcat -> g_aT (channel-last hi/lo)
    g_a2_k<<<dim3(32, 5, 8), 512, GEMM_SMEM>>>(b_a2);
    // conv3x3 + bias + relu -> main output
    mma_conv3_k<<<dim3(32, 2, 8), 512, GEMM_SMEM>>>(b_ot, out);
}

// round 7
// speedup vs baseline: 2.3975x; 1.2271x over previous
#include <cuda_runtime.h>
#include <cuda_bf16.h>
#include <cuda_fp16.h>
#include <math.h>
#include <stdint.h>

// ---------------------------------------------------------------------------
// Problem constants
// ---------------------------------------------------------------------------
#define HW     4096          // 64*64
#define NB     8
#define OUT_A_ELEMS (8 * 256 * 4096)   // "a" output
// output layout: a [8,256,64,64] followed by w [8,256]

typedef __nv_bfloat16 bf16;

// ---------------------------------------------------------------------------
// Scratch (static device globals -- no allocation allowed)
// ---------------------------------------------------------------------------
__device__ float g_txup[8 * 256 * 4096];   // upsampled tx (fp32)
__device__ float g_sum [8 * 256];          // stage-A GAP accumulator
__device__ float g_w   [8 * 256];          // normalized channel weights

// channel-last bf16 hi/lo activation planes [n*4096][C]  (bf16x3 GEMM chain)
__device__ __align__(16) bf16 g_thxh[8ULL * 4096 * 256], g_thxl[8ULL * 4096 * 256];
__device__ __align__(16) bf16 g_txuh[8ULL * 4096 * 256], g_txul[8ULL * 4096 * 256];
__device__ __align__(16) bf16 g_x2h [8ULL * 4096 * 256], g_x2l [8ULL * 4096 * 256];
__device__ __align__(16) bf16 g_b1h [8ULL * 4096 * 256], g_b1l [8ULL * 4096 * 256];
__device__ __align__(16) bf16 g_b2h [8ULL * 4096 * 128], g_b2l [8ULL * 4096 * 128];
__device__ __align__(16) bf16 g_a1h [8ULL * 4096 * 128], g_a1l [8ULL * 4096 * 128];

// fp16 single activation planes (fp16x2 consumers: stageA, conv3x3)
__device__ __align__(16) __half g_x1f [8ULL * 4096 * 256];
__device__ __align__(16) __half g_thxf[8ULL * 4096 * 256];
__device__ __align__(16) __half g_txuf[8ULL * 4096 * 256];
__device__ __align__(16) __half g_aT_f[8ULL * 4096 * 640];

// weight splits
__device__ __align__(16) __half g_wt1h[256 * 768], g_wt1l[256 * 768];   // fp16 hi/lo
__device__ __align__(16) bf16 g_wUh [256 * 256], g_wUl [256 * 256];
__device__ __align__(16) bf16 g_wVh [128 * 256], g_wVl [128 * 256];
__device__ __align__(16) bf16 g_wa1h[128 * 640], g_wa1l[128 * 640];
__device__ __align__(16) bf16 g_wa2h[640 * 128], g_wa2l[640 * 128];
// conv3x3 weights, tap-major [oc][tap*640+c], fp16 hi/lo
__device__ __align__(16) __half g_wfh[256 * 5760], g_wfl[256 * 5760];

// ---------------------------------------------------------------------------
// helpers
// ---------------------------------------------------------------------------
__device__ __forceinline__ uint32_t smem_to_u32(const void* p) {
    uint32_t a;
    asm("{ .reg .u64 t; cvta.to.shared.u64 t, %1; cvt.u32.u64 %0, t; }"
        : "=r"(a) : "l"(p));
    return a;
}

__device__ __forceinline__ void cp16(uint32_t dst, const void* src, uint32_t bytes) {
    asm volatile("cp.async.cg.shared.global [%0], [%1], 16, %2;"
                 :: "r"(dst), "l"(src), "r"(bytes) : "memory");
}
__device__ __forceinline__ void cp_commit() {
    asm volatile("cp.async.commit_group;" ::: "memory");
}
template<int N>
__device__ __forceinline__ void cp_wait() {
    asm volatile("cp.async.wait_group %0;" :: "n"(N) : "memory");
}

__device__ __forceinline__ void ldm_x4(uint32_t (&r)[4], uint32_t addr) {
    asm volatile("ldmatrix.sync.aligned.m8n8.x4.shared.b16 {%0,%1,%2,%3}, [%4];"
                 : "=r"(r[0]), "=r"(r[1]), "=r"(r[2]), "=r"(r[3]) : "r"(addr));
}

__device__ __forceinline__ void mma_bf16(float (&c)[4], const uint32_t (&a)[4],
                                         uint32_t b0, uint32_t b1) {
    asm volatile(
        "mma.sync.aligned.m16n8k16.row.col.f32.bf16.bf16.f32 "
        "{%0,%1,%2,%3}, {%4,%5,%6,%7}, {%8,%9}, {%0,%1,%2,%3};"
        : "+f"(c[0]), "+f"(c[1]), "+f"(c[2]), "+f"(c[3])
        : "r"(a[0]), "r"(a[1]), "r"(a[2]), "r"(a[3]), "r"(b0), "r"(b1));
}

__device__ __forceinline__ void mma_f16(float (&c)[4], const uint32_t (&a)[4],
                                        uint32_t b0, uint32_t b1) {
    asm volatile(
        "mma.sync.aligned.m16n8k16.row.col.f32.f16.f16.f32 "
        "{%0,%1,%2,%3}, {%4,%5,%6,%7}, {%8,%9}, {%0,%1,%2,%3};"
        : "+f"(c[0]), "+f"(c[1]), "+f"(c[2]), "+f"(c[3])
        : "r"(a[0]), "r"(a[1]), "r"(a[2]), "r"(a[3]), "r"(b0), "r"(b1));
}

// ---------------------------------------------------------------------------
// bilinear upsample x2, align_corners=True (32x32 -> 64x64), fp32 out
// ---------------------------------------------------------------------------
__global__ __launch_bounds__(256) void upsample_k(const float* __restrict__ tx)
{
    __shared__ float s[1024];
    const int bc = blockIdx.x;
    const float* src = tx + (size_t)bc * 1024;
    for (int idx = threadIdx.x; idx < 1024; idx += 256) s[idx] = src[idx];
    __syncthreads();

    float* dst = g_txup + (size_t)bc * 4096;
    const float step = 31.0f / 63.0f;
#pragma unroll
    for (int rpt = 0; rpt < 16; rpt++) {
        int opix = rpt * 256 + threadIdx.x;
        int y = opix >> 6, x = opix & 63;
        float fy = y * step;  int y0 = (int)fy;  float wy = fy - y0;
        int y1 = min(y0 + 1, 31);
        float fx = x * step;  int x0 = (int)fx;  float wx = fx - x0;
        int x1 = min(x0 + 1, 31);
        float top = s[y0 * 32 + x0] * (1.f - wx) + s[y0 * 32 + x1] * wx;
        float bot = s[y1 * 32 + x0] * (1.f - wx) + s[y1 * 32 + x1] * wx;
        dst[opix] = top * (1.f - wy) + bot * wy;
    }
}

__global__ void zero_sum_k()
{
    g_sum[blockIdx.x * 256 + threadIdx.x] = 0.f;
}

// ---------------------------------------------------------------------------
// transpose + split: [n][C][4096] fp32 -> [n*4096][C]
//  optional bf16 hi/lo pair outputs, optional fp16 single output
// ---------------------------------------------------------------------------
__device__ __forceinline__ void cvtT_body(const float* __restrict__ src,
                                          bf16* __restrict__ dh,
                                          bf16* __restrict__ dl,
                                          __half* __restrict__ df, int C)
{
    __shared__ float t[64][65];
    const int n = blockIdx.z, c0 = blockIdx.y * 64, p0 = blockIdx.x * 64;
    const float* sp = src + ((size_t)n * C + c0) * HW + p0;
    for (int it = threadIdx.x; it < 4096; it += 256) {
        int c = it >> 6, px = it & 63;
        t[c][px] = sp[(size_t)c * HW + px];
    }
    __syncthreads();
    for (int it = threadIdx.x; it < 4096; it += 256) {
        int px = it >> 6, c = it & 63;
        float v = t[c][px];
        size_t o = ((size_t)n * HW + p0 + px) * C + c0 + c;
        if (dh) {
            bf16 h = __float2bfloat16(v);
            bf16 l = __float2bfloat16(v - __bfloat162float(h));
            dh[o] = h; dl[o] = l;
        }
        if (df) df[o] = __float2half(v);
    }
}

__global__ __launch_bounds__(256) void cvt_sx1_k(const float* __restrict__ s)
{ cvtT_body(s, nullptr, nullptr, g_x1f, 256); }
__global__ __launch_bounds__(256) void cvt_thx_k(const float* __restrict__ s)
{ cvtT_body(s, g_thxh, g_thxl, g_thxf, 256); }
__global__ __launch_bounds__(256) void cvt_sx2_k(const float* __restrict__ s)
{ cvtT_body(s, g_x2h, g_x2l, nullptr, 256); }
__global__ __launch_bounds__(256) void cvt_txu_k()
{ cvtT_body(g_txup, g_txuh, g_txul, g_txuf, 256); }

// ---------------------------------------------------------------------------
// weight splits
// ---------------------------------------------------------------------------
__global__ __launch_bounds__(256) void split_all_k(
    const float* __restrict__ a, const float* __restrict__ b,
    const float* __restrict__ c, const float* __restrict__ d,
    const float* __restrict__ e)
{
    if (blockIdx.y == 0) {                       // W_t1 -> fp16 hi/lo
        for (int i = blockIdx.x * 256 + threadIdx.x; i < 256 * 768;
             i += gridDim.x * 256) {
            float v = a[i];
            __half hi = __float2half(v);
            g_wt1h[i] = hi;
            g_wt1l[i] = __float2half(v - __half2float(hi));
        }
        return;
    }
    const float* src; bf16 *h, *l; int nel;
    switch (blockIdx.y) {
        case 1:  src = b; h = g_wUh;  l = g_wUl;  nel = 256 * 256; break;
        case 2:  src = c; h = g_wVh;  l = g_wVl;  nel = 128 * 256; break;
        case 3:  src = d; h = g_wa1h; l = g_wa1l; nel = 128 * 640; break;
        default: src = e; h = g_wa2h; l = g_wa2l; nel = 640 * 128; break;
    }
    for (int i = blockIdx.x * 256 + threadIdx.x; i < nel; i += gridDim.x * 256) {
        float v = src[i];
        bf16 hi = __float2bfloat16(v);
        h[i] = hi;
        l[i] = __float2bfloat16(v - __bfloat162float(hi));
    }
}

// conv weights: [oc][c][ky][kx] fp32 -> tap-major [oc][tap*640+c] fp16 hi/lo
__global__ __launch_bounds__(256) void cvt_w_k(const float* __restrict__ W)
{
    const int oc = blockIdx.x;
    for (int t = threadIdx.x; t < 5760; t += 256) {
        int c = t / 9, tap = t - c * 9;
        float v = W[(size_t)oc * 5760 + t];
        __half h = __float2half(v);
        __half l = __float2half(v - __half2float(h));
        size_t o = (size_t)oc * 5760 + (size_t)tap * 640 + c;
        g_wfh[o] = h; g_wfl[o] = l;
    }
}

// ---------------------------------------------------------------------------
// Head (squeeze-excite MLP + L2 normalize); writes "w" output tail
// ---------------------------------------------------------------------------
__global__ __launch_bounds__(256) void head_k(
    const float* __restrict__ Wt2, const float* __restrict__ Wt3,
    float* __restrict__ outw)
{
    const int n = blockIdx.x, tid = threadIdx.x;
    __shared__ float w1[256], w2[64], red[256];

    w1[tid] = g_sum[n * 256 + tid] * (1.f / 4096.f);
    __syncthreads();

    if (tid < 64) {
        float s = 0.f;
#pragma unroll 8
        for (int k = 0; k < 256; k++) s = fmaf(Wt2[tid * 256 + k], w1[k], s);
        w2[tid] = fmaxf(s, 0.f);
    }
    __syncthreads();

    float s = 0.f;
#pragma unroll
    for (int e = 0; e < 64; e++) s = fmaf(Wt3[tid * 64 + e], w2[e], s);

    red[tid] = s * s;
    __syncthreads();
    for (int off = 128; off > 0; off >>= 1) {
        if (tid < off) red[tid] += red[tid + off];
        __syncthreads();
    }
    float nv = sqrtf(red[0]);
    float wv = s / fmaxf(nv, 1e-12f);
    g_w[n * 256 + tid] = wv;
    outw[n * 256 + tid] = wv;
}

// ---------------------------------------------------------------------------
// Unified mma.sync 1x1-conv GEMM.
//   FP16_2P=0: bf16x3 compensated (AhBh + AhBl + AlBh)
//   FP16_2P=1: fp16 2-pass (AhB + AlB), B single fp16
// MODE 0: relu(acc+bias), GAP-sum -> atomicAdd g_sum
// MODE 1: relu(acc+bias) * g_w  -> bf16 hi/lo channel-last
// MODE 2: relu(acc+bias)        -> bf16 hi/lo channel-last
// MODE 3: sigmoid(acc+bias) * bcat -> fp16 single channel-last (g_aT_f)
// ---------------------------------------------------------------------------
#define TILE_B   10240                 // one 128x40 16-bit tile
#define STAGE_B  (4 * TILE_B)
#define GEMM_SMEM (2 * STAGE_B)        // 81920 bytes

template<int MODE, int FP16_2P>
__device__ __forceinline__ void gemm_body(
    int K, int COUT,
    const void* s0h, const void* s0l, int st0,
    const void* s1h, const void* s1l, int st1,
    const void* s2h, const void* s2l, int st2,
    int kb0, int kb1,
    const void* wh, const void* wl,
    const float* __restrict__ bias,
    bf16* __restrict__ oh, bf16* __restrict__ ol,
    __half* __restrict__ of)
{
    extern __shared__ __align__(128) char smem[];
    const uint32_t sb = smem_to_u32(smem);

    const int tid  = threadIdx.x;
    const int lane = tid & 31;
    const int wid  = tid >> 5;
    const int wm   = wid & 3;
    const int wn   = wid >> 2;
    const int n    = blockIdx.z;
    const int ocb  = blockIdx.y * 128;
    const int p0   = blockIdx.x * 128;

    float acc[2][4][4];
#pragma unroll
    for (int mi = 0; mi < 2; mi++)
#pragma unroll
        for (int ni = 0; ni < 4; ni++)
#pragma unroll
            for (int r = 0; r < 4; r++) acc[mi][ni][r] = 0.f;

    auto stage = [&](int chunk) {
        const uint32_t base = sb + (chunk & 1) * STAGE_B;
        const int k0 = chunk * 32;
        const char *sh, *sl; int stride, ks;
        if (k0 < kb0)      { sh = (const char*)s0h; sl = (const char*)s0l; stride = st0; ks = 0;   }
        else if (k0 < kb1) { sh = (const char*)s1h; sl = (const char*)s1l; stride = st1; ks = kb0; }
        else               { sh = (const char*)s2h; sl = (const char*)s2l; stride = st2; ks = kb1; }
        const int c0 = k0 - ks;
#pragma unroll
        for (int it = tid; it < 1024; it += 512) {
            int half = it >> 9, row = (it >> 2) & 127, seg = it & 3;
            const char* w = half ? (const char*)wl : (const char*)wh;
            cp16(base + half * TILE_B + row * 80 + seg * 16,
                 w + 2 * ((size_t)(ocb + row) * K + k0 + seg * 8), 16);
        }
        if (FP16_2P) {
#pragma unroll
            for (int it = tid; it < 512; it += 512) {
                int row = (it >> 2) & 127, seg = it & 3;
                cp16(base + 2 * TILE_B + row * 80 + seg * 16,
                     sh + 2 * (((size_t)n * HW + p0 + row) * stride + c0 + seg * 8), 16);
            }
        } else {
#pragma unroll
            for (int it = tid; it < 1024; it += 512) {
                int half = it >> 9, row = (it >> 2) & 127, seg = it & 3;
                const char* a = half ? sl : sh;
                cp16(base + (2 + half) * TILE_B + row * 80 + seg * 16,
                     a + 2 * (((size_t)n * HW + p0 + row) * stride + c0 + seg * 8), 16);
            }
        }
    };

    const int NC = K >> 5;
    stage(0);
    cp_commit();

    for (int i = 0; i < NC; i++) {
        if (i + 1 < NC) { stage(i + 1); cp_commit(); cp_wait<1>(); }
        else            cp_wait<0>();
        __syncthreads();

        const uint32_t base = sb + (i & 1) * STAGE_B;
        const uint32_t aAh = base;
        const uint32_t aAl = base + TILE_B;
        const uint32_t aBh = base + 2 * TILE_B;
        const uint32_t aBl = base + 3 * TILE_B;

#pragma unroll
        for (int ks = 0; ks < 2; ks++) {
            const int kb = ks * 32;
            uint32_t ah[2][4], al[2][4];
#pragma unroll
            for (int mi = 0; mi < 2; mi++) {
                uint32_t ro = (uint32_t)(wm * 32 + mi * 16 + (lane & 15)) * 80
                            + (uint32_t)(lane >> 4) * 16 + kb;
                ldm_x4(ah[mi], aAh + ro);
                ldm_x4(al[mi], aAl + ro);
            }
#pragma unroll
            for (int ni = 0; ni < 4; ni++) {
                uint32_t ro = (uint32_t)(wn * 32 + ni * 8 + (lane >> 2)) * 80
                            + kb + (uint32_t)(lane & 3) * 4;
                uint32_t bh0 = *(const uint32_t*)(smem + (aBh + ro      - sb));
                uint32_t bh1 = *(const uint32_t*)(smem + (aBh + ro + 16 - sb));
                if (FP16_2P) {
#pragma unroll
                    for (int mi = 0; mi < 2; mi++) {
                        mma_f16(acc[mi][ni], ah[mi], bh0, bh1);
                        mma_f16(acc[mi][ni], al[mi], bh0, bh1);
                    }
                } else {
                    uint32_t bl0 = *(const uint32_t*)(smem + (aBl + ro      - sb));
                    uint32_t bl1 = *(const uint32_t*)(smem + (aBl + ro + 16 - sb));
#pragma unroll
                    for (int mi = 0; mi < 2; mi++) {
                        mma_bf16(acc[mi][ni], ah[mi], bh0, bh1);
                        mma_bf16(acc[mi][ni], ah[mi], bl0, bl1);
                        mma_bf16(acc[mi][ni], al[mi], bh0, bh1);
                    }
                }
            }
        }
        __syncthreads();
    }

    if (MODE == 0) {
#pragma unroll
        for (int mi = 0; mi < 2; mi++) {
            int r0 = ocb + wm * 32 + mi * 16 + (lane >> 2);
            float b0 = bias[r0], b1 = bias[r0 + 8];
            float s0 = 0.f, s1 = 0.f;
#pragma unroll
            for (int ni = 0; ni < 4; ni++) {
                s0 += fmaxf(acc[mi][ni][0] + b0, 0.f) + fmaxf(acc[mi][ni][1] + b0, 0.f);
                s1 += fmaxf(acc[mi][ni][2] + b1, 0.f) + fmaxf(acc[mi][ni][3] + b1, 0.f);
            }
            s0 += __shfl_xor_sync(0xffffffffu, s0, 1);
            s0 += __shfl_xor_sync(0xffffffffu, s0, 2);
            s1 += __shfl_xor_sync(0xffffffffu, s1, 1);
            s1 += __shfl_xor_sync(0xffffffffu, s1, 2);
            if ((lane & 3) == 0) {
                atomicAdd(&g_sum[n * 256 + r0],     s0);
                atomicAdd(&g_sum[n * 256 + r0 + 8], s1);
            }
        }
        return;
    }

    // transpose epilogue: per-warp 32x32 patch in (reused) smem
    __syncthreads();
    float* patch = (float*)smem + wid * (32 * 33);
#pragma unroll
    for (int mi = 0; mi < 2; mi++)
#pragma unroll
        for (int ni = 0; ni < 4; ni++) {
            int r = mi * 16 + (lane >> 2);
            int p = ni * 8 + (lane & 3) * 2;
            patch[r * 33 + p]           = acc[mi][ni][0];
            patch[r * 33 + p + 1]       = acc[mi][ni][1];
            patch[(r + 8) * 33 + p]     = acc[mi][ni][2];
            patch[(r + 8) * 33 + p + 1] = acc[mi][ni][3];
        }
    __syncwarp();

    const int pxg = p0 + wn * 32 + lane;
    const int oc0 = ocb + wm * 32;

    if (MODE == 3) {
        const bf16 *gh, *gl; int gst, gks;
        if (oc0 < 128)      { gh = g_b2h;  gl = g_b2l;  gst = 128; gks = 0;   }
        else if (oc0 < 384) { gh = g_thxh; gl = g_thxl; gst = 256; gks = 128; }
        else                { gh = g_txuh; gl = g_txul; gst = 256; gks = 384; }
        __half ff[32];
#pragma unroll
        for (int j = 0; j < 32; j++) {
            float v = patch[j * 33 + lane] + bias[oc0 + j];
            float sg = 1.f / (1.f + expf(-v));
            size_t gi = ((size_t)n * HW + pxg) * gst + (oc0 - gks) + j;
            ff[j] = __float2half(sg * (__bfloat162float(gh[gi]) + __bfloat162float(gl[gi])));
        }
        size_t o = ((size_t)n * HW + pxg) * COUT + oc0;
#pragma unroll
        for (int q = 0; q < 4; q++)
            *(uint4*)(of + o + q * 8) = ((const uint4*)ff)[q];
        return;
    }

    bf16 hh[32], ll[32];
#pragma unroll
    for (int j = 0; j < 32; j++) {
        float v = patch[j * 33 + lane] + bias[oc0 + j];
        if (MODE == 1)      v = fmaxf(v, 0.f) * g_w[n * 256 + oc0 + j];
        else                v = fmaxf(v, 0.f);
        bf16 h = __float2bfloat16(v);
        hh[j] = h;
        ll[j] = __float2bfloat16(v - __bfloat162float(h));
    }
    size_t o = ((size_t)n * HW + pxg) * COUT + oc0;
#pragma unroll
    for (int q = 0; q < 4; q++) {
        *(uint4*)(oh + o + q * 8) = ((const uint4*)hh)[q];
        *(uint4*)(ol + o + q * 8) = ((const uint4*)ll)[q];
    }
}

// ----- wrappers -------------------------------------------------------------
__global__ __launch_bounds__(512) void g_stageA_k(const float* __restrict__ bias)
{
    gemm_body<0, 1>(768, 256, g_x1f, nullptr, 256, g_thxf, nullptr, 256,
                    g_txuf, nullptr, 256, 256, 512,
                    g_wt1h, g_wt1l, bias, nullptr, nullptr, nullptr);
}
__global__ __launch_bounds__(512) void g_b1_k(const float* __restrict__ bias)
{
    gemm_body<1, 0>(256, 256, g_x2h, g_x2l, 256, nullptr, nullptr, 0,
                    nullptr, nullptr, 0, 256, 256,
                    g_wUh, g_wUl, bias, g_b1h, g_b1l, nullptr);
}
__global__ __launch_bounds__(512) void g_b2_k(const float* __restrict__ bias)
{
    gemm_body<2, 0>(256, 128, g_b1h, g_b1l, 256, nullptr, nullptr, 0,
                    nullptr, nullptr, 0, 256, 256,
                    g_wVh, g_wVl, bias, g_b2h, g_b2l, nullptr);
}
__global__ __launch_bounds__(512) void g_a1_k(const float* __restrict__ bias)
{
    gemm_body<2, 0>(640, 128, g_b2h, g_b2l, 128, g_thxh, g_thxl, 256,
                    g_txuh, g_txul, 256, 128, 384,
                    g_wa1h, g_wa1l, bias, g_a1h, g_a1l, nullptr);
}
__global__ __launch_bounds__(512) void g_a2_k(const float* __restrict__ bias)
{
    gemm_body<3, 0>(128, 640, g_a1h, g_a1l, 128, nullptr, nullptr, 0,
                    nullptr, nullptr, 0, 128, 128,
                    g_wa2h, g_wa2l, bias, nullptr, nullptr, g_aT_f);
}

// ---------------------------------------------------------------------------
// mma.sync conv3x3, fp16 2-pass (A = W fp16 hi/lo, B = act fp16 single)
// ---------------------------------------------------------------------------
__global__ __launch_bounds__(512) void mma_conv3_k(
    const float* __restrict__ bot, float* __restrict__ out)
{
    extern __shared__ __align__(128) char smem[];
    const uint32_t sb = smem_to_u32(smem);

    const int tid  = threadIdx.x;
    const int lane = tid & 31;
    const int wid  = tid >> 5;
    const int wm   = wid & 3;
    const int wn   = wid >> 2;
    const int n    = blockIdx.z;
    const int ocb  = blockIdx.y * 128;
    const int p0   = blockIdx.x * 128;

    float acc[2][4][4];
#pragma unroll
    for (int mi = 0; mi < 2; mi++)
#pragma unroll
        for (int ni = 0; ni < 4; ni++)
#pragma unroll
            for (int r = 0; r < 4; r++) acc[mi][ni][r] = 0.f;

    auto stage = [&](int chunk) {
        const uint32_t base = sb + (chunk & 1) * STAGE_B;
        const int tap = chunk / 20;
        const int dy = tap / 3 - 1, dx = tap % 3 - 1;
        const int c0 = (chunk - tap * 20) * 32;
        const int k0 = chunk * 32;
#pragma unroll
        for (int it = tid; it < 1024; it += 512) {
            int half = it >> 9, row = (it >> 2) & 127, seg = it & 3;
            const __half* w = half ? g_wfl : g_wfh;
            cp16(base + half * TILE_B + row * 80 + seg * 16,
                 w + (size_t)(ocb + row) * 5760 + k0 + seg * 8, 16);
        }
#pragma unroll
        for (int it = tid; it < 512; it += 512) {
            int row = (it >> 2) & 127, seg = it & 3;
            int p = p0 + row;
            int iy = (p >> 6) + dy, ix = (p & 63) + dx;
            bool ok = ((unsigned)iy < 64u) && ((unsigned)ix < 64u);
            const __half* src = ok
                ? g_aT_f + ((size_t)(n * HW + iy * 64 + ix)) * 640 + c0 + seg * 8
                : g_aT_f;
            cp16(base + 2 * TILE_B + row * 80 + seg * 16, src, ok ? 16u : 0u);
        }
    };

    stage(0);
    cp_commit();

    const int NCHUNK = 180;
    for (int i = 0; i < NCHUNK; i++) {
        if (i + 1 < NCHUNK) { stage(i + 1); cp_commit(); cp_wait<1>(); }
        else                cp_wait<0>();
        __syncthreads();

        const uint32_t base = sb + (i & 1) * STAGE_B;
        const uint32_t aAh = base;
        const uint32_t aAl = base + TILE_B;
        const uint32_t aBh = base + 2 * TILE_B;

#pragma unroll
        for (int ks = 0; ks < 2; ks++) {
            const int kb = ks * 32;
            uint32_t ah[2][4], al[2][4];
#pragma unroll
            for (int mi = 0; mi < 2; mi++) {
                uint32_t ro = (uint32_t)(wm * 32 + mi * 16 + (lane & 15)) * 80
                            + (uint32_t)(lane >> 4) * 16 + kb;
                ldm_x4(ah[mi], aAh + ro);
                ldm_x4(al[mi], aAl + ro);
            }
#pragma unroll
            for (int ni = 0; ni < 4; ni++) {
                uint32_t ro = (uint32_t)(wn * 32 + ni * 8 + (lane >> 2)) * 80
                            + kb + (uint32_t)(lane & 3) * 4;
                uint32_t bh0 = *(const uint32_t*)(smem + (aBh + ro      - sb));
                uint32_t bh1 = *(const uint32_t*)(smem + (aBh + ro + 16 - sb));
#pragma unroll
                for (int mi = 0; mi < 2; mi++) {
                    mma_f16(acc[mi][ni], ah[mi], bh0, bh1);
                    mma_f16(acc[mi][ni], al[mi], bh0, bh1);
                }
            }
        }
        __syncthreads();
    }

    const size_t nb = (size_t)n * 256 * HW;
#pragma unroll
    for (int mi = 0; mi < 2; mi++) {
        int r0 = ocb + wm * 32 + mi * 16 + (lane >> 2);
        float bv0 = bot[r0], bv1 = bot[r0 + 8];
#pragma unroll
        for (int ni = 0; ni < 4; ni++) {
            int px = p0 + wn * 32 + ni * 8 + (lane & 3) * 2;
            float2 v0, v1;
            v0.x = fmaxf(acc[mi][ni][0] + bv0, 0.f);
            v0.y = fmaxf(acc[mi][ni][1] + bv0, 0.f);
            v1.x = fmaxf(acc[mi][ni][2] + bv1, 0.f);
            v1.y = fmaxf(acc[mi][ni][3] + bv1, 0.f);
            *(float2*)(out + nb + (size_t)r0 * HW + px)       = v0;
            *(float2*)(out + nb + (size_t)(r0 + 8) * HW + px) = v1;
        }
    }
}

// ---------------------------------------------------------------------------
// Launch
// ---------------------------------------------------------------------------
extern "C" void kernel_launch(void* const* d_in, const int* in_sizes, int n_in,
                              void* d_out, int out_size)
{
    const float* sx1  = (const float*)d_in[0];
    const float* sx2  = (const float*)d_in[1];
    const float* t_hx = (const float*)d_in[2];
    const float* tx   = (const float*)d_in[3];
    const float* W_t1 = (const float*)d_in[4];
    const float* b_t1 = (const float*)d_in[5];
    const float* W_t2 = (const float*)d_in[6];
    const float* W_t3 = (const float*)d_in[7];
    const float* W_U  = (const float*)d_in[8];
    const float* b_U  = (const float*)d_in[9];
    const float* W_V  = (const float*)d_in[10];
    const float* b_V  = (const float*)d_in[11];
    const float* W_a1 = (const float*)d_in[12];
    const float* b_a1 = (const float*)d_in[13];
    const float* W_a2 = (const float*)d_in[14];
    const float* b_a2 = (const float*)d_in[15];
    const float* W_ot = (const float*)d_in[16];
    const float* b_ot = (const float*)d_in[17];
    float* out = (float*)d_out;

    cudaFuncSetAttribute(g_stageA_k, cudaFuncAttributeMaxDynamicSharedMemorySize, GEMM_SMEM);
    cudaFuncSetAttribute(g_b1_k,     cudaFuncAttributeMaxDynamicSharedMemorySize, GEMM_SMEM);
    cudaFuncSetAttribute(g_b2_k,     cudaFuncAttributeMaxDynamicSharedMemorySize, GEMM_SMEM);
    cudaFuncSetAttribute(g_a1_k,     cudaFuncAttributeMaxDynamicSharedMemorySize, GEMM_SMEM);
    cudaFuncSetAttribute(g_a2_k,     cudaFuncAttributeMaxDynamicSharedMemorySize, GEMM_SMEM);
    cudaFuncSetAttribute(mma_conv3_k, cudaFuncAttributeMaxDynamicSharedMemorySize, GEMM_SMEM);

    // weight conversions
    split_all_k<<<dim3(96, 5), 256>>>(W_t1, W_U, W_V, W_a1, W_a2);
    cvt_w_k<<<256, 256>>>(W_ot);
    // upsample + activation conversions
    upsample_k<<<2048, 256>>>(tx);
    cvt_sx1_k<<<dim3(64, 4, 8), 256>>>(sx1);
    cvt_thx_k<<<dim3(64, 4, 8), 256>>>(t_hx);
    cvt_sx2_k<<<dim3(64, 4, 8), 256>>>(sx2);
    cvt_txu_k<<<dim3(64, 4, 8), 256>>>();
    zero_sum_k<<<8, 256>>>();
    // stage A GEMM + GAP (fp16 2-pass)
    g_stageA_k<<<dim3(32, 2, 8), 512, GEMM_SMEM>>>(b_t1);
    // head MLP + normalize
    head_k<<<8, 256>>>(W_t2, W_t3, out + OUT_A_ELEMS);
    // b1 = relu(W_U@sx2 + b)*w   (bf16x3)
    g_b1_k<<<dim3(32, 2, 8), 512, GEMM_SMEM>>>(b_U);
    // b2 = relu(W_V@b1 + b)      (bf16x3)
    g_b2_k<<<dim3(32, 1, 8), 512, GEMM_SMEM>>>(b_V);
    // a1 = relu(W_a1@[b2;thx;txu] + b)  (bf16x3)
    g_a1_k<<<dim3(32, 1, 8), 512, GEMM_SMEM>>>(b_a1);
    // apod = sigmoid(W_a2@a1 + b) * bcat -> g_aT_f (fp16 channel-last)
    g_a2_k<<<dim3(32, 5, 8), 512, GEMM_SMEM>>>(b_a2);
    // conv3x3 + bias + relu -> main output (fp16 2-pass)
    mma_conv3_k<<<dim3(32, 2, 8), 512, GEMM_SMEM>>>(b_ot, out);
}

// round 8
// speedup vs baseline: 2.9507x; 1.2307x over previous
#include <cuda_runtime.h>
#include <cuda_fp16.h>
#include <math.h>
#include <stdint.h>

// ---------------------------------------------------------------------------
// Problem constants
// ---------------------------------------------------------------------------
#define HW     4096          // 64*64
#define NB     8
#define OUT_A_ELEMS (8 * 256 * 4096)   // "a" output
// output layout: a [8,256,64,64] followed by w [8,256]

// ---------------------------------------------------------------------------
// Scratch (static device globals -- no allocation allowed)
// ---------------------------------------------------------------------------
__device__ float g_sum [8 * 256];          // stage-A GAP accumulator
__device__ float g_w   [8 * 256];          // normalized channel weights

// fp16 channel-last activation planes [n*4096][C]
__device__ __align__(16) __half g_x1f [8ULL * 4096 * 256];
__device__ __align__(16) __half g_thxf[8ULL * 4096 * 256];
__device__ __align__(16) __half g_txuf[8ULL * 4096 * 256];
__device__ __align__(16) __half g_x2f [8ULL * 4096 * 256];
__device__ __align__(16) __half g_b1f [8ULL * 4096 * 256];
__device__ __align__(16) __half g_b2f [8ULL * 4096 * 128];
__device__ __align__(16) __half g_a1f [8ULL * 4096 * 128];
__device__ __align__(16) __half g_aT_f[8ULL * 4096 * 640];

// fp16 hi/lo weight splits (row-major [O][K])
__device__ __align__(16) __half g_wt1h[256 * 768], g_wt1l[256 * 768];
__device__ __align__(16) __half g_wUh [256 * 256], g_wUl [256 * 256];
__device__ __align__(16) __half g_wVh [128 * 256], g_wVl [128 * 256];
__device__ __align__(16) __half g_wa1h[128 * 640], g_wa1l[128 * 640];
__device__ __align__(16) __half g_wa2h[640 * 128], g_wa2l[640 * 128];
// conv3x3 weights, tap-major [oc][tap*640+c]
__device__ __align__(16) __half g_wfh[256 * 5760], g_wfl[256 * 5760];

// ---------------------------------------------------------------------------
// helpers
// ---------------------------------------------------------------------------
__device__ __forceinline__ uint32_t smem_to_u32(const void* p) {
    uint32_t a;
    asm("{ .reg .u64 t; cvta.to.shared.u64 t, %1; cvt.u32.u64 %0, t; }"
        : "=r"(a) : "l"(p));
    return a;
}

__device__ __forceinline__ void cp16(uint32_t dst, const void* src, uint32_t bytes) {
    asm volatile("cp.async.cg.shared.global [%0], [%1], 16, %2;"
                 :: "r"(dst), "l"(src), "r"(bytes) : "memory");
}
__device__ __forceinline__ void cp_commit() {
    asm volatile("cp.async.commit_group;" ::: "memory");
}
template<int N>
__device__ __forceinline__ void cp_wait() {
    asm volatile("cp.async.wait_group %0;" :: "n"(N) : "memory");
}

__device__ __forceinline__ void ldm_x4(uint32_t (&r)[4], uint32_t addr) {
    asm volatile("ldmatrix.sync.aligned.m8n8.x4.shared.b16 {%0,%1,%2,%3}, [%4];"
                 : "=r"(r[0]), "=r"(r[1]), "=r"(r[2]), "=r"(r[3]) : "r"(addr));
}

__device__ __forceinline__ void mma_f16(float (&c)[4], const uint32_t (&a)[4],
                                        uint32_t b0, uint32_t b1) {
    asm volatile(
        "mma.sync.aligned.m16n8k16.row.col.f32.f16.f16.f32 "
        "{%0,%1,%2,%3}, {%4,%5,%6,%7}, {%8,%9}, {%0,%1,%2,%3};"
        : "+f"(c[0]), "+f"(c[1]), "+f"(c[2]), "+f"(c[3])
        : "r"(a[0]), "r"(a[1]), "r"(a[2]), "r"(a[3]), "r"(b0), "r"(b1));
}

// ---------------------------------------------------------------------------
// fused upsample x2 (align_corners) + transpose + fp16: tx -> g_txuf
//   block: (y-row, 64-ch block, n); computes one output row for 64 channels
// ---------------------------------------------------------------------------
__global__ __launch_bounds__(256) void ups_cvt_k(const float* __restrict__ tx)
{
    __shared__ float s0[64][32], s1[64][32];
    const int y  = blockIdx.x;
    const int c0 = blockIdx.y * 64;
    const int n  = blockIdx.z;

    const float step = 31.0f / 63.0f;
    const float fy = y * step;
    const int y0 = (int)fy;
    const int y1 = min(y0 + 1, 31);
    const float wy = fy - y0;

    for (int it = threadIdx.x; it < 4096; it += 256) {
        int c = it >> 6, r = (it >> 5) & 1, x = it & 31;
        const float* sp = tx + (((size_t)(n * 256 + c0 + c) * 32) + (r ? y1 : y0)) * 32;
        if (r) s1[c][x] = sp[x]; else s0[c][x] = sp[x];
    }
    __syncthreads();

    for (int it = threadIdx.x; it < 4096; it += 256) {
        int x = it >> 6, c = it & 63;
        float fx = x * step;
        int x0 = (int)fx;  float wx = fx - x0;
        int x1 = min(x0 + 1, 31);
        float top = s0[c][x0] * (1.f - wx) + s0[c][x1] * wx;
        float bot = s1[c][x0] * (1.f - wx) + s1[c][x1] * wx;
        g_txuf[((size_t)n * HW + y * 64 + x) * 256 + c0 + c] =
            __float2half(top * (1.f - wy) + bot * wy);
    }
}

// ---------------------------------------------------------------------------
// transpose + fp16: [n][256][4096] fp32 -> [n*4096][256] fp16 (3 sources)
// ---------------------------------------------------------------------------
__global__ __launch_bounds__(256) void cvt3_k(
    const float* __restrict__ sx1, const float* __restrict__ t_hx,
    const float* __restrict__ sx2)
{
    __shared__ float t[64][65];
    const int src = blockIdx.y >> 2;
    const int c0  = (blockIdx.y & 3) * 64;
    const int n   = blockIdx.z, p0 = blockIdx.x * 64;
    const float* sp = (src == 0 ? sx1 : src == 1 ? t_hx : sx2)
                    + ((size_t)n * 256 + c0) * HW + p0;
    __half* dst = (src == 0 ? g_x1f : src == 1 ? g_thxf : g_x2f);

    for (int it = threadIdx.x; it < 4096; it += 256) {
        int c = it >> 6, px = it & 63;
        t[c][px] = sp[(size_t)c * HW + px];
    }
    __syncthreads();
    for (int it = threadIdx.x; it < 4096; it += 256) {
        int px = it >> 6, c = it & 63;
        dst[((size_t)n * HW + p0 + px) * 256 + c0 + c] = __float2half(t[c][px]);
    }
}

// ---------------------------------------------------------------------------
// weight splits (fp16 hi/lo) + g_sum zeroing
// ---------------------------------------------------------------------------
__global__ __launch_bounds__(256) void split_all_k(
    const float* __restrict__ a, const float* __restrict__ b,
    const float* __restrict__ c, const float* __restrict__ d,
    const float* __restrict__ e)
{
    if (blockIdx.y == 5) {
        int i = blockIdx.x * 256 + threadIdx.x;
        if (i < 8 * 256) g_sum[i] = 0.f;
        return;
    }
    const float* src; __half *h, *l; int nel;
    switch (blockIdx.y) {
        case 0:  src = a; h = g_wt1h; l = g_wt1l; nel = 256 * 768; break;
        case 1:  src = b; h = g_wUh;  l = g_wUl;  nel = 256 * 256; break;
        case 2:  src = c; h = g_wVh;  l = g_wVl;  nel = 128 * 256; break;
        case 3:  src = d; h = g_wa1h; l = g_wa1l; nel = 128 * 640; break;
        default: src = e; h = g_wa2h; l = g_wa2l; nel = 640 * 128; break;
    }
    for (int i = blockIdx.x * 256 + threadIdx.x; i < nel; i += gridDim.x * 256) {
        float v = src[i];
        __half hi = __float2half(v);
        h[i] = hi;
        l[i] = __float2half(v - __half2float(hi));
    }
}

// conv weights: [oc][c][ky][kx] fp32 -> tap-major [oc][tap*640+c] fp16 hi/lo
__global__ __launch_bounds__(256) void cvt_w_k(const float* __restrict__ W)
{
    const int oc = blockIdx.x;
    for (int t = threadIdx.x; t < 5760; t += 256) {
        int c = t / 9, tap = t - c * 9;
        float v = W[(size_t)oc * 5760 + t];
        __half h = __float2half(v);
        __half l = __float2half(v - __half2float(h));
        size_t o = (size_t)oc * 5760 + (size_t)tap * 640 + c;
        g_wfh[o] = h; g_wfl[o] = l;
    }
}

// ---------------------------------------------------------------------------
// Head (squeeze-excite MLP + L2 normalize); writes "w" output tail
// ---------------------------------------------------------------------------
__global__ __launch_bounds__(256) void head_k(
    const float* __restrict__ Wt2, const float* __restrict__ Wt3,
    float* __restrict__ outw)
{
    const int n = blockIdx.x, tid = threadIdx.x;
    __shared__ float w1[256], w2[64], red[256];

    w1[tid] = g_sum[n * 256 + tid] * (1.f / 4096.f);
    __syncthreads();

    if (tid < 64) {
        float s = 0.f;
#pragma unroll 8
        for (int k = 0; k < 256; k++) s = fmaf(Wt2[tid * 256 + k], w1[k], s);
        w2[tid] = fmaxf(s, 0.f);
    }
    __syncthreads();

    float s = 0.f;
#pragma unroll
    for (int e = 0; e < 64; e++) s = fmaf(Wt3[tid * 64 + e], w2[e], s);

    red[tid] = s * s;
    __syncthreads();
    for (int off = 128; off > 0; off >>= 1) {
        if (tid < off) red[tid] += red[tid + off];
        __syncthreads();
    }
    float nv = sqrtf(red[0]);
    float wv = s / fmaxf(nv, 1e-12f);
    g_w[n * 256 + tid] = wv;
    outw[n * 256 + tid] = wv;
}

// ---------------------------------------------------------------------------
// Unified mma.sync 1x1-conv GEMM, fp16 2-pass (W = fp16 hi/lo, act = fp16).
//   CTA 128oc x 128px, 16 warps 32x32, K chunks of 32, 4-stage cp.async.
// MODE 0: relu(acc+bias), GAP-sum -> atomicAdd g_sum
// MODE 1: relu(acc+bias) * g_w  -> fp16 channel-last
// MODE 2: relu(acc+bias)        -> fp16 channel-last
// MODE 3: sigmoid(acc+bias) * bcat -> fp16 channel-last (bcat = b2|thx|txu)
// ---------------------------------------------------------------------------
#define TILE_B   10240                 // one 128x40 fp16 tile
#define ST3      (3 * TILE_B)          // Ah, Al, B
#define NST      4
#define GEMM_SMEM (NST * ST3)          // 122880 bytes

template<int MODE>
__device__ __forceinline__ void gemm_body(
    int K, int COUT,
    const __half* s0, int st0,
    const __half* s1, int st1,
    const __half* s2, int st2,
    int kb0, int kb1,
    const __half* wh, const __half* wl,
    const float* __restrict__ bias,
    __half* __restrict__ of)
{
    extern __shared__ __align__(128) char smem[];
    const uint32_t sb = smem_to_u32(smem);

    const int tid  = threadIdx.x;
    const int lane = tid & 31;
    const int wid  = tid >> 5;
    const int wm   = wid & 3;
    const int wn   = wid >> 2;
    const int n    = blockIdx.z;
    const int ocb  = blockIdx.y * 128;
    const int p0   = blockIdx.x * 128;

    float acc[2][4][4];
#pragma unroll
    for (int mi = 0; mi < 2; mi++)
#pragma unroll
        for (int ni = 0; ni < 4; ni++)
#pragma unroll
            for (int r = 0; r < 4; r++) acc[mi][ni][r] = 0.f;

    auto stage = [&](int chunk) {
        const uint32_t base = sb + (chunk & 3) * ST3;
        const int k0 = chunk * 32;
        const __half* sh; int stride, ks;
        if (k0 < kb0)      { sh = s0; stride = st0; ks = 0;   }
        else if (k0 < kb1) { sh = s1; stride = st1; ks = kb0; }
        else               { sh = s2; stride = st2; ks = kb1; }
        const int c0 = k0 - ks;
#pragma unroll
        for (int it = tid; it < 1024; it += 512) {
            int half = it >> 9, row = (it >> 2) & 127, seg = it & 3;
            const __half* w = half ? wl : wh;
            cp16(base + half * TILE_B + row * 80 + seg * 16,
                 w + (size_t)(ocb + row) * K + k0 + seg * 8, 16);
        }
        {
            int row = (tid >> 2) & 127, seg = tid & 3;
            if (tid < 512)
                cp16(base + 2 * TILE_B + row * 80 + seg * 16,
                     sh + ((size_t)n * HW + p0 + row) * stride + c0 + seg * 8, 16);
        }
    };

    const int NC = K >> 5;
    stage(0); cp_commit();
    stage(1); cp_commit();

    for (int i = 0; i < NC; i++) {
        if (i + 2 < NC)      { stage(i + 2); cp_commit(); cp_wait<2>(); }
        else if (i + 1 < NC) cp_wait<1>();
        else                 cp_wait<0>();
        __syncthreads();

        const uint32_t base = sb + (i & 3) * ST3;
        const uint32_t aAh = base;
        const uint32_t aAl = base + TILE_B;
        const uint32_t aBh = base + 2 * TILE_B;

#pragma unroll
        for (int ks = 0; ks < 2; ks++) {
            const int kb = ks * 32;
            uint32_t ah[2][4], al[2][4];
#pragma unroll
            for (int mi = 0; mi < 2; mi++) {
                uint32_t ro = (uint32_t)(wm * 32 + mi * 16 + (lane & 15)) * 80
                            + (uint32_t)(lane >> 4) * 16 + kb;
                ldm_x4(ah[mi], aAh + ro);
                ldm_x4(al[mi], aAl + ro);
            }
#pragma unroll
            for (int ni = 0; ni < 4; ni++) {
                uint32_t ro = (uint32_t)(wn * 32 + ni * 8 + (lane >> 2)) * 80
                            + kb + (uint32_t)(lane & 3) * 4;
                uint32_t bh0 = *(const uint32_t*)(smem + (aBh + ro      - sb));
                uint32_t bh1 = *(const uint32_t*)(smem + (aBh + ro + 16 - sb));
#pragma unroll
                for (int mi = 0; mi < 2; mi++) {
                    mma_f16(acc[mi][ni], ah[mi], bh0, bh1);
                    mma_f16(acc[mi][ni], al[mi], bh0, bh1);
                }
            }
        }
    }

    if (MODE == 0) {
#pragma unroll
        for (int mi = 0; mi < 2; mi++) {
            int r0 = ocb + wm * 32 + mi * 16 + (lane >> 2);
            float b0 = bias[r0], b1 = bias[r0 + 8];
            float s0v = 0.f, s1v = 0.f;
#pragma unroll
            for (int ni = 0; ni < 4; ni++) {
                s0v += fmaxf(acc[mi][ni][0] + b0, 0.f) + fmaxf(acc[mi][ni][1] + b0, 0.f);
                s1v += fmaxf(acc[mi][ni][2] + b1, 0.f) + fmaxf(acc[mi][ni][3] + b1, 0.f);
            }
            s0v += __shfl_xor_sync(0xffffffffu, s0v, 1);
            s0v += __shfl_xor_sync(0xffffffffu, s0v, 2);
            s1v += __shfl_xor_sync(0xffffffffu, s1v, 1);
            s1v += __shfl_xor_sync(0xffffffffu, s1v, 2);
            if ((lane & 3) == 0) {
                atomicAdd(&g_sum[n * 256 + r0],     s0v);
                atomicAdd(&g_sum[n * 256 + r0 + 8], s1v);
            }
        }
        return;
    }

    // transpose epilogue: per-warp 32x32 patch in (reused) smem
    __syncthreads();
    float* patch = (float*)smem + wid * (32 * 33);
#pragma unroll
    for (int mi = 0; mi < 2; mi++)
#pragma unroll
        for (int ni = 0; ni < 4; ni++) {
            int r = mi * 16 + (lane >> 2);
            int p = ni * 8 + (lane & 3) * 2;
            patch[r * 33 + p]           = acc[mi][ni][0];
            patch[r * 33 + p + 1]       = acc[mi][ni][1];
            patch[(r + 8) * 33 + p]     = acc[mi][ni][2];
            patch[(r + 8) * 33 + p + 1] = acc[mi][ni][3];
        }
    __syncwarp();

    const int pxg = p0 + wn * 32 + lane;
    const int oc0 = ocb + wm * 32;

    __half ff[32];
    if (MODE == 3) {
        const __half* gp; int gst, gks;
        if (oc0 < 128)      { gp = g_b2f;  gst = 128; gks = 0;   }
        else if (oc0 < 384) { gp = g_thxf; gst = 256; gks = 128; }
        else                { gp = g_txuf; gst = 256; gks = 384; }
        const __half* gr = gp + ((size_t)n * HW + pxg) * gst + (oc0 - gks);
#pragma unroll
        for (int j = 0; j < 32; j++) {
            float v = patch[j * 33 + lane] + bias[oc0 + j];
            float sg = 1.f / (1.f + expf(-v));
            ff[j] = __float2half(sg * __half2float(gr[j]));
        }
    } else {
#pragma unroll
        for (int j = 0; j < 32; j++) {
            float v = patch[j * 33 + lane] + bias[oc0 + j];
            v = fmaxf(v, 0.f);
            if (MODE == 1) v *= g_w[n * 256 + oc0 + j];
            ff[j] = __float2half(v);
        }
    }
    size_t o = ((size_t)n * HW + pxg) * COUT + oc0;
#pragma unroll
    for (int q = 0; q < 4; q++)
        *(uint4*)(of + o + q * 8) = ((const uint4*)ff)[q];
}

// ----- wrappers -------------------------------------------------------------
__global__ __launch_bounds__(512) void g_stageA_k(const float* __restrict__ bias)
{
    gemm_body<0>(768, 256, g_x1f, 256, g_thxf, 256, g_txuf, 256, 256, 512,
                 g_wt1h, g_wt1l, bias, nullptr);
}
__global__ __launch_bounds__(512) void g_b1_k(const float* __restrict__ bias)
{
    gemm_body<1>(256, 256, g_x2f, 256, nullptr, 0, nullptr, 0, 256, 256,
                 g_wUh, g_wUl, bias, g_b1f);
}
__global__ __launch_bounds__(512) void g_b2_k(const float* __restrict__ bias)
{
    gemm_body<2>(256, 128, g_b1f, 256, nullptr, 0, nullptr, 0, 256, 256,
                 g_wVh, g_wVl, bias, g_b2f);
}
__global__ __launch_bounds__(512) void g_a1_k(const float* __restrict__ bias)
{
    gemm_body<2>(640, 128, g_b2f, 128, g_thxf, 256, g_txuf, 256, 128, 384,
                 g_wa1h, g_wa1l, bias, g_a1f);
}
__global__ __launch_bounds__(512) void g_a2_k(const float* __restrict__ bias)
{
    gemm_body<3>(128, 640, g_a1f, 128, nullptr, 0, nullptr, 0, 128, 128,
                 g_wa2h, g_wa2l, bias, g_aT_f);
}

// ---------------------------------------------------------------------------
// mma.sync conv3x3, fp16 2-pass, 4-stage pipeline
// ---------------------------------------------------------------------------
__global__ __launch_bounds__(512) void mma_conv3_k(
    const float* __restrict__ bot, float* __restrict__ out)
{
    extern __shared__ __align__(128) char smem[];
    const uint32_t sb = smem_to_u32(smem);

    const int tid  = threadIdx.x;
    const int lane = tid & 31;
    const int wid  = tid >> 5;
    const int wm   = wid & 3;
    const int wn   = wid >> 2;
    const int n    = blockIdx.z;
    const int ocb  = blockIdx.y * 128;
    const int p0   = blockIdx.x * 128;

    float acc[2][4][4];
#pragma unroll
    for (int mi = 0; mi < 2; mi++)
#pragma unroll
        for (int ni = 0; ni < 4; ni++)
#pragma unroll
            for (int r = 0; r < 4; r++) acc[mi][ni][r] = 0.f;

    auto stage = [&](int chunk) {
        const uint32_t base = sb + (chunk & 3) * ST3;
        const int tap = chunk / 20;
        const int dy = tap / 3 - 1, dx = tap % 3 - 1;
        const int c0 = (chunk - tap * 20) * 32;
        const int k0 = chunk * 32;
#pragma unroll
        for (int it = tid; it < 1024; it += 512) {
            int half = it >> 9, row = (it >> 2) & 127, seg = it & 3;
            const __half* w = half ? g_wfl : g_wfh;
            cp16(base + half * TILE_B + row * 80 + seg * 16,
                 w + (size_t)(ocb + row) * 5760 + k0 + seg * 8, 16);
        }
        if (tid < 512) {
            int row = (tid >> 2) & 127, seg = tid & 3;
            int p = p0 + row;
            int iy = (p >> 6) + dy, ix = (p & 63) + dx;
            bool ok = ((unsigned)iy < 64u) && ((unsigned)ix < 64u);
            const __half* src = ok
                ? g_aT_f + ((size_t)(n * HW + iy * 64 + ix)) * 640 + c0 + seg * 8
                : g_aT_f;
            cp16(base + 2 * TILE_B + row * 80 + seg * 16, src, ok ? 16u : 0u);
        }
    };

    const int NCHUNK = 180;
    stage(0); cp_commit();
    stage(1); cp_commit();

    for (int i = 0; i < NCHUNK; i++) {
        if (i + 2 < NCHUNK)      { stage(i + 2); cp_commit(); cp_wait<2>(); }
        else if (i + 1 < NCHUNK) cp_wait<1>();
        else                     cp_wait<0>();
        __syncthreads();

        const uint32_t base = sb + (i & 3) * ST3;
        const uint32_t aAh = base;
        const uint32_t aAl = base + TILE_B;
        const uint32_t aBh = base + 2 * TILE_B;

#pragma unroll
        for (int ks = 0; ks < 2; ks++) {
            const int kb = ks * 32;
            uint32_t ah[2][4], al[2][4];
#pragma unroll
            for (int mi = 0; mi < 2; mi++) {
                uint32_t ro = (uint32_t)(wm * 32 + mi * 16 + (lane & 15)) * 80
                            + (uint32_t)(lane >> 4) * 16 + kb;
                ldm_x4(ah[mi], aAh + ro);
                ldm_x4(al[mi], aAl + ro);
            }
#pragma unroll
            for (int ni = 0; ni < 4; ni++) {
                uint32_t ro = (uint32_t)(wn * 32 + ni * 8 + (lane >> 2)) * 80
                            + kb + (uint32_t)(lane & 3) * 4;
                uint32_t bh0 = *(const uint32_t*)(smem + (aBh + ro      - sb));
                uint32_t bh1 = *(const uint32_t*)(smem + (aBh + ro + 16 - sb));
#pragma unroll
                for (int mi = 0; mi < 2; mi++) {
                    mma_f16(acc[mi][ni], ah[mi], bh0, bh1);
                    mma_f16(acc[mi][ni], al[mi], bh0, bh1);
                }
            }
        }
    }

    const size_t nb = (size_t)n * 256 * HW;
#pragma unroll
    for (int mi = 0; mi < 2; mi++) {
        int r0 = ocb + wm * 32 + mi * 16 + (lane >> 2);
        float bv0 = bot[r0], bv1 = bot[r0 + 8];
#pragma unroll
        for (int ni = 0; ni < 4; ni++) {
            int px = p0 + wn * 32 + ni * 8 + (lane & 3) * 2;
            float2 v0, v1;
            v0.x = fmaxf(acc[mi][ni][0] + bv0, 0.f);
            v0.y = fmaxf(acc[mi][ni][1] + bv0, 0.f);
            v1.x = fmaxf(acc[mi][ni][2] + bv1, 0.f);
            v1.y = fmaxf(acc[mi][ni][3] + bv1, 0.f);
            *(float2*)(out + nb + (size_t)r0 * HW + px)       = v0;
            *(float2*)(out + nb + (size_t)(r0 + 8) * HW + px) = v1;
        }
    }
}

// ---------------------------------------------------------------------------
// Launch
// ---------------------------------------------------------------------------
extern "C" void kernel_launch(void* const* d_in, const int* in_sizes, int n_in,
                              void* d_out, int out_size)
{
    const float* sx1  = (const float*)d_in[0];
    const float* sx2  = (const float*)d_in[1];
    const float* t_hx = (const float*)d_in[2];
    const float* tx   = (const float*)d_in[3];
    const float* W_t1 = (const float*)d_in[4];
    const float* b_t1 = (const float*)d_in[5];
    const float* W_t2 = (const float*)d_in[6];
    const float* W_t3 = (const float*)d_in[7];
    const float* W_U  = (const float*)d_in[8];
    const float* b_U  = (const float*)d_in[9];
    const float* W_V  = (const float*)d_in[10];
    const float* b_V  = (const float*)d_in[11];
    const float* W_a1 = (const float*)d_in[12];
    const float* b_a1 = (const float*)d_in[13];
    const float* W_a2 = (const float*)d_in[14];
    const float* b_a2 = (const float*)d_in[15];
    const float* W_ot = (const float*)d_in[16];
    const float* b_ot = (const float*)d_in[17];
    float* out = (float*)d_out;

    cudaFuncSetAttribute(g_stageA_k,  cudaFuncAttributeMaxDynamicSharedMemorySize, GEMM_SMEM);
    cudaFuncSetAttribute(g_b1_k,      cudaFuncAttributeMaxDynamicSharedMemorySize, GEMM_SMEM);
    cudaFuncSetAttribute(g_b2_k,      cudaFuncAttributeMaxDynamicSharedMemorySize, GEMM_SMEM);
    cudaFuncSetAttribute(g_a1_k,      cudaFuncAttributeMaxDynamicSharedMemorySize, GEMM_SMEM);
    cudaFuncSetAttribute(g_a2_k,      cudaFuncAttributeMaxDynamicSharedMemorySize, GEMM_SMEM);
    cudaFuncSetAttribute(mma_conv3_k, cudaFuncAttributeMaxDynamicSharedMemorySize, GEMM_SMEM);

    // weight conversions (+ g_sum zero)
    split_all_k<<<dim3(96, 6), 256>>>(W_t1, W_U, W_V, W_a1, W_a2);
    cvt_w_k<<<256, 256>>>(W_ot);
    // activation conversions
    ups_cvt_k<<<dim3(64, 4, 8), 256>>>(tx);
    cvt3_k<<<dim3(64, 12, 8), 256>>>(sx1, t_hx, sx2);
    // stage A GEMM + GAP
    g_stageA_k<<<dim3(32, 2, 8), 512, GEMM_SMEM>>>(b_t1);
    // head MLP + normalize
    head_k<<<8, 256>>>(W_t2, W_t3, out + OUT_A_ELEMS);
    // b1 = relu(W_U@sx2 + b)*w
    g_b1_k<<<dim3(32, 2, 8), 512, GEMM_SMEM>>>(b_U);
    // b2 = relu(W_V@b1 + b)
    g_b2_k<<<dim3(32, 1, 8), 512, GEMM_SMEM>>>(b_V);
    // a1 = relu(W_a1@[b2;thx;txu] + b)
    g_a1_k<<<dim3(32, 1, 8), 512, GEMM_SMEM>>>(b_a1);
    // apod = sigmoid(W_a2@a1 + b) * bcat -> g_aT_f
    g_a2_k<<<dim3(32, 5, 8), 512, GEMM_SMEM>>>(b_a2);
    // conv3x3 + bias + relu -> main output
    mma_conv3_k<<<dim3(32, 2, 8), 512, GEMM_SMEM>>>(b_ot, out);
}

// round 9
// speedup vs baseline: 4.3995x; 1.4910x over previous
#include <cuda_runtime.h>
#include <cuda_fp16.h>
#include <math.h>
#include <stdint.h>

// ---------------------------------------------------------------------------
// Problem constants
// ---------------------------------------------------------------------------
#define HW     4096          // 64*64
#define NB     8
#define OUT_A_ELEMS (8 * 256 * 4096)   // "a" output
// output layout: a [8,256,64,64] followed by w [8,256]

// ---------------------------------------------------------------------------
// Scratch (static device globals -- no allocation allowed)
// ---------------------------------------------------------------------------
__device__ float g_sum [8 * 256];          // stage-A GAP accumulator
__device__ float g_w   [8 * 256];          // normalized channel weights

// fp16 channel-last activation planes [n*4096][C]
__device__ __align__(16) __half g_x1f [8ULL * 4096 * 256];
__device__ __align__(16) __half g_thxf[8ULL * 4096 * 256];
__device__ __align__(16) __half g_txuf[8ULL * 4096 * 256];
__device__ __align__(16) __half g_x2f [8ULL * 4096 * 256];
__device__ __align__(16) __half g_b1f [8ULL * 4096 * 256];
__device__ __align__(16) __half g_b2f [8ULL * 4096 * 128];
__device__ __align__(16) __half g_a1f [8ULL * 4096 * 128];
__device__ __align__(16) __half g_aT_f[8ULL * 4096 * 640];

// fp16 weights (row-major [O][K])
__device__ __align__(16) __half g_wt1[256 * 768];
__device__ __align__(16) __half g_wU [256 * 256];
__device__ __align__(16) __half g_wV [128 * 256];
__device__ __align__(16) __half g_wa1[128 * 640];
__device__ __align__(16) __half g_wa2[640 * 128];
// conv3x3 weights, tap-major [oc][tap*640+c]
__device__ __align__(16) __half g_wf[256 * 5760];

// ---------------------------------------------------------------------------
// helpers
// ---------------------------------------------------------------------------
__device__ __forceinline__ uint32_t smem_to_u32(const void* p) {
    uint32_t a;
    asm("{ .reg .u64 t; cvta.to.shared.u64 t, %1; cvt.u32.u64 %0, t; }"
        : "=r"(a) : "l"(p));
    return a;
}

__device__ __forceinline__ void cp16(uint32_t dst, const void* src, uint32_t bytes) {
    asm volatile("cp.async.cg.shared.global [%0], [%1], 16, %2;"
                 :: "r"(dst), "l"(src), "r"(bytes) : "memory");
}
__device__ __forceinline__ void cp_commit() {
    asm volatile("cp.async.commit_group;" ::: "memory");
}
template<int N>
__device__ __forceinline__ void cp_wait() {
    asm volatile("cp.async.wait_group %0;" :: "n"(N) : "memory");
}

__device__ __forceinline__ void ldm_x4(uint32_t (&r)[4], uint32_t addr) {
    asm volatile("ldmatrix.sync.aligned.m8n8.x4.shared.b16 {%0,%1,%2,%3}, [%4];"
                 : "=r"(r[0]), "=r"(r[1]), "=r"(r[2]), "=r"(r[3]) : "r"(addr));
}

__device__ __forceinline__ void mma_f16(float (&c)[4], const uint32_t (&a)[4],
                                        uint32_t b0, uint32_t b1) {
    asm volatile(
        "mma.sync.aligned.m16n8k16.row.col.f32.f16.f16.f32 "
        "{%0,%1,%2,%3}, {%4,%5,%6,%7}, {%8,%9}, {%0,%1,%2,%3};"
        : "+f"(c[0]), "+f"(c[1]), "+f"(c[2]), "+f"(c[3])
        : "r"(a[0]), "r"(a[1]), "r"(a[2]), "r"(a[3]), "r"(b0), "r"(b1));
}

// ---------------------------------------------------------------------------
// fused upsample x2 (align_corners) + transpose + fp16: tx -> g_txuf
// ---------------------------------------------------------------------------
__global__ __launch_bounds__(256) void ups_cvt_k(const float* __restrict__ tx)
{
    __shared__ float s0[64][32], s1[64][32];
    const int y  = blockIdx.x;
    const int c0 = blockIdx.y * 64;
    const int n  = blockIdx.z;

    const float step = 31.0f / 63.0f;
    const float fy = y * step;
    const int y0 = (int)fy;
    const int y1 = min(y0 + 1, 31);
    const float wy = fy - y0;

    for (int it = threadIdx.x; it < 4096; it += 256) {
        int c = it >> 6, r = (it >> 5) & 1, x = it & 31;
        const float* sp = tx + (((size_t)(n * 256 + c0 + c) * 32) + (r ? y1 : y0)) * 32;
        if (r) s1[c][x] = sp[x]; else s0[c][x] = sp[x];
    }
    __syncthreads();

    for (int it = threadIdx.x; it < 4096; it += 256) {
        int x = it >> 6, c = it & 63;
        float fx = x * step;
        int x0 = (int)fx;  float wx = fx - x0;
        int x1 = min(x0 + 1, 31);
        float top = s0[c][x0] * (1.f - wx) + s0[c][x1] * wx;
        float bot = s1[c][x0] * (1.f - wx) + s1[c][x1] * wx;
        g_txuf[((size_t)n * HW + y * 64 + x) * 256 + c0 + c] =
            __float2half(top * (1.f - wy) + bot * wy);
    }
}

// ---------------------------------------------------------------------------
// transpose + fp16: [n][256][4096] fp32 -> [n*4096][256] fp16 (3 sources)
//   half2-vectorized stores
// ---------------------------------------------------------------------------
__global__ __launch_bounds__(256) void cvt3_k(
    const float* __restrict__ sx1, const float* __restrict__ t_hx,
    const float* __restrict__ sx2)
{
    __shared__ float t[64][65];
    const int src = blockIdx.y >> 2;
    const int c0  = (blockIdx.y & 3) * 64;
    const int n   = blockIdx.z, p0 = blockIdx.x * 64;
    const float* sp = (src == 0 ? sx1 : src == 1 ? t_hx : sx2)
                    + ((size_t)n * 256 + c0) * HW + p0;
    __half* dst = (src == 0 ? g_x1f : src == 1 ? g_thxf : g_x2f);

    for (int it = threadIdx.x; it < 4096; it += 256) {
        int c = it >> 6, px = it & 63;
        t[c][px] = sp[(size_t)c * HW + px];
    }
    __syncthreads();
    for (int it = threadIdx.x; it < 2048; it += 256) {
        int px = it >> 5, c2 = (it & 31) * 2;
        __half2 v = __floats2half2_rn(t[c2][px], t[c2 + 1][px]);
        *(__half2*)(dst + ((size_t)n * HW + p0 + px) * 256 + c0 + c2) = v;
    }
}

// ---------------------------------------------------------------------------
// weight conversions (single fp16) + g_sum zeroing
// ---------------------------------------------------------------------------
__global__ __launch_bounds__(256) void split_all_k(
    const float* __restrict__ a, const float* __restrict__ b,
    const float* __restrict__ c, const float* __restrict__ d,
    const float* __restrict__ e)
{
    if (blockIdx.y == 5) {
        int i = blockIdx.x * 256 + threadIdx.x;
        if (i < 8 * 256) g_sum[i] = 0.f;
        return;
    }
    const float* src; __half* h; int nel;
    switch (blockIdx.y) {
        case 0:  src = a; h = g_wt1; nel = 256 * 768; break;
        case 1:  src = b; h = g_wU;  nel = 256 * 256; break;
        case 2:  src = c; h = g_wV;  nel = 128 * 256; break;
        case 3:  src = d; h = g_wa1; nel = 128 * 640; break;
        default: src = e; h = g_wa2; nel = 640 * 128; break;
    }
    for (int i = blockIdx.x * 256 + threadIdx.x; i < nel; i += gridDim.x * 256)
        h[i] = __float2half(src[i]);
}

// conv weights: [oc][c][ky][kx] fp32 -> tap-major [oc][tap*640+c] fp16
__global__ __launch_bounds__(256) void cvt_w_k(const float* __restrict__ W)
{
    const int oc = blockIdx.x;
    for (int t = threadIdx.x; t < 5760; t += 256) {
        int c = t / 9, tap = t - c * 9;
        g_wf[(size_t)oc * 5760 + (size_t)tap * 640 + c] =
            __float2half(W[(size_t)oc * 5760 + t]);
    }
}

// ---------------------------------------------------------------------------
// Head (squeeze-excite MLP + L2 normalize); writes "w" output tail
// ---------------------------------------------------------------------------
__global__ __launch_bounds__(256) void head_k(
    const float* __restrict__ Wt2, const float* __restrict__ Wt3,
    float* __restrict__ outw)
{
    const int n = blockIdx.x, tid = threadIdx.x;
    __shared__ float w1[256], w2[64], red[256];

    w1[tid] = g_sum[n * 256 + tid] * (1.f / 4096.f);
    __syncthreads();

    if (tid < 64) {
        float s = 0.f;
#pragma unroll 8
        for (int k = 0; k < 256; k++) s = fmaf(Wt2[tid * 256 + k], w1[k], s);
        w2[tid] = fmaxf(s, 0.f);
    }
    __syncthreads();

    float s = 0.f;
#pragma unroll
    for (int e = 0; e < 64; e++) s = fmaf(Wt3[tid * 64 + e], w2[e], s);

    red[tid] = s * s;
    __syncthreads();
    for (int off = 128; off > 0; off >>= 1) {
        if (tid < off) red[tid] += red[tid + off];
        __syncthreads();
    }
    float nv = sqrtf(red[0]);
    float wv = s / fmaxf(nv, 1e-12f);
    g_w[n * 256 + tid] = wv;
    outw[n * 256 + tid] = wv;
}

// ---------------------------------------------------------------------------
// Unified mma.sync 1x1-conv GEMM, single-pass fp16.
//   CTA 128oc x 128px, 16 warps 32x32, K chunks of 32, 4-stage cp.async.
// MODE 0: relu(acc+bias), GAP-sum -> atomicAdd g_sum
// MODE 1: relu(acc+bias) * g_w  -> fp16 channel-last
// MODE 2: relu(acc+bias)        -> fp16 channel-last
// MODE 3: sigmoid(acc+bias) * bcat -> fp16 channel-last (bcat = b2|thx|txu)
// ---------------------------------------------------------------------------
#define TILE_B   10240                 // one 128x40 fp16 tile
#define ST2      (2 * TILE_B)          // A, B
#define NST      4
#define GEMM_SMEM (NST * ST2)          // 81920 bytes

template<int MODE>
__device__ __forceinline__ void gemm_body(
    int K, int COUT,
    const __half* s0, int st0,
    const __half* s1, int st1,
    const __half* s2, int st2,
    int kb0, int kb1,
    const __half* wp,
    const float* __restrict__ bias,
    __half* __restrict__ of)
{
    extern __shared__ __align__(128) char smem[];
    const uint32_t sb = smem_to_u32(smem);

    const int tid  = threadIdx.x;
    const int lane = tid & 31;
    const int wid  = tid >> 5;
    const int wm   = wid & 3;
    const int wn   = wid >> 2;
    const int n    = blockIdx.z;
    const int ocb  = blockIdx.y * 128;
    const int p0   = blockIdx.x * 128;

    float acc[2][4][4];
#pragma unroll
    for (int mi = 0; mi < 2; mi++)
#pragma unroll
        for (int ni = 0; ni < 4; ni++)
#pragma unroll
            for (int r = 0; r < 4; r++) acc[mi][ni][r] = 0.f;

    auto stage = [&](int chunk) {
        const uint32_t base = sb + (chunk & 3) * ST2;
        const int k0 = chunk * 32;
        const __half* sh; int stride, ks;
        if (k0 < kb0)      { sh = s0; stride = st0; ks = 0;   }
        else if (k0 < kb1) { sh = s1; stride = st1; ks = kb0; }
        else               { sh = s2; stride = st2; ks = kb1; }
        const int c0 = k0 - ks;
        if (tid < 512) {
            int row = (tid >> 2) & 127, seg = tid & 3;
            cp16(base + row * 80 + seg * 16,
                 wp + (size_t)(ocb + row) * K + k0 + seg * 8, 16);
            cp16(base + TILE_B + row * 80 + seg * 16,
                 sh + ((size_t)n * HW + p0 + row) * stride + c0 + seg * 8, 16);
        }
    };

    const int NC = K >> 5;
    stage(0); cp_commit();
    stage(1); cp_commit();

    for (int i = 0; i < NC; i++) {
        if (i + 2 < NC)      { stage(i + 2); cp_commit(); cp_wait<2>(); }
        else if (i + 1 < NC) cp_wait<1>();
        else                 cp_wait<0>();
        __syncthreads();

        const uint32_t base = sb + (i & 3) * ST2;
        const uint32_t aA = base;
        const uint32_t aB = base + TILE_B;

#pragma unroll
        for (int ks = 0; ks < 2; ks++) {
            const int kb = ks * 32;
            uint32_t ah[2][4];
#pragma unroll
            for (int mi = 0; mi < 2; mi++) {
                uint32_t ro = (uint32_t)(wm * 32 + mi * 16 + (lane & 15)) * 80
                            + (uint32_t)(lane >> 4) * 16 + kb;
                ldm_x4(ah[mi], aA + ro);
            }
#pragma unroll
            for (int ni = 0; ni < 4; ni++) {
                uint32_t ro = (uint32_t)(wn * 32 + ni * 8 + (lane >> 2)) * 80
                            + kb + (uint32_t)(lane & 3) * 4;
                uint32_t b0 = *(const uint32_t*)(smem + (aB + ro      - sb));
                uint32_t b1 = *(const uint32_t*)(smem + (aB + ro + 16 - sb));
#pragma unroll
                for (int mi = 0; mi < 2; mi++)
                    mma_f16(acc[mi][ni], ah[mi], b0, b1);
            }
        }
    }

    if (MODE == 0) {
#pragma unroll
        for (int mi = 0; mi < 2; mi++) {
            int r0 = ocb + wm * 32 + mi * 16 + (lane >> 2);
            float b0 = bias[r0], b1 = bias[r0 + 8];
            float s0v = 0.f, s1v = 0.f;
#pragma unroll
            for (int ni = 0; ni < 4; ni++) {
                s0v += fmaxf(acc[mi][ni][0] + b0, 0.f) + fmaxf(acc[mi][ni][1] + b0, 0.f);
                s1v += fmaxf(acc[mi][ni][2] + b1, 0.f) + fmaxf(acc[mi][ni][3] + b1, 0.f);
            }
            s0v += __shfl_xor_sync(0xffffffffu, s0v, 1);
            s0v += __shfl_xor_sync(0xffffffffu, s0v, 2);
            s1v += __shfl_xor_sync(0xffffffffu, s1v, 1);
            s1v += __shfl_xor_sync(0xffffffffu, s1v, 2);
            if ((lane & 3) == 0) {
                atomicAdd(&g_sum[n * 256 + r0],     s0v);
                atomicAdd(&g_sum[n * 256 + r0 + 8], s1v);
            }
        }
        return;
    }

    // transpose epilogue: per-warp 32x32 patch in (reused) smem
    __syncthreads();
    float* patch = (float*)smem + wid * (32 * 33);
#pragma unroll
    for (int mi = 0; mi < 2; mi++)
#pragma unroll
        for (int ni = 0; ni < 4; ni++) {
            int r = mi * 16 + (lane >> 2);
            int p = ni * 8 + (lane & 3) * 2;
            patch[r * 33 + p]           = acc[mi][ni][0];
            patch[r * 33 + p + 1]       = acc[mi][ni][1];
            patch[(r + 8) * 33 + p]     = acc[mi][ni][2];
            patch[(r + 8) * 33 + p + 1] = acc[mi][ni][3];
        }
    __syncwarp();

    const int pxg = p0 + wn * 32 + lane;
    const int oc0 = ocb + wm * 32;

    __half ff[32];
    if (MODE == 3) {
        const __half* gp; int gst, gks;
        if (oc0 < 128)      { gp = g_b2f;  gst = 128; gks = 0;   }
        else if (oc0 < 384) { gp = g_thxf; gst = 256; gks = 128; }
        else                { gp = g_txuf; gst = 256; gks = 384; }
        const __half* gr = gp + ((size_t)n * HW + pxg) * gst + (oc0 - gks);
#pragma unroll
        for (int j = 0; j < 32; j++) {
            float v = patch[j * 33 + lane] + bias[oc0 + j];
            float sg = 1.f / (1.f + expf(-v));
            ff[j] = __float2half(sg * __half2float(gr[j]));
        }
    } else {
#pragma unroll
        for (int j = 0; j < 32; j++) {
            float v = patch[j * 33 + lane] + bias[oc0 + j];
            v = fmaxf(v, 0.f);
            if (MODE == 1) v *= g_w[n * 256 + oc0 + j];
            ff[j] = __float2half(v);
        }
    }
    size_t o = ((size_t)n * HW + pxg) * COUT + oc0;
#pragma unroll
    for (int q = 0; q < 4; q++)
        *(uint4*)(of + o + q * 8) = ((const uint4*)ff)[q];
}

// ----- wrappers -------------------------------------------------------------
__global__ __launch_bounds__(512) void g_stageA_k(const float* __restrict__ bias)
{
    gemm_body<0>(768, 256, g_x1f, 256, g_thxf, 256, g_txuf, 256, 256, 512,
                 g_wt1, bias, nullptr);
}
__global__ __launch_bounds__(512) void g_b1_k(const float* __restrict__ bias)
{
    gemm_body<1>(256, 256, g_x2f, 256, nullptr, 0, nullptr, 0, 256, 256,
                 g_wU, bias, g_b1f);
}
__global__ __launch_bounds__(512) void g_b2_k(const float* __restrict__ bias)
{
    gemm_body<2>(256, 128, g_b1f, 256, nullptr, 0, nullptr, 0, 256, 256,
                 g_wV, bias, g_b2f);
}
__global__ __launch_bounds__(512) void g_a1_k(const float* __restrict__ bias)
{
    gemm_body<2>(640, 128, g_b2f, 128, g_thxf, 256, g_txuf, 256, 128, 384,
                 g_wa1, bias, g_a1f);
}
__global__ __launch_bounds__(512) void g_a2_k(const float* __restrict__ bias)
{
    gemm_body<3>(128, 640, g_a1f, 128, nullptr, 0, nullptr, 0, 128, 128,
                 g_wa2, bias, g_aT_f);
}

// ---------------------------------------------------------------------------
// mma.sync conv3x3, single-pass fp16, 4-stage pipeline
// ---------------------------------------------------------------------------
__global__ __launch_bounds__(512) void mma_conv3_k(
    const float* __restrict__ bot, float* __restrict__ out)
{
    extern __shared__ __align__(128) char smem[];
    const uint32_t sb = smem_to_u32(smem);

    const int tid  = threadIdx.x;
    const int lane = tid & 31;
    const int wid  = tid >> 5;
    const int wm   = wid & 3;
    const int wn   = wid >> 2;
    const int n    = blockIdx.z;
    const int ocb  = blockIdx.y * 128;
    const int p0   = blockIdx.x * 128;

    float acc[2][4][4];
#pragma unroll
    for (int mi = 0; mi < 2; mi++)
#pragma unroll
        for (int ni = 0; ni < 4; ni++)
#pragma unroll
            for (int r = 0; r < 4; r++) acc[mi][ni][r] = 0.f;

    auto stage = [&](int chunk) {
        const uint32_t base = sb + (chunk & 3) * ST2;
        const int tap = chunk / 20;
        const int dy = tap / 3 - 1, dx = tap % 3 - 1;
        const int c0 = (chunk - tap * 20) * 32;
        const int k0 = chunk * 32;
        if (tid < 512) {
            int row = (tid >> 2) & 127, seg = tid & 3;
            cp16(base + row * 80 + seg * 16,
                 g_wf + (size_t)(ocb + row) * 5760 + k0 + seg * 8, 16);
            int p = p0 + row;
            int iy = (p >> 6) + dy, ix = (p & 63) + dx;
            bool ok = ((unsigned)iy < 64u) && ((unsigned)ix < 64u);
            const __half* src = ok
                ? g_aT_f + ((size_t)(n * HW + iy * 64 + ix)) * 640 + c0 + seg * 8
                : g_aT_f;
            cp16(base + TILE_B + row * 80 + seg * 16, src, ok ? 16u : 0u);
        }
    };

    const int NCHUNK = 180;
    stage(0); cp_commit();
    stage(1); cp_commit();

    for (int i = 0; i < NCHUNK; i++) {
        if (i + 2 < NCHUNK)      { stage(i + 2); cp_commit(); cp_wait<2>(); }
        else if (i + 1 < NCHUNK) cp_wait<1>();
        else                     cp_wait<0>();
        __syncthreads();

        const uint32_t base = sb + (i & 3) * ST2;
        const uint32_t aA = base;
        const uint32_t aB = base + TILE_B;

#pragma unroll
        for (int ks = 0; ks < 2; ks++) {
            const int kb = ks * 32;
            uint32_t ah[2][4];
#pragma unroll
            for (int mi = 0; mi < 2; mi++) {
                uint32_t ro = (uint32_t)(wm * 32 + mi * 16 + (lane & 15)) * 80
                            + (uint32_t)(lane >> 4) * 16 + kb;
                ldm_x4(ah[mi], aA + ro);
            }
#pragma unroll
            for (int ni = 0; ni < 4; ni++) {
                uint32_t ro = (uint32_t)(wn * 32 + ni * 8 + (lane >> 2)) * 80
                            + kb + (uint32_t)(lane & 3) * 4;
                uint32_t b0 = *(const uint32_t*)(smem + (aB + ro      - sb));
                uint32_t b1 = *(const uint32_t*)(smem + (aB + ro + 16 - sb));
#pragma unroll
                for (int mi = 0; mi < 2; mi++)
                    mma_f16(acc[mi][ni], ah[mi], b0, b1);
            }
        }
    }

    const size_t nb = (size_t)n * 256 * HW;
#pragma unroll
    for (int mi = 0; mi < 2; mi++) {
        int r0 = ocb + wm * 32 + mi * 16 + (lane >> 2);
        float bv0 = bot[r0], bv1 = bot[r0 + 8];
#pragma unroll
        for (int ni = 0; ni < 4; ni++) {
            int px = p0 + wn * 32 + ni * 8 + (lane & 3) * 2;
            float2 v0, v1;
            v0.x = fmaxf(acc[mi][ni][0] + bv0, 0.f);
            v0.y = fmaxf(acc[mi][ni][1] + bv0, 0.f);
            v1.x = fmaxf(acc[mi][ni][2] + bv1, 0.f);
            v1.y = fmaxf(acc[mi][ni][3] + bv1, 0.f);
            *(float2*)(out + nb + (size_t)r0 * HW + px)       = v0;
            *(float2*)(out + nb + (size_t)(r0 + 8) * HW + px) = v1;
        }
    }
}

// ---------------------------------------------------------------------------
// Launch
// ---------------------------------------------------------------------------
extern "C" void kernel_launch(void* const* d_in, const int* in_sizes, int n_in,
                              void* d_out, int out_size)
{
    const float* sx1  = (const float*)d_in[0];
    const float* sx2  = (const float*)d_in[1];
    const float* t_hx = (const float*)d_in[2];
    const float* tx   = (const float*)d_in[3];
    const float* W_t1 = (const float*)d_in[4];
    const float* b_t1 = (const float*)d_in[5];
    const float* W_t2 = (const float*)d_in[6];
    const float* W_t3 = (const float*)d_in[7];
    const float* W_U  = (const float*)d_in[8];
    const float* b_U  = (const float*)d_in[9];
    const float* W_V  = (const float*)d_in[10];
    const float* b_V  = (const float*)d_in[11];
    const float* W_a1 = (const float*)d_in[12];
    const float* b_a1 = (const float*)d_in[13];
    const float* W_a2 = (const float*)d_in[14];
    const float* b_a2 = (const float*)d_in[15];
    const float* W_ot = (const float*)d_in[16];
    const float* b_ot = (const float*)d_in[17];
    float* out = (float*)d_out;

    cudaFuncSetAttribute(g_stageA_k,  cudaFuncAttributeMaxDynamicSharedMemorySize, GEMM_SMEM);
    cudaFuncSetAttribute(g_b1_k,      cudaFuncAttributeMaxDynamicSharedMemorySize, GEMM_SMEM);
    cudaFuncSetAttribute(g_b2_k,      cudaFuncAttributeMaxDynamicSharedMemorySize, GEMM_SMEM);
    cudaFuncSetAttribute(g_a1_k,      cudaFuncAttributeMaxDynamicSharedMemorySize, GEMM_SMEM);
    cudaFuncSetAttribute(g_a2_k,      cudaFuncAttributeMaxDynamicSharedMemorySize, GEMM_SMEM);
    cudaFuncSetAttribute(mma_conv3_k, cudaFuncAttributeMaxDynamicSharedMemorySize, GEMM_SMEM);

    // weight conversions (+ g_sum zero)
    split_all_k<<<dim3(96, 6), 256>>>(W_t1, W_U, W_V, W_a1, W_a2);
    cvt_w_k<<<256, 256>>>(W_ot);
    // activation conversions
    ups_cvt_k<<<dim3(64, 4, 8), 256>>>(tx);
    cvt3_k<<<dim3(64, 12, 8), 256>>>(sx1, t_hx, sx2);
    // stage A GEMM + GAP
    g_stageA_k<<<dim3(32, 2, 8), 512, GEMM_SMEM>>>(b_t1);
    // head MLP + normalize
    head_k<<<8, 256>>>(W_t2, W_t3, out + OUT_A_ELEMS);
    // b1 = relu(W_U@sx2 + b)*w
    g_b1_k<<<dim3(32, 2, 8), 512, GEMM_SMEM>>>(b_U);
    // b2 = relu(W_V@b1 + b)
    g_b2_k<<<dim3(32, 1, 8), 512, GEMM_SMEM>>>(b_V);
    // a1 = relu(W_a1@[b2;thx;txu] + b)
    g_a1_k<<<dim3(32, 1, 8), 512, GEMM_SMEM>>>(b_a1);
    // apod = sigmoid(W_a2@a1 + b) * bcat -> g_aT_f
    g_a2_k<<<dim3(32, 5, 8), 512, GEMM_SMEM>>>(b_a2);
    // conv3x3 + bias + relu -> main output
    mma_conv3_k<<<dim3(32, 2, 8), 512, GEMM_SMEM>>>(b_ot, out);
}

// round 10
// speedup vs baseline: 4.5493x; 1.0340x over previous
#include <cuda_runtime.h>
#include <cuda_fp16.h>
#include <math.h>
#include <stdint.h>

// ---------------------------------------------------------------------------
// Problem constants
// ---------------------------------------------------------------------------
#define HW     4096          // 64*64
#define NB     8
#define OUT_A_ELEMS (8 * 256 * 4096)   // "a" output
// output layout: a [8,256,64,64] followed by w [8,256]

// ---------------------------------------------------------------------------
// Scratch (static device globals -- no allocation allowed)
// ---------------------------------------------------------------------------
__device__ float g_sum [8 * 256];          // stage-A GAP accumulator
__device__ float g_w   [8 * 256];          // normalized channel weights

// fp16 channel-last activation planes [n*4096][C]
__device__ __align__(16) __half g_x1f [8ULL * 4096 * 256];
__device__ __align__(16) __half g_thxf[8ULL * 4096 * 256];
__device__ __align__(16) __half g_txuf[8ULL * 4096 * 256];
__device__ __align__(16) __half g_x2f [8ULL * 4096 * 256];
__device__ __align__(16) __half g_b1f [8ULL * 4096 * 256];
__device__ __align__(16) __half g_b2f [8ULL * 4096 * 128];
__device__ __align__(16) __half g_a1f [8ULL * 4096 * 128];
__device__ __align__(16) __half g_aT_f[8ULL * 4096 * 640];

// fp16 weights (row-major [O][K])
__device__ __align__(16) __half g_wt1[256 * 768];
__device__ __align__(16) __half g_wU [256 * 256];
__device__ __align__(16) __half g_wV [128 * 256];
__device__ __align__(16) __half g_wa1[128 * 640];
__device__ __align__(16) __half g_wa2[640 * 128];
// conv3x3 weights, tap-major [oc][tap*640+c]
__device__ __align__(16) __half g_wf[256 * 5760];

// ---------------------------------------------------------------------------
// helpers
// ---------------------------------------------------------------------------
__device__ __forceinline__ uint32_t smem_to_u32(const void* p) {
    uint32_t a;
    asm("{ .reg .u64 t; cvta.to.shared.u64 t, %1; cvt.u32.u64 %0, t; }"
        : "=r"(a) : "l"(p));
    return a;
}

__device__ __forceinline__ void cp16(uint32_t dst, const void* src, uint32_t bytes) {
    asm volatile("cp.async.cg.shared.global [%0], [%1], 16, %2;"
                 :: "r"(dst), "l"(src), "r"(bytes) : "memory");
}
__device__ __forceinline__ void cp_commit() {
    asm volatile("cp.async.commit_group;" ::: "memory");
}
template<int N>
__device__ __forceinline__ void cp_wait() {
    asm volatile("cp.async.wait_group %0;" :: "n"(N) : "memory");
}

__device__ __forceinline__ void ldm_x4(uint32_t (&r)[4], uint32_t addr) {
    asm volatile("ldmatrix.sync.aligned.m8n8.x4.shared.b16 {%0,%1,%2,%3}, [%4];"
                 : "=r"(r[0]), "=r"(r[1]), "=r"(r[2]), "=r"(r[3]) : "r"(addr));
}

__device__ __forceinline__ void mma_f16(float (&c)[4], const uint32_t (&a)[4],
                                        uint32_t b0, uint32_t b1) {
    asm volatile(
        "mma.sync.aligned.m16n8k16.row.col.f32.f16.f16.f32 "
        "{%0,%1,%2,%3}, {%4,%5,%6,%7}, {%8,%9}, {%0,%1,%2,%3};"
        : "+f"(c[0]), "+f"(c[1]), "+f"(c[2]), "+f"(c[3])
        : "r"(a[0]), "r"(a[1]), "r"(a[2]), "r"(a[3]), "r"(b0), "r"(b1));
}

// ---------------------------------------------------------------------------
// fused upsample x2 (align_corners) + transpose + fp16: tx -> g_txuf
// ---------------------------------------------------------------------------
__global__ __launch_bounds__(256) void ups_cvt_k(const float* __restrict__ tx)
{
    __shared__ float s0[64][32], s1[64][32];
    const int y  = blockIdx.x;
    const int c0 = blockIdx.y * 64;
    const int n  = blockIdx.z;

    const float step = 31.0f / 63.0f;
    const float fy = y * step;
    const int y0 = (int)fy;
    const int y1 = min(y0 + 1, 31);
    const float wy = fy - y0;

    for (int it = threadIdx.x; it < 4096; it += 256) {
        int c = it >> 6, r = (it >> 5) & 1, x = it & 31;
        const float* sp = tx + (((size_t)(n * 256 + c0 + c) * 32) + (r ? y1 : y0)) * 32;
        if (r) s1[c][x] = sp[x]; else s0[c][x] = sp[x];
    }
    __syncthreads();

    for (int it = threadIdx.x; it < 4096; it += 256) {
        int x = it >> 6, c = it & 63;
        float fx = x * step;
        int x0 = (int)fx;  float wx = fx - x0;
        int x1 = min(x0 + 1, 31);
        float top = s0[c][x0] * (1.f - wx) + s0[c][x1] * wx;
        float bot = s1[c][x0] * (1.f - wx) + s1[c][x1] * wx;
        g_txuf[((size_t)n * HW + y * 64 + x) * 256 + c0 + c] =
            __float2half(top * (1.f - wy) + bot * wy);
    }
}

// ---------------------------------------------------------------------------
// transpose + fp16: [n][256][4096] fp32 -> [n*4096][256] fp16 (3 sources)
//   uint4-vectorized stores (8 channels per thread)
// ---------------------------------------------------------------------------
__global__ __launch_bounds__(256) void cvt3_k(
    const float* __restrict__ sx1, const float* __restrict__ t_hx,
    const float* __restrict__ sx2)
{
    __shared__ float t[64][65];
    const int src = blockIdx.y >> 2;
    const int c0  = (blockIdx.y & 3) * 64;
    const int n   = blockIdx.z, p0 = blockIdx.x * 64;
    const float* sp = (src == 0 ? sx1 : src == 1 ? t_hx : sx2)
                    + ((size_t)n * 256 + c0) * HW + p0;
    __half* dst = (src == 0 ? g_x1f : src == 1 ? g_thxf : g_x2f);

    for (int it = threadIdx.x; it < 4096; it += 256) {
        int c = it >> 6, px = it & 63;
        t[c][px] = sp[(size_t)c * HW + px];
    }
    __syncthreads();
    for (int it = threadIdx.x; it < 512; it += 256) {
        int px = it >> 3, cg = (it & 7) * 8;
        __half hh[8];
#pragma unroll
        for (int j = 0; j < 8; j++) hh[j] = __float2half(t[cg + j][px]);
        *(uint4*)(dst + ((size_t)n * HW + p0 + px) * 256 + c0 + cg) = *(uint4*)hh;
    }
}

// ---------------------------------------------------------------------------
// weight conversions (single fp16) + g_sum zeroing
// ---------------------------------------------------------------------------
__global__ __launch_bounds__(256) void split_all_k(
    const float* __restrict__ a, const float* __restrict__ b,
    const float* __restrict__ c, const float* __restrict__ d,
    const float* __restrict__ e)
{
    if (blockIdx.y == 5) {
        int i = blockIdx.x * 256 + threadIdx.x;
        if (i < 8 * 256) g_sum[i] = 0.f;
        return;
    }
    const float* src; __half* h; int nel;
    switch (blockIdx.y) {
        case 0:  src = a; h = g_wt1; nel = 256 * 768; break;
        case 1:  src = b; h = g_wU;  nel = 256 * 256; break;
        case 2:  src = c; h = g_wV;  nel = 128 * 256; break;
        case 3:  src = d; h = g_wa1; nel = 128 * 640; break;
        default: src = e; h = g_wa2; nel = 640 * 128; break;
    }
    for (int i = blockIdx.x * 256 + threadIdx.x; i < nel; i += gridDim.x * 256)
        h[i] = __float2half(src[i]);
}

// conv weights: [oc][c][ky][kx] fp32 -> tap-major [oc][tap*640+c] fp16
__global__ __launch_bounds__(256) void cvt_w_k(const float* __restrict__ W)
{
    const int oc = blockIdx.x;
    for (int t = threadIdx.x; t < 5760; t += 256) {
        int c = t / 9, tap = t - c * 9;
        g_wf[(size_t)oc * 5760 + (size_t)tap * 640 + c] =
            __float2half(W[(size_t)oc * 5760 + t]);
    }
}

// ---------------------------------------------------------------------------
// Head (squeeze-excite MLP + L2 normalize); writes "w" output tail
// ---------------------------------------------------------------------------
__global__ __launch_bounds__(256) void head_k(
    const float* __restrict__ Wt2, const float* __restrict__ Wt3,
    float* __restrict__ outw)
{
    const int n = blockIdx.x, tid = threadIdx.x;
    __shared__ float w1[256], w2[64], red[256];

    w1[tid] = g_sum[n * 256 + tid] * (1.f / 4096.f);
    __syncthreads();

    if (tid < 64) {
        float s = 0.f;
#pragma unroll 8
        for (int k = 0; k < 256; k++) s = fmaf(Wt2[tid * 256 + k], w1[k], s);
        w2[tid] = fmaxf(s, 0.f);
    }
    __syncthreads();

    float s = 0.f;
#pragma unroll
    for (int e = 0; e < 64; e++) s = fmaf(Wt3[tid * 64 + e], w2[e], s);

    red[tid] = s * s;
    __syncthreads();
    for (int off = 128; off > 0; off >>= 1) {
        if (tid < off) red[tid] += red[tid + off];
        __syncthreads();
    }
    float nv = sqrtf(red[0]);
    float wv = s / fmaxf(nv, 1e-12f);
    g_w[n * 256 + tid] = wv;
    outw[n * 256 + tid] = wv;
}

// ---------------------------------------------------------------------------
// Unified mma.sync 1x1-conv GEMM, single-pass fp16 (unchanged from R8)
// ---------------------------------------------------------------------------
#define TILE_B   10240                 // one 128x40 fp16 tile
#define ST2      (2 * TILE_B)          // A, B
#define NST      4
#define GEMM_SMEM (NST * ST2)          // 81920 bytes

template<int MODE>
__device__ __forceinline__ void gemm_body(
    int K, int COUT,
    const __half* s0, int st0,
    const __half* s1, int st1,
    const __half* s2, int st2,
    int kb0, int kb1,
    const __half* wp,
    const float* __restrict__ bias,
    __half* __restrict__ of)
{
    extern __shared__ __align__(128) char smem[];
    const uint32_t sb = smem_to_u32(smem);

    const int tid  = threadIdx.x;
    const int lane = tid & 31;
    const int wid  = tid >> 5;
    const int wm   = wid & 3;
    const int wn   = wid >> 2;
    const int n    = blockIdx.z;
    const int ocb  = blockIdx.y * 128;
    const int p0   = blockIdx.x * 128;

    float acc[2][4][4];
#pragma unroll
    for (int mi = 0; mi < 2; mi++)
#pragma unroll
        for (int ni = 0; ni < 4; ni++)
#pragma unroll
            for (int r = 0; r < 4; r++) acc[mi][ni][r] = 0.f;

    auto stage = [&](int chunk) {
        const uint32_t base = sb + (chunk & 3) * ST2;
        const int k0 = chunk * 32;
        const __half* sh; int stride, ks;
        if (k0 < kb0)      { sh = s0; stride = st0; ks = 0;   }
        else if (k0 < kb1) { sh = s1; stride = st1; ks = kb0; }
        else               { sh = s2; stride = st2; ks = kb1; }
        const int c0 = k0 - ks;
        if (tid < 512) {
            int row = (tid >> 2) & 127, seg = tid & 3;
            cp16(base + row * 80 + seg * 16,
                 wp + (size_t)(ocb + row) * K + k0 + seg * 8, 16);
            cp16(base + TILE_B + row * 80 + seg * 16,
                 sh + ((size_t)n * HW + p0 + row) * stride + c0 + seg * 8, 16);
        }
    };

    const int NC = K >> 5;
    stage(0); cp_commit();
    stage(1); cp_commit();

    for (int i = 0; i < NC; i++) {
        if (i + 2 < NC)      { stage(i + 2); cp_commit(); cp_wait<2>(); }
        else if (i + 1 < NC) cp_wait<1>();
        else                 cp_wait<0>();
        __syncthreads();

        const uint32_t base = sb + (i & 3) * ST2;
        const uint32_t aA = base;
        const uint32_t aB = base + TILE_B;

#pragma unroll
        for (int ks = 0; ks < 2; ks++) {
            const int kb = ks * 32;
            uint32_t ah[2][4];
#pragma unroll
            for (int mi = 0; mi < 2; mi++) {
                uint32_t ro = (uint32_t)(wm * 32 + mi * 16 + (lane & 15)) * 80
                            + (uint32_t)(lane >> 4) * 16 + kb;
                ldm_x4(ah[mi], aA + ro);
            }
#pragma unroll
            for (int ni = 0; ni < 4; ni++) {
                uint32_t ro = (uint32_t)(wn * 32 + ni * 8 + (lane >> 2)) * 80
                            + kb + (uint32_t)(lane & 3) * 4;
                uint32_t b0 = *(const uint32_t*)(smem + (aB + ro      - sb));
                uint32_t b1 = *(const uint32_t*)(smem + (aB + ro + 16 - sb));
#pragma unroll
                for (int mi = 0; mi < 2; mi++)
                    mma_f16(acc[mi][ni], ah[mi], b0, b1);
            }
        }
    }

    if (MODE == 0) {
#pragma unroll
        for (int mi = 0; mi < 2; mi++) {
            int r0 = ocb + wm * 32 + mi * 16 + (lane >> 2);
            float b0 = bias[r0], b1 = bias[r0 + 8];
            float s0v = 0.f, s1v = 0.f;
#pragma unroll
            for (int ni = 0; ni < 4; ni++) {
                s0v += fmaxf(acc[mi][ni][0] + b0, 0.f) + fmaxf(acc[mi][ni][1] + b0, 0.f);
                s1v += fmaxf(acc[mi][ni][2] + b1, 0.f) + fmaxf(acc[mi][ni][3] + b1, 0.f);
            }
            s0v += __shfl_xor_sync(0xffffffffu, s0v, 1);
            s0v += __shfl_xor_sync(0xffffffffu, s0v, 2);
            s1v += __shfl_xor_sync(0xffffffffu, s1v, 1);
            s1v += __shfl_xor_sync(0xffffffffu, s1v, 2);
            if ((lane & 3) == 0) {
                atomicAdd(&g_sum[n * 256 + r0],     s0v);
                atomicAdd(&g_sum[n * 256 + r0 + 8], s1v);
            }
        }
        return;
    }

    // transpose epilogue: per-warp 32x32 patch in (reused) smem
    __syncthreads();
    float* patch = (float*)smem + wid * (32 * 33);
#pragma unroll
    for (int mi = 0; mi < 2; mi++)
#pragma unroll
        for (int ni = 0; ni < 4; ni++) {
            int r = mi * 16 + (lane >> 2);
            int p = ni * 8 + (lane & 3) * 2;
            patch[r * 33 + p]           = acc[mi][ni][0];
            patch[r * 33 + p + 1]       = acc[mi][ni][1];
            patch[(r + 8) * 33 + p]     = acc[mi][ni][2];
            patch[(r + 8) * 33 + p + 1] = acc[mi][ni][3];
        }
    __syncwarp();

    const int pxg = p0 + wn * 32 + lane;
    const int oc0 = ocb + wm * 32;

    __half ff[32];
    if (MODE == 3) {
        const __half* gp; int gst, gks;
        if (oc0 < 128)      { gp = g_b2f;  gst = 128; gks = 0;   }
        else if (oc0 < 384) { gp = g_thxf; gst = 256; gks = 128; }
        else                { gp = g_txuf; gst = 256; gks = 384; }
        const __half* gr = gp + ((size_t)n * HW + pxg) * gst + (oc0 - gks);
#pragma unroll
        for (int j = 0; j < 32; j++) {
            float v = patch[j * 33 + lane] + bias[oc0 + j];
            float sg = 1.f / (1.f + expf(-v));
            ff[j] = __float2half(sg * __half2float(gr[j]));
        }
    } else {
#pragma unroll
        for (int j = 0; j < 32; j++) {
            float v = patch[j * 33 + lane] + bias[oc0 + j];
            v = fmaxf(v, 0.f);
            if (MODE == 1) v *= g_w[n * 256 + oc0 + j];
            ff[j] = __float2half(v);
        }
    }
    size_t o = ((size_t)n * HW + pxg) * COUT + oc0;
#pragma unroll
    for (int q = 0; q < 4; q++)
        *(uint4*)(of + o + q * 8) = ((const uint4*)ff)[q];
}

// ----- wrappers -------------------------------------------------------------
__global__ __launch_bounds__(512) void g_stageA_k(const float* __restrict__ bias)
{
    gemm_body<0>(768, 256, g_x1f, 256, g_thxf, 256, g_txuf, 256, 256, 512,
                 g_wt1, bias, nullptr);
}
__global__ __launch_bounds__(512) void g_b1_k(const float* __restrict__ bias)
{
    gemm_body<1>(256, 256, g_x2f, 256, nullptr, 0, nullptr, 0, 256, 256,
                 g_wU, bias, g_b1f);
}
__global__ __launch_bounds__(512) void g_b2_k(const float* __restrict__ bias)
{
    gemm_body<2>(256, 128, g_b1f, 256, nullptr, 0, nullptr, 0, 256, 256,
                 g_wV, bias, g_b2f);
}
__global__ __launch_bounds__(512) void g_a1_k(const float* __restrict__ bias)
{
    gemm_body<2>(640, 128, g_b2f, 128, g_thxf, 256, g_txuf, 256, 128, 384,
                 g_wa1, bias, g_a1f);
}
__global__ __launch_bounds__(512) void g_a2_k(const float* __restrict__ bias)
{
    gemm_body<3>(128, 640, g_a1f, 128, nullptr, 0, nullptr, 0, 128, 128,
                 g_wa2, bias, g_aT_f);
}

// ---------------------------------------------------------------------------
// mma.sync conv3x3, single-pass fp16, halo-shared B staging.
//   K loop restructured channels-outer / taps-inner:
//     step s = cc*9 + tap  (cc = 32-ch chunk 0..19, tap 0..8)
//   B: one [4 rows x 66 px][32 ch] halo tile per cc, shared by all 9 taps
//      (2-deep ring).  A: per-step [128oc][32k] tile (4-deep ring, dist 2).
//   One cp.async commit per step -> wait_group<2> exact.
// ---------------------------------------------------------------------------
#define CONV_A_TILE 10240              // 128 rows x 80B
#define CONV_B_TILE (264 * 80)         // 21120: 4x66 halo rows x 80B
#define CONV_SMEM   (4 * CONV_A_TILE + 2 * CONV_B_TILE)   // 83200

__global__ __launch_bounds__(512) void mma_conv3_k(
    const float* __restrict__ bot, float* __restrict__ out)
{
    extern __shared__ __align__(128) char smem[];
    const uint32_t sb  = smem_to_u32(smem);
    const uint32_t sbB = sb + 4 * CONV_A_TILE;

    const int tid  = threadIdx.x;
    const int lane = tid & 31;
    const int wid  = tid >> 5;
    const int wm   = wid & 3;
    const int wn   = wid >> 2;
    const int n    = blockIdx.z;
    const int ocb  = blockIdx.y * 128;
    const int by2  = blockIdx.x * 2;   // output row pair
    const int p0   = blockIdx.x * 128;

    float acc[2][4][4];
#pragma unroll
    for (int mi = 0; mi < 2; mi++)
#pragma unroll
        for (int ni = 0; ni < 4; ni++)
#pragma unroll
            for (int r = 0; r < 4; r++) acc[mi][ni][r] = 0.f;

    // A tile for step s (= cc*9+tap): weights [ocb..+128][tap*640 + cc*32 ..+32]
    auto stageA = [&](int s) {
        const uint32_t base = sb + (s & 3) * CONV_A_TILE;
        const int tap = s % 9, cc = s / 9;
        const int koff = tap * 640 + cc * 32;
        if (tid < 512) {
            int row = (tid >> 2) & 127, seg = tid & 3;
            cp16(base + row * 80 + seg * 16,
                 g_wf + (size_t)(ocb + row) * 5760 + koff + seg * 8, 16);
        }
    };
    // B halo for channel chunk cc: rows iy = by2-1..by2+2, ix = -1..64
    auto stageB = [&](int cc) {
        const uint32_t base = sbB + (cc & 1) * CONV_B_TILE;
        const int c0 = cc * 32;
        for (int it = tid; it < 1056; it += 512) {
            int hrow = it >> 2, seg = it & 3;        // hrow = ry*66 + rx
            int ry = hrow / 66, rx = hrow - ry * 66;
            int iy = by2 - 1 + ry, ix = rx - 1;
            bool ok = ((unsigned)iy < 64u) && ((unsigned)ix < 64u);
            const __half* src = ok
                ? g_aT_f + ((size_t)(n * HW + iy * 64 + ix)) * 640 + c0 + seg * 8
                : g_aT_f;
            cp16(base + hrow * 80 + seg * 16, src, ok ? 16u : 0u);
        }
    };

    const int NS = 180;                // 20 chunks x 9 taps
    stageB(0); stageA(0); cp_commit();
    stageA(1); cp_commit();

    for (int s = 0; s < NS; s++) {
        if (s + 2 < NS) {
            stageA(s + 2);
            if ((s + 2) % 9 == 0) stageB((s + 2) / 9);
            cp_commit(); cp_wait<2>();
        } else if (s + 1 < NS) cp_wait<1>();
        else                   cp_wait<0>();
        __syncthreads();

        const int tap = s % 9;
        const int dy = tap / 3 - 1, dx = tap % 3 - 1;
        const uint32_t aA = sb + (s & 3) * CONV_A_TILE;
        const uint32_t aB = sbB + ((s / 9) & 1) * CONV_B_TILE;

#pragma unroll
        for (int ks = 0; ks < 2; ks++) {
            const int kb = ks * 32;
            uint32_t ah[2][4];
#pragma unroll
            for (int mi = 0; mi < 2; mi++) {
                uint32_t ro = (uint32_t)(wm * 32 + mi * 16 + (lane & 15)) * 80
                            + (uint32_t)(lane >> 4) * 16 + kb;
                ldm_x4(ah[mi], aA + ro);
            }
#pragma unroll
            for (int ni = 0; ni < 4; ni++) {
                int pr = wn * 32 + ni * 8 + (lane >> 2);
                int hrow = ((pr >> 6) + dy + 1) * 66 + (pr & 63) + dx + 1;
                uint32_t ro = (uint32_t)hrow * 80 + kb + (lane & 3) * 4;
                uint32_t b0 = *(const uint32_t*)(smem + (aB + ro      - sb));
                uint32_t b1 = *(const uint32_t*)(smem + (aB + ro + 16 - sb));
#pragma unroll
                for (int mi = 0; mi < 2; mi++)
                    mma_f16(acc[mi][ni], ah[mi], b0, b1);
            }
        }
    }

    const size_t nb = (size_t)n * 256 * HW;
#pragma unroll
    for (int mi = 0; mi < 2; mi++) {
        int r0 = ocb + wm * 32 + mi * 16 + (lane >> 2);
        float bv0 = bot[r0], bv1 = bot[r0 + 8];
#pragma unroll
        for (int ni = 0; ni < 4; ni++) {
            int px = p0 + wn * 32 + ni * 8 + (lane & 3) * 2;
            float2 v0, v1;
            v0.x = fmaxf(acc[mi][ni][0] + bv0, 0.f);
            v0.y = fmaxf(acc[mi][ni][1] + bv0, 0.f);
            v1.x = fmaxf(acc[mi][ni][2] + bv1, 0.f);
            v1.y = fmaxf(acc[mi][ni][3] + bv1, 0.f);
            *(float2*)(out + nb + (size_t)r0 * HW + px)       = v0;
            *(float2*)(out + nb + (size_t)(r0 + 8) * HW + px) = v1;
        }
    }
}

// ---------------------------------------------------------------------------
// Launch
// ---------------------------------------------------------------------------
extern "C" void kernel_launch(void* const* d_in, const int* in_sizes, int n_in,
                              void* d_out, int out_size)
{
    const float* sx1  = (const float*)d_in[0];
    const float* sx2  = (const float*)d_in[1];
    const float* t_hx = (const float*)d_in[2];
    const float* tx   = (const float*)d_in[3];
    const float* W_t1 = (const float*)d_in[4];
    const float* b_t1 = (const float*)d_in[5];
    const float* W_t2 = (const float*)d_in[6];
    const float* W_t3 = (const float*)d_in[7];
    const float* W_U  = (const float*)d_in[8];
    const float* b_U  = (const float*)d_in[9];
    const float* W_V  = (const float*)d_in[10];
    const float* b_V  = (const float*)d_in[11];
    const float* W_a1 = (const float*)d_in[12];
    const float* b_a1 = (const float*)d_in[13];
    const float* W_a2 = (const float*)d_in[14];
    const float* b_a2 = (const float*)d_in[15];
    const float* W_ot = (const float*)d_in[16];
    const float* b_ot = (const float*)d_in[17];
    float* out = (float*)d_out;

    cudaFuncSetAttribute(g_stageA_k,  cudaFuncAttributeMaxDynamicSharedMemorySize, GEMM_SMEM);
    cudaFuncSetAttribute(g_b1_k,      cudaFuncAttributeMaxDynamicSharedMemorySize, GEMM_SMEM);
    cudaFuncSetAttribute(g_b2_k,      cudaFuncAttributeMaxDynamicSharedMemorySize, GEMM_SMEM);
    cudaFuncSetAttribute(g_a1_k,      cudaFuncAttributeMaxDynamicSharedMemorySize, GEMM_SMEM);
    cudaFuncSetAttribute(g_a2_k,      cudaFuncAttributeMaxDynamicSharedMemorySize, GEMM_SMEM);
    cudaFuncSetAttribute(mma_conv3_k, cudaFuncAttributeMaxDynamicSharedMemorySize, CONV_SMEM);

    // weight conversions (+ g_sum zero)
    split_all_k<<<dim3(96, 6), 256>>>(W_t1, W_U, W_V, W_a1, W_a2);
    cvt_w_k<<<256, 256>>>(W_ot);
    // activation conversions
    ups_cvt_k<<<dim3(64, 4, 8), 256>>>(tx);
    cvt3_k<<<dim3(64, 12, 8), 256>>>(sx1, t_hx, sx2);
    // stage A GEMM + GAP
    g_stageA_k<<<dim3(32, 2, 8), 512, GEMM_SMEM>>>(b_t1);
    // head MLP + normalize
    head_k<<<8, 256>>>(W_t2, W_t3, out + OUT_A_ELEMS);
    // b1 = relu(W_U@sx2 + b)*w
    g_b1_k<<<dim3(32, 2, 8), 512, GEMM_SMEM>>>(b_U);
    // b2 = relu(W_V@b1 + b)
    g_b2_k<<<dim3(32, 1, 8), 512, GEMM_SMEM>>>(b_V);
    // a1 = relu(W_a1@[b2;thx;txu] + b)
    g_a1_k<<<dim3(32, 1, 8), 512, GEMM_SMEM>>>(b_a1);
    // apod = sigmoid(W_a2@a1 + b) * bcat -> g_aT_f
    g_a2_k<<<dim3(32, 5, 8), 512, GEMM_SMEM>>>(b_a2);
    // conv3x3 + bias + relu -> main output (halo-shared B)
    mma_conv3_k<<<dim3(32, 2, 8), 512, CONV_SMEM>>>(b_ot, out);
}

// round 11
// speedup vs baseline: 4.6757x; 1.0278x over previous
#include <cuda_runtime.h>
#include <cuda_fp16.h>
#include <math.h>
#include <stdint.h>

// ---------------------------------------------------------------------------
// Problem constants
// ---------------------------------------------------------------------------
#define HW     4096          // 64*64
#define NB     8
#define OUT_A_ELEMS (8 * 256 * 4096)   // "a" output
// output layout: a [8,256,64,64] followed by w [8,256]

// ---------------------------------------------------------------------------
// Scratch (static device globals -- no allocation allowed)
// ---------------------------------------------------------------------------
__device__ float g_sum [8 * 256];          // stage-A GAP accumulator
__device__ float g_w   [8 * 256];          // normalized channel weights

// fp16 channel-last activation planes [n*4096][C]
__device__ __align__(16) __half g_x1f [8ULL * 4096 * 256];
__device__ __align__(16) __half g_thxf[8ULL * 4096 * 256];
__device__ __align__(16) __half g_txuf[8ULL * 4096 * 256];
__device__ __align__(16) __half g_x2f [8ULL * 4096 * 256];
__device__ __align__(16) __half g_b1f [8ULL * 4096 * 256];
__device__ __align__(16) __half g_b2f [8ULL * 4096 * 128];
__device__ __align__(16) __half g_a1f [8ULL * 4096 * 128];
__device__ __align__(16) __half g_aT_f[8ULL * 4096 * 640];

// fp16 weights (row-major [O][K])
__device__ __align__(16) __half g_wt1[256 * 768];
__device__ __align__(16) __half g_wU [256 * 256];
__device__ __align__(16) __half g_wV [128 * 256];
__device__ __align__(16) __half g_wa1[128 * 640];
__device__ __align__(16) __half g_wa2[640 * 128];
// conv3x3 weights, tap-major [oc][tap*640+c]
__device__ __align__(16) __half g_wf[256 * 5760];

// ---------------------------------------------------------------------------
// helpers
// ---------------------------------------------------------------------------
__device__ __forceinline__ uint32_t smem_to_u32(const void* p) {
    uint32_t a;
    asm("{ .reg .u64 t; cvta.to.shared.u64 t, %1; cvt.u32.u64 %0, t; }"
        : "=r"(a) : "l"(p));
    return a;
}

__device__ __forceinline__ void cp16(uint32_t dst, const void* src, uint32_t bytes) {
    asm volatile("cp.async.cg.shared.global [%0], [%1], 16, %2;"
                 :: "r"(dst), "l"(src), "r"(bytes) : "memory");
}
__device__ __forceinline__ void cp_commit() {
    asm volatile("cp.async.commit_group;" ::: "memory");
}
template<int N>
__device__ __forceinline__ void cp_wait() {
    asm volatile("cp.async.wait_group %0;" :: "n"(N) : "memory");
}

__device__ __forceinline__ void ldm_x4(uint32_t (&r)[4], uint32_t addr) {
    asm volatile("ldmatrix.sync.aligned.m8n8.x4.shared.b16 {%0,%1,%2,%3}, [%4];"
                 : "=r"(r[0]), "=r"(r[1]), "=r"(r[2]), "=r"(r[3]) : "r"(addr));
}

__device__ __forceinline__ void mma_f16(float (&c)[4], const uint32_t (&a)[4],
                                        uint32_t b0, uint32_t b1) {
    asm volatile(
        "mma.sync.aligned.m16n8k16.row.col.f32.f16.f16.f32 "
        "{%0,%1,%2,%3}, {%4,%5,%6,%7}, {%8,%9}, {%0,%1,%2,%3};"
        : "+f"(c[0]), "+f"(c[1]), "+f"(c[2]), "+f"(c[3])
        : "r"(a[0]), "r"(a[1]), "r"(a[2]), "r"(a[3]), "r"(b0), "r"(b1));
}

// ---------------------------------------------------------------------------
// fused upsample x2 (align_corners) + transpose + fp16: tx -> g_txuf
// ---------------------------------------------------------------------------
__global__ __launch_bounds__(256) void ups_cvt_k(const float* __restrict__ tx)
{
    __shared__ float s0[64][32], s1[64][32];
    const int y  = blockIdx.x;
    const int c0 = blockIdx.y * 64;
    const int n  = blockIdx.z;

    const float step = 31.0f / 63.0f;
    const float fy = y * step;
    const int y0 = (int)fy;
    const int y1 = min(y0 + 1, 31);
    const float wy = fy - y0;

    for (int it = threadIdx.x; it < 4096; it += 256) {
        int c = it >> 6, r = (it >> 5) & 1, x = it & 31;
        const float* sp = tx + (((size_t)(n * 256 + c0 + c) * 32) + (r ? y1 : y0)) * 32;
        if (r) s1[c][x] = sp[x]; else s0[c][x] = sp[x];
    }
    __syncthreads();

    for (int it = threadIdx.x; it < 4096; it += 256) {
        int x = it >> 6, c = it & 63;
        float fx = x * step;
        int x0 = (int)fx;  float wx = fx - x0;
        int x1 = min(x0 + 1, 31);
        float top = s0[c][x0] * (1.f - wx) + s0[c][x1] * wx;
        float bot = s1[c][x0] * (1.f - wx) + s1[c][x1] * wx;
        g_txuf[((size_t)n * HW + y * 64 + x) * 256 + c0 + c] =
            __float2half(top * (1.f - wy) + bot * wy);
    }
}

// ---------------------------------------------------------------------------
// transpose + fp16: [n][256][4096] fp32 -> [n*4096][256] fp16 (3 sources)
// ---------------------------------------------------------------------------
__global__ __launch_bounds__(256) void cvt3_k(
    const float* __restrict__ sx1, const float* __restrict__ t_hx,
    const float* __restrict__ sx2)
{
    __shared__ float t[64][65];
    const int src = blockIdx.y >> 2;
    const int c0  = (blockIdx.y & 3) * 64;
    const int n   = blockIdx.z, p0 = blockIdx.x * 64;
    const float* sp = (src == 0 ? sx1 : src == 1 ? t_hx : sx2)
                    + ((size_t)n * 256 + c0) * HW + p0;
    __half* dst = (src == 0 ? g_x1f : src == 1 ? g_thxf : g_x2f);

    for (int it = threadIdx.x; it < 4096; it += 256) {
        int c = it >> 6, px = it & 63;
        t[c][px] = sp[(size_t)c * HW + px];
    }
    __syncthreads();
    for (int it = threadIdx.x; it < 512; it += 256) {
        int px = it >> 3, cg = (it & 7) * 8;
        __half hh[8];
#pragma unroll
        for (int j = 0; j < 8; j++) hh[j] = __float2half(t[cg + j][px]);
        *(uint4*)(dst + ((size_t)n * HW + p0 + px) * 256 + c0 + cg) = *(uint4*)hh;
    }
}

// ---------------------------------------------------------------------------
// weight conversions (single fp16) + g_sum zeroing
// ---------------------------------------------------------------------------
__global__ __launch_bounds__(256) void split_all_k(
    const float* __restrict__ a, const float* __restrict__ b,
    const float* __restrict__ c, const float* __restrict__ d,
    const float* __restrict__ e)
{
    if (blockIdx.y == 5) {
        int i = blockIdx.x * 256 + threadIdx.x;
        if (i < 8 * 256) g_sum[i] = 0.f;
        return;
    }
    const float* src; __half* h; int nel;
    switch (blockIdx.y) {
        case 0:  src = a; h = g_wt1; nel = 256 * 768; break;
        case 1:  src = b; h = g_wU;  nel = 256 * 256; break;
        case 2:  src = c; h = g_wV;  nel = 128 * 256; break;
        case 3:  src = d; h = g_wa1; nel = 128 * 640; break;
        default: src = e; h = g_wa2; nel = 640 * 128; break;
    }
    for (int i = blockIdx.x * 256 + threadIdx.x; i < nel; i += gridDim.x * 256)
        h[i] = __float2half(src[i]);
}

// conv weights: [oc][c][ky][kx] fp32 -> tap-major [oc][tap*640+c] fp16
__global__ __launch_bounds__(256) void cvt_w_k(const float* __restrict__ W)
{
    const int oc = blockIdx.x;
    for (int t = threadIdx.x; t < 5760; t += 256) {
        int c = t / 9, tap = t - c * 9;
        g_wf[(size_t)oc * 5760 + (size_t)tap * 640 + c] =
            __float2half(W[(size_t)oc * 5760 + t]);
    }
}

// ---------------------------------------------------------------------------
// Head (squeeze-excite MLP + L2 normalize); writes "w" output tail
// ---------------------------------------------------------------------------
__global__ __launch_bounds__(256) void head_k(
    const float* __restrict__ Wt2, const float* __restrict__ Wt3,
    float* __restrict__ outw)
{
    const int n = blockIdx.x, tid = threadIdx.x;
    __shared__ float w1[256], w2[64], red[256];

    w1[tid] = g_sum[n * 256 + tid] * (1.f / 4096.f);
    __syncthreads();

    if (tid < 64) {
        float s = 0.f;
#pragma unroll 8
        for (int k = 0; k < 256; k++) s = fmaf(Wt2[tid * 256 + k], w1[k], s);
        w2[tid] = fmaxf(s, 0.f);
    }
    __syncthreads();

    float s = 0.f;
#pragma unroll
    for (int e = 0; e < 64; e++) s = fmaf(Wt3[tid * 64 + e], w2[e], s);

    red[tid] = s * s;
    __syncthreads();
    for (int off = 128; off > 0; off >>= 1) {
        if (tid < off) red[tid] += red[tid + off];
        __syncthreads();
    }
    float nv = sqrtf(red[0]);
    float wv = s / fmaxf(nv, 1e-12f);
    g_w[n * 256 + tid] = wv;
    outw[n * 256 + tid] = wv;
}

// ---------------------------------------------------------------------------
// Unified mma.sync 1x1-conv GEMM, single-pass fp16, N=256 px tiles.
//   CTA 128oc x 256px, 16 warps (4m x 4n), warp tile 32oc x 64px.
//   K chunks of 32, 4-stage cp.async ring (dist-2 prefetch).
// ---------------------------------------------------------------------------
#define TILE_A   10240                 // A: 128 rows x 80B
#define TILE_BB  20480                 // B: 256 rows x 80B
#define ST2      (TILE_A + TILE_BB)    // 30720
#define NST      4
#define GEMM_SMEM (NST * ST2)          // 122880 bytes

template<int MODE>
__device__ __forceinline__ void gemm_body(
    int K, int COUT,
    const __half* s0, int st0,
    const __half* s1, int st1,
    const __half* s2, int st2,
    int kb0, int kb1,
    const __half* wp,
    const float* __restrict__ bias,
    __half* __restrict__ of)
{
    extern __shared__ __align__(128) char smem[];
    const uint32_t sb = smem_to_u32(smem);

    const int tid  = threadIdx.x;
    const int lane = tid & 31;
    const int wid  = tid >> 5;
    const int wm   = wid & 3;
    const int wn   = wid >> 2;
    const int n    = blockIdx.z;
    const int ocb  = blockIdx.y * 128;
    const int p0   = blockIdx.x * 256;

    float acc[2][8][4];
#pragma unroll
    for (int mi = 0; mi < 2; mi++)
#pragma unroll
        for (int ni = 0; ni < 8; ni++)
#pragma unroll
            for (int r = 0; r < 4; r++) acc[mi][ni][r] = 0.f;

    auto stage = [&](int chunk) {
        const uint32_t base = sb + (chunk & 3) * ST2;
        const int k0 = chunk * 32;
        const __half* sh; int stride, ks;
        if (k0 < kb0)      { sh = s0; stride = st0; ks = 0;   }
        else if (k0 < kb1) { sh = s1; stride = st1; ks = kb0; }
        else               { sh = s2; stride = st2; ks = kb1; }
        const int c0 = k0 - ks;
#pragma unroll
        for (int it = tid; it < 1536; it += 512) {
            int seg = it & 3;
            if (it < 512) {
                int row = it >> 2;
                cp16(base + row * 80 + seg * 16,
                     wp + (size_t)(ocb + row) * K + k0 + seg * 8, 16);
            } else {
                int row = (it - 512) >> 2;
                cp16(base + TILE_A + row * 80 + seg * 16,
                     sh + ((size_t)n * HW + p0 + row) * stride + c0 + seg * 8, 16);
            }
        }
    };

    const int NC = K >> 5;
    stage(0); cp_commit();
    stage(1); cp_commit();

    for (int i = 0; i < NC; i++) {
        if (i + 2 < NC)      { stage(i + 2); cp_commit(); cp_wait<2>(); }
        else if (i + 1 < NC) cp_wait<1>();
        else                 cp_wait<0>();
        __syncthreads();

        const uint32_t base = sb + (i & 3) * ST2;
        const uint32_t aA = base;
        const uint32_t aB = base + TILE_A;

#pragma unroll
        for (int ks = 0; ks < 2; ks++) {
            const int kb = ks * 32;
            uint32_t ah[2][4];
#pragma unroll
            for (int mi = 0; mi < 2; mi++) {
                uint32_t ro = (uint32_t)(wm * 32 + mi * 16 + (lane & 15)) * 80
                            + (uint32_t)(lane >> 4) * 16 + kb;
                ldm_x4(ah[mi], aA + ro);
            }
#pragma unroll
            for (int ni = 0; ni < 8; ni++) {
                uint32_t ro = (uint32_t)(wn * 64 + ni * 8 + (lane >> 2)) * 80
                            + kb + (uint32_t)(lane & 3) * 4;
                uint32_t b0 = *(const uint32_t*)(smem + (aB + ro      - sb));
                uint32_t b1 = *(const uint32_t*)(smem + (aB + ro + 16 - sb));
#pragma unroll
                for (int mi = 0; mi < 2; mi++)
                    mma_f16(acc[mi][ni], ah[mi], b0, b1);
            }
        }
    }

    if (MODE == 0) {
#pragma unroll
        for (int mi = 0; mi < 2; mi++) {
            int r0 = ocb + wm * 32 + mi * 16 + (lane >> 2);
            float b0 = bias[r0], b1 = bias[r0 + 8];
            float s0v = 0.f, s1v = 0.f;
#pragma unroll
            for (int ni = 0; ni < 8; ni++) {
                s0v += fmaxf(acc[mi][ni][0] + b0, 0.f) + fmaxf(acc[mi][ni][1] + b0, 0.f);
                s1v += fmaxf(acc[mi][ni][2] + b1, 0.f) + fmaxf(acc[mi][ni][3] + b1, 0.f);
            }
            s0v += __shfl_xor_sync(0xffffffffu, s0v, 1);
            s0v += __shfl_xor_sync(0xffffffffu, s0v, 2);
            s1v += __shfl_xor_sync(0xffffffffu, s1v, 1);
            s1v += __shfl_xor_sync(0xffffffffu, s1v, 2);
            if ((lane & 3) == 0) {
                atomicAdd(&g_sum[n * 256 + r0],     s0v);
                atomicAdd(&g_sum[n * 256 + r0 + 8], s1v);
            }
        }
        return;
    }

    // transpose epilogue: two 32px halves per warp, 32x32 patch in smem
    __syncthreads();
    float* patch = (float*)smem + wid * (32 * 33);
    const int oc0 = ocb + wm * 32;

#pragma unroll
    for (int h = 0; h < 2; h++) {
#pragma unroll
        for (int mi = 0; mi < 2; mi++)
#pragma unroll
            for (int nl = 0; nl < 4; nl++) {
                int ni = h * 4 + nl;
                int r = mi * 16 + (lane >> 2);
                int p = nl * 8 + (lane & 3) * 2;
                patch[r * 33 + p]           = acc[mi][ni][0];
                patch[r * 33 + p + 1]       = acc[mi][ni][1];
                patch[(r + 8) * 33 + p]     = acc[mi][ni][2];
                patch[(r + 8) * 33 + p + 1] = acc[mi][ni][3];
            }
        __syncwarp();

        const int pxg = p0 + wn * 64 + h * 32 + lane;
        __half ff[32];
        if (MODE == 3) {
            const __half* gp; int gst, gks;
            if (oc0 < 128)      { gp = g_b2f;  gst = 128; gks = 0;   }
            else if (oc0 < 384) { gp = g_thxf; gst = 256; gks = 128; }
            else                { gp = g_txuf; gst = 256; gks = 384; }
            const __half* gr = gp + ((size_t)n * HW + pxg) * gst + (oc0 - gks);
#pragma unroll
            for (int j = 0; j < 32; j++) {
                float v = patch[j * 33 + lane] + bias[oc0 + j];
                float sg = 1.f / (1.f + expf(-v));
                ff[j] = __float2half(sg * __half2float(gr[j]));
            }
        } else {
#pragma unroll
            for (int j = 0; j < 32; j++) {
                float v = patch[j * 33 + lane] + bias[oc0 + j];
                v = fmaxf(v, 0.f);
                if (MODE == 1) v *= g_w[n * 256 + oc0 + j];
                ff[j] = __float2half(v);
            }
        }
        size_t o = ((size_t)n * HW + pxg) * COUT + oc0;
#pragma unroll
        for (int q = 0; q < 4; q++)
            *(uint4*)(of + o + q * 8) = ((const uint4*)ff)[q];
        __syncwarp();
    }
}

// ----- wrappers -------------------------------------------------------------
__global__ __launch_bounds__(512) void g_stageA_k(const float* __restrict__ bias)
{
    gemm_body<0>(768, 256, g_x1f, 256, g_thxf, 256, g_txuf, 256, 256, 512,
                 g_wt1, bias, nullptr);
}
__global__ __launch_bounds__(512) void g_b1_k(const float* __restrict__ bias)
{
    gemm_body<1>(256, 256, g_x2f, 256, nullptr, 0, nullptr, 0, 256, 256,
                 g_wU, bias, g_b1f);
}
__global__ __launch_bounds__(512) void g_b2_k(const float* __restrict__ bias)
{
    gemm_body<2>(256, 128, g_b1f, 256, nullptr, 0, nullptr, 0, 256, 256,
                 g_wV, bias, g_b2f);
}
__global__ __launch_bounds__(512) void g_a1_k(const float* __restrict__ bias)
{
    gemm_body<2>(640, 128, g_b2f, 128, g_thxf, 256, g_txuf, 256, 128, 384,
                 g_wa1, bias, g_a1f);
}
__global__ __launch_bounds__(512) void g_a2_k(const float* __restrict__ bias)
{
    gemm_body<3>(128, 640, g_a1f, 128, nullptr, 0, nullptr, 0, 128, 128,
                 g_wa2, bias, g_aT_f);
}

// ---------------------------------------------------------------------------
// mma.sync conv3x3, single-pass fp16, N=256 px (4 rows), halo-shared B.
//   step s = cc*9 + tap; B halo [6 rows x 66 px][32ch] per cc (2-deep ring);
//   A per-step [128oc][32k] (4-deep ring, dist 2).
// ---------------------------------------------------------------------------
#define CONV_A_TILE 10240              // 128 rows x 80B
#define CONV_B_TILE (396 * 80)         // 31680: 6x66 halo rows x 80B
#define CONV_SMEM   (4 * CONV_A_TILE + 2 * CONV_B_TILE)   // 104320

__global__ __launch_bounds__(512) void mma_conv3_k(
    const float* __restrict__ bot, float* __restrict__ out)
{
    extern __shared__ __align__(128) char smem[];
    const uint32_t sb  = smem_to_u32(smem);
    const uint32_t sbB = sb + 4 * CONV_A_TILE;

    const int tid  = threadIdx.x;
    const int lane = tid & 31;
    const int wid  = tid >> 5;
    const int wm   = wid & 3;
    const int wn   = wid >> 2;
    const int n    = blockIdx.z;
    const int ocb  = blockIdx.y * 128;
    const int by4  = blockIdx.x * 4;   // 4 output rows
    const int p0   = blockIdx.x * 256;

    float acc[2][8][4];
#pragma unroll
    for (int mi = 0; mi < 2; mi++)
#pragma unroll
        for (int ni = 0; ni < 8; ni++)
#pragma unroll
            for (int r = 0; r < 4; r++) acc[mi][ni][r] = 0.f;

    auto stageA = [&](int s) {
        const uint32_t base = sb + (s & 3) * CONV_A_TILE;
        const int tap = s % 9, cc = s / 9;
        const int koff = tap * 640 + cc * 32;
        if (tid < 512) {
            int row = (tid >> 2) & 127, seg = tid & 3;
            cp16(base + row * 80 + seg * 16,
                 g_wf + (size_t)(ocb + row) * 5760 + koff + seg * 8, 16);
        }
    };
    auto stageB = [&](int cc) {
        const uint32_t base = sbB + (cc & 1) * CONV_B_TILE;
        const int c0 = cc * 32;
        for (int it = tid; it < 1584; it += 512) {
            int hrow = it >> 2, seg = it & 3;        // hrow = ry*66 + rx
            int ry = hrow / 66, rx = hrow - ry * 66;
            int iy = by4 - 1 + ry, ix = rx - 1;
            bool ok = ((unsigned)iy < 64u) && ((unsigned)ix < 64u);
            const __half* src = ok
                ? g_aT_f + ((size_t)(n * HW + iy * 64 + ix)) * 640 + c0 + seg * 8
                : g_aT_f;
            cp16(base + hrow * 80 + seg * 16, src, ok ? 16u : 0u);
        }
    };

    const int NS = 180;                // 20 chunks x 9 taps
    stageB(0); stageA(0); cp_commit();
    stageA(1); cp_commit();

    for (int s = 0; s < NS; s++) {
        if (s + 2 < NS) {
            stageA(s + 2);
            if ((s + 2) % 9 == 0) stageB((s + 2) / 9);
            cp_commit(); cp_wait<2>();
        } else if (s + 1 < NS) cp_wait<1>();
        else                   cp_wait<0>();
        __syncthreads();

        const int tap = s % 9;
        const int dy = tap / 3 - 1, dx = tap % 3 - 1;
        const uint32_t aA = sb + (s & 3) * CONV_A_TILE;
        const uint32_t aB = sbB + ((s / 9) & 1) * CONV_B_TILE;

#pragma unroll
        for (int ks = 0; ks < 2; ks++) {
            const int kb = ks * 32;
            uint32_t ah[2][4];
#pragma unroll
            for (int mi = 0; mi < 2; mi++) {
                uint32_t ro = (uint32_t)(wm * 32 + mi * 16 + (lane & 15)) * 80
                            + (uint32_t)(lane >> 4) * 16 + kb;
                ldm_x4(ah[mi], aA + ro);
            }
#pragma unroll
            for (int ni = 0; ni < 8; ni++) {
                int pr = wn * 64 + ni * 8 + (lane >> 2);
                int hrow = ((pr >> 6) + dy + 1) * 66 + (pr & 63) + dx + 1;
                uint32_t ro = (uint32_t)hrow * 80 + kb + (lane & 3) * 4;
                uint32_t b0 = *(const uint32_t*)(smem + (aB + ro      - sb));
                uint32_t b1 = *(const uint32_t*)(smem + (aB + ro + 16 - sb));
#pragma unroll
                for (int mi = 0; mi < 2; mi++)
                    mma_f16(acc[mi][ni], ah[mi], b0, b1);
            }
        }
    }

    const size_t nb = (size_t)n * 256 * HW;
#pragma unroll
    for (int mi = 0; mi < 2; mi++) {
        int r0 = ocb + wm * 32 + mi * 16 + (lane >> 2);
        float bv0 = bot[r0], bv1 = bot[r0 + 8];
#pragma unroll
        for (int ni = 0; ni < 8; ni++) {
            int px = p0 + wn * 64 + ni * 8 + (lane & 3) * 2;
            float2 v0, v1;
            v0.x = fmaxf(acc[mi][ni][0] + bv0, 0.f);
            v0.y = fmaxf(acc[mi][ni][1] + bv0, 0.f);
            v1.x = fmaxf(acc[mi][ni][2] + bv1, 0.f);
            v1.y = fmaxf(acc[mi][ni][3] + bv1, 0.f);
            *(float2*)(out + nb + (size_t)r0 * HW + px)       = v0;
            *(float2*)(out + nb + (size_t)(r0 + 8) * HW + px) = v1;
        }
    }
}

// ---------------------------------------------------------------------------
// Launch
// ---------------------------------------------------------------------------
extern "C" void kernel_launch(void* const* d_in, const int* in_sizes, int n_in,
                              void* d_out, int out_size)
{
    const float* sx1  = (const float*)d_in[0];
    const float* sx2  = (const float*)d_in[1];
    const float* t_hx = (const float*)d_in[2];
    const float* tx   = (const float*)d_in[3];
    const float* W_t1 = (const float*)d_in[4];
    const float* b_t1 = (const float*)d_in[5];
    const float* W_t2 = (const float*)d_in[6];
    const float* W_t3 = (const float*)d_in[7];
    const float* W_U  = (const float*)d_in[8];
    const float* b_U  = (const float*)d_in[9];
    const float* W_V  = (const float*)d_in[10];
    const float* b_V  = (const float*)d_in[11];
    const float* W_a1 = (const float*)d_in[12];
    const float* b_a1 = (const float*)d_in[13];
    const float* W_a2 = (const float*)d_in[14];
    const float* b_a2 = (const float*)d_in[15];
    const float* W_ot = (const float*)d_in[16];
    const float* b_ot = (const float*)d_in[17];
    float* out = (float*)d_out;

    cudaFuncSetAttribute(g_stageA_k,  cudaFuncAttributeMaxDynamicSharedMemorySize, GEMM_SMEM);
    cudaFuncSetAttribute(g_b1_k,      cudaFuncAttributeMaxDynamicSharedMemorySize, GEMM_SMEM);
    cudaFuncSetAttribute(g_b2_k,      cudaFuncAttributeMaxDynamicSharedMemorySize, GEMM_SMEM);
    cudaFuncSetAttribute(g_a1_k,      cudaFuncAttributeMaxDynamicSharedMemorySize, GEMM_SMEM);
    cudaFuncSetAttribute(g_a2_k,      cudaFuncAttributeMaxDynamicSharedMemorySize, GEMM_SMEM);
    cudaFuncSetAttribute(mma_conv3_k, cudaFuncAttributeMaxDynamicSharedMemorySize, CONV_SMEM);

    // weight conversions (+ g_sum zero)
    split_all_k<<<dim3(96, 6), 256>>>(W_t1, W_U, W_V, W_a1, W_a2);
    cvt_w_k<<<256, 256>>>(W_ot);
    // activation conversions
    ups_cvt_k<<<dim3(64, 4, 8), 256>>>(tx);
    cvt3_k<<<dim3(64, 12, 8), 256>>>(sx1, t_hx, sx2);
    // stage A GEMM + GAP
    g_stageA_k<<<dim3(16, 2, 8), 512, GEMM_SMEM>>>(b_t1);
    // head MLP + normalize
    head_k<<<8, 256>>>(W_t2, W_t3, out + OUT_A_ELEMS);
    // b1 = relu(W_U@sx2 + b)*w
    g_b1_k<<<dim3(16, 2, 8), 512, GEMM_SMEM>>>(b_U);
    // b2 = relu(W_V@b1 + b)
    g_b2_k<<<dim3(16, 1, 8), 512, GEMM_SMEM>>>(b_V);
    // a1 = relu(W_a1@[b2;thx;txu] + b)
    g_a1_k<<<dim3(16, 1, 8), 512, GEMM_SMEM>>>(b_a1);
    // apod = sigmoid(W_a2@a1 + b) * bcat -> g_aT_f
    g_a2_k<<<dim3(16, 5, 8), 512, GEMM_SMEM>>>(b_a2);
    // conv3x3 + bias + relu -> main output
    mma_conv3_k<<<dim3(16, 2, 8), 512, CONV_SMEM>>>(b_ot, out);
}

// round 12
// speedup vs baseline: 4.8197x; 1.0308x over previous
#include <cuda_runtime.h>
#include <cuda_fp16.h>
#include <math.h>
#include <stdint.h>

// ---------------------------------------------------------------------------
// Problem constants
// ---------------------------------------------------------------------------
#define HW     4096          // 64*64
#define NB     8
#define OUT_A_ELEMS (8 * 256 * 4096)   // "a" output
// output layout: a [8,256,64,64] followed by w [8,256]

// ---------------------------------------------------------------------------
// Scratch (static device globals -- no allocation allowed)
// ---------------------------------------------------------------------------
__device__ float g_sum [8 * 256];          // stage-A GAP accumulator
__device__ float g_w   [8 * 256];          // normalized channel weights

// fp16 channel-last activation planes [n*4096][C]
__device__ __align__(16) __half g_x1f [8ULL * 4096 * 256];
__device__ __align__(16) __half g_thxf[8ULL * 4096 * 256];
__device__ __align__(16) __half g_txuf[8ULL * 4096 * 256];
__device__ __align__(16) __half g_x2f [8ULL * 4096 * 256];
__device__ __align__(16) __half g_b1f [8ULL * 4096 * 256];
__device__ __align__(16) __half g_b2f [8ULL * 4096 * 128];
__device__ __align__(16) __half g_a1f [8ULL * 4096 * 128];
__device__ __align__(16) __half g_aT_f[8ULL * 4096 * 640];

// fp16 weights (row-major [O][K])
__device__ __align__(16) __half g_wt1[256 * 768];
__device__ __align__(16) __half g_wU [256 * 256];
__device__ __align__(16) __half g_wV [128 * 256];
__device__ __align__(16) __half g_wa1[128 * 640];
__device__ __align__(16) __half g_wa2[640 * 128];
// conv3x3 weights, tap-major [oc][tap*640+c]
__device__ __align__(16) __half g_wf[256 * 5760];

// ---------------------------------------------------------------------------
// helpers
// ---------------------------------------------------------------------------
__device__ __forceinline__ uint32_t smem_to_u32(const void* p) {
    uint32_t a;
    asm("{ .reg .u64 t; cvta.to.shared.u64 t, %1; cvt.u32.u64 %0, t; }"
        : "=r"(a) : "l"(p));
    return a;
}

__device__ __forceinline__ void cp16(uint32_t dst, const void* src, uint32_t bytes) {
    asm volatile("cp.async.cg.shared.global [%0], [%1], 16, %2;"
                 :: "r"(dst), "l"(src), "r"(bytes) : "memory");
}
__device__ __forceinline__ void cp_commit() {
    asm volatile("cp.async.commit_group;" ::: "memory");
}
template<int N>
__device__ __forceinline__ void cp_wait() {
    asm volatile("cp.async.wait_group %0;" :: "n"(N) : "memory");
}

__device__ __forceinline__ void ldm_x4(uint32_t (&r)[4], uint32_t addr) {
    asm volatile("ldmatrix.sync.aligned.m8n8.x4.shared.b16 {%0,%1,%2,%3}, [%4];"
                 : "=r"(r[0]), "=r"(r[1]), "=r"(r[2]), "=r"(r[3]) : "r"(addr));
}

__device__ __forceinline__ void mma_f16(float (&c)[4], const uint32_t (&a)[4],
                                        uint32_t b0, uint32_t b1) {
    asm volatile(
        "mma.sync.aligned.m16n8k16.row.col.f32.f16.f16.f32 "
        "{%0,%1,%2,%3}, {%4,%5,%6,%7}, {%8,%9}, {%0,%1,%2,%3};"
        : "+f"(c[0]), "+f"(c[1]), "+f"(c[2]), "+f"(c[3])
        : "r"(a[0]), "r"(a[1]), "r"(a[2]), "r"(a[3]), "r"(b0), "r"(b1));
}

// ---------------------------------------------------------------------------
// fused upsample x2 (align_corners) + transpose + fp16: tx -> g_txuf
// ---------------------------------------------------------------------------
__global__ __launch_bounds__(256) void ups_cvt_k(const float* __restrict__ tx)
{
    __shared__ float s0[64][32], s1[64][32];
    const int y  = blockIdx.x;
    const int c0 = blockIdx.y * 64;
    const int n  = blockIdx.z;

    const float step = 31.0f / 63.0f;
    const float fy = y * step;
    const int y0 = (int)fy;
    const int y1 = min(y0 + 1, 31);
    const float wy = fy - y0;

    for (int it = threadIdx.x; it < 4096; it += 256) {
        int c = it >> 6, r = (it >> 5) & 1, x = it & 31;
        const float* sp = tx + (((size_t)(n * 256 + c0 + c) * 32) + (r ? y1 : y0)) * 32;
        if (r) s1[c][x] = sp[x]; else s0[c][x] = sp[x];
    }
    __syncthreads();

    for (int it = threadIdx.x; it < 4096; it += 256) {
        int x = it >> 6, c = it & 63;
        float fx = x * step;
        int x0 = (int)fx;  float wx = fx - x0;
        int x1 = min(x0 + 1, 31);
        float top = s0[c][x0] * (1.f - wx) + s0[c][x1] * wx;
        float bot = s1[c][x0] * (1.f - wx) + s1[c][x1] * wx;
        g_txuf[((size_t)n * HW + y * 64 + x) * 256 + c0 + c] =
            __float2half(top * (1.f - wy) + bot * wy);
    }
}

// ---------------------------------------------------------------------------
// transpose + fp16: [n][256][4096] fp32 -> [n*4096][256] fp16 (3 sources)
// ---------------------------------------------------------------------------
__global__ __launch_bounds__(256) void cvt3_k(
    const float* __restrict__ sx1, const float* __restrict__ t_hx,
    const float* __restrict__ sx2)
{
    __shared__ float t[64][65];
    const int src = blockIdx.y >> 2;
    const int c0  = (blockIdx.y & 3) * 64;
    const int n   = blockIdx.z, p0 = blockIdx.x * 64;
    const float* sp = (src == 0 ? sx1 : src == 1 ? t_hx : sx2)
                    + ((size_t)n * 256 + c0) * HW + p0;
    __half* dst = (src == 0 ? g_x1f : src == 1 ? g_thxf : g_x2f);

    for (int it = threadIdx.x; it < 4096; it += 256) {
        int c = it >> 6, px = it & 63;
        t[c][px] = sp[(size_t)c * HW + px];
    }
    __syncthreads();
    for (int it = threadIdx.x; it < 512; it += 256) {
        int px = it >> 3, cg = (it & 7) * 8;
        __half hh[8];
#pragma unroll
        for (int j = 0; j < 8; j++) hh[j] = __float2half(t[cg + j][px]);
        *(uint4*)(dst + ((size_t)n * HW + p0 + px) * 256 + c0 + cg) = *(uint4*)hh;
    }
}

// ---------------------------------------------------------------------------
// weight conversions (single fp16) + g_sum zeroing
// ---------------------------------------------------------------------------
__global__ __launch_bounds__(256) void split_all_k(
    const float* __restrict__ a, const float* __restrict__ b,
    const float* __restrict__ c, const float* __restrict__ d,
    const float* __restrict__ e)
{
    if (blockIdx.y == 5) {
        int i = blockIdx.x * 256 + threadIdx.x;
        if (i < 8 * 256) g_sum[i] = 0.f;
        return;
    }
    const float* src; __half* h; int nel;
    switch (blockIdx.y) {
        case 0:  src = a; h = g_wt1; nel = 256 * 768; break;
        case 1:  src = b; h = g_wU;  nel = 256 * 256; break;
        case 2:  src = c; h = g_wV;  nel = 128 * 256; break;
        case 3:  src = d; h = g_wa1; nel = 128 * 640; break;
        default: src = e; h = g_wa2; nel = 640 * 128; break;
    }
    for (int i = blockIdx.x * 256 + threadIdx.x; i < nel; i += gridDim.x * 256)
        h[i] = __float2half(src[i]);
}

// conv weights: [oc][c][ky][kx] fp32 -> tap-major [oc][tap*640+c] fp16
__global__ __launch_bounds__(256) void cvt_w_k(const float* __restrict__ W)
{
    const int oc = blockIdx.x;
    for (int t = threadIdx.x; t < 5760; t += 256) {
        int c = t / 9, tap = t - c * 9;
        g_wf[(size_t)oc * 5760 + (size_t)tap * 640 + c] =
            __float2half(W[(size_t)oc * 5760 + t]);
    }
}

// ---------------------------------------------------------------------------
// Head (squeeze-excite MLP + L2 normalize); writes "w" output tail
// ---------------------------------------------------------------------------
__global__ __launch_bounds__(256) void head_k(
    const float* __restrict__ Wt2, const float* __restrict__ Wt3,
    float* __restrict__ outw)
{
    const int n = blockIdx.x, tid = threadIdx.x;
    __shared__ float w1[256], w2[64], red[256];

    w1[tid] = g_sum[n * 256 + tid] * (1.f / 4096.f);
    __syncthreads();

    if (tid < 64) {
        float s = 0.f;
#pragma unroll 8
        for (int k = 0; k < 256; k++) s = fmaf(Wt2[tid * 256 + k], w1[k], s);
        w2[tid] = fmaxf(s, 0.f);
    }
    __syncthreads();

    float s = 0.f;
#pragma unroll
    for (int e = 0; e < 64; e++) s = fmaf(Wt3[tid * 64 + e], w2[e], s);

    red[tid] = s * s;
    __syncthreads();
    for (int off = 128; off > 0; off >>= 1) {
        if (tid < off) red[tid] += red[tid + off];
        __syncthreads();
    }
    float nv = sqrtf(red[0]);
    float wv = s / fmaxf(nv, 1e-12f);
    g_w[n * 256 + tid] = wv;
    outw[n * 256 + tid] = wv;
}

// ---------------------------------------------------------------------------
// Unified mma.sync 1x1-conv GEMM, single-pass fp16, N=256 px tiles.
//   CTA 128oc x 256px, 16 warps (4m x 4n), warp tile 32oc x 64px.
//   B fragments via ldmatrix.x4 (one per ni-pair per ks).
// ---------------------------------------------------------------------------
#define TILE_A   10240                 // A: 128 rows x 80B
#define TILE_BB  20480                 // B: 256 rows x 80B
#define ST2      (TILE_A + TILE_BB)    // 30720
#define NST      4
#define GEMM_SMEM (NST * ST2)          // 122880 bytes

template<int MODE>
__device__ __forceinline__ void gemm_body(
    int K, int COUT,
    const __half* s0, int st0,
    const __half* s1, int st1,
    const __half* s2, int st2,
    int kb0, int kb1,
    const __half* wp,
    const float* __restrict__ bias,
    __half* __restrict__ of)
{
    extern __shared__ __align__(128) char smem[];
    const uint32_t sb = smem_to_u32(smem);

    const int tid  = threadIdx.x;
    const int lane = tid & 31;
    const int wid  = tid >> 5;
    const int wm   = wid & 3;
    const int wn   = wid >> 2;
    const int n    = blockIdx.z;
    const int ocb  = blockIdx.y * 128;
    const int p0   = blockIdx.x * 256;

    // B-ldmatrix lane addressing: lanes 0-7 -> ni even, kb; 8-15 -> ni even,
    // kb+16; 16-23 -> ni odd, kb; 24-31 -> ni odd, kb+16
    const int bpr0 = wn * 64 + (lane >> 4) * 8 + (lane & 7);   // row for q=0
    const uint32_t bkadd = (uint32_t)(((lane >> 3) & 1) * 16);

    float acc[2][8][4];
#pragma unroll
    for (int mi = 0; mi < 2; mi++)
#pragma unroll
        for (int ni = 0; ni < 8; ni++)
#pragma unroll
            for (int r = 0; r < 4; r++) acc[mi][ni][r] = 0.f;

    auto stage = [&](int chunk) {
        const uint32_t base = sb + (chunk & 3) * ST2;
        const int k0 = chunk * 32;
        const __half* sh; int stride, ks;
        if (k0 < kb0)      { sh = s0; stride = st0; ks = 0;   }
        else if (k0 < kb1) { sh = s1; stride = st1; ks = kb0; }
        else               { sh = s2; stride = st2; ks = kb1; }
        const int c0 = k0 - ks;
#pragma unroll
        for (int it = tid; it < 1536; it += 512) {
            int seg = it & 3;
            if (it < 512) {
                int row = it >> 2;
                cp16(base + row * 80 + seg * 16,
                     wp + (size_t)(ocb + row) * K + k0 + seg * 8, 16);
            } else {
                int row = (it - 512) >> 2;
                cp16(base + TILE_A + row * 80 + seg * 16,
                     sh + ((size_t)n * HW + p0 + row) * stride + c0 + seg * 8, 16);
            }
        }
    };

    const int NC = K >> 5;
    stage(0); cp_commit();
    stage(1); cp_commit();

    for (int i = 0; i < NC; i++) {
        if (i + 2 < NC)      { stage(i + 2); cp_commit(); cp_wait<2>(); }
        else if (i + 1 < NC) cp_wait<1>();
        else                 cp_wait<0>();
        __syncthreads();

        const uint32_t base = sb + (i & 3) * ST2;
        const uint32_t aA = base;
        const uint32_t aB = base + TILE_A;

#pragma unroll
        for (int ks = 0; ks < 2; ks++) {
            const int kb = ks * 32;
            uint32_t ah[2][4];
#pragma unroll
            for (int mi = 0; mi < 2; mi++) {
                uint32_t ro = (uint32_t)(wm * 32 + mi * 16 + (lane & 15)) * 80
                            + (uint32_t)(lane >> 4) * 16 + kb;
                ldm_x4(ah[mi], aA + ro);
            }
#pragma unroll
            for (int q = 0; q < 4; q++) {           // ni pairs (2q, 2q+1)
                uint32_t bro = (uint32_t)(bpr0 + q * 16) * 80 + kb + bkadd;
                uint32_t br[4];
                ldm_x4(br, aB + bro);
#pragma unroll
                for (int mi = 0; mi < 2; mi++) {
                    mma_f16(acc[mi][2 * q],     ah[mi], br[0], br[1]);
                    mma_f16(acc[mi][2 * q + 1], ah[mi], br[2], br[3]);
                }
            }
        }
    }

    if (MODE == 0) {
#pragma unroll
        for (int mi = 0; mi < 2; mi++) {
            int r0 = ocb + wm * 32 + mi * 16 + (lane >> 2);
            float b0 = bias[r0], b1 = bias[r0 + 8];
            float s0v = 0.f, s1v = 0.f;
#pragma unroll
            for (int ni = 0; ni < 8; ni++) {
                s0v += fmaxf(acc[mi][ni][0] + b0, 0.f) + fmaxf(acc[mi][ni][1] + b0, 0.f);
                s1v += fmaxf(acc[mi][ni][2] + b1, 0.f) + fmaxf(acc[mi][ni][3] + b1, 0.f);
            }
            s0v += __shfl_xor_sync(0xffffffffu, s0v, 1);
            s0v += __shfl_xor_sync(0xffffffffu, s0v, 2);
            s1v += __shfl_xor_sync(0xffffffffu, s1v, 1);
            s1v += __shfl_xor_sync(0xffffffffu, s1v, 2);
            if ((lane & 3) == 0) {
                atomicAdd(&g_sum[n * 256 + r0],     s0v);
                atomicAdd(&g_sum[n * 256 + r0 + 8], s1v);
            }
        }
        return;
    }

    // transpose epilogue: two 32px halves per warp, 32x32 patch in smem
    __syncthreads();
    float* patch = (float*)smem + wid * (32 * 33);
    const int oc0 = ocb + wm * 32;

#pragma unroll
    for (int h = 0; h < 2; h++) {
#pragma unroll
        for (int mi = 0; mi < 2; mi++)
#pragma unroll
            for (int nl = 0; nl < 4; nl++) {
                int ni = h * 4 + nl;
                int r = mi * 16 + (lane >> 2);
                int p = nl * 8 + (lane & 3) * 2;
                patch[r * 33 + p]           = acc[mi][ni][0];
                patch[r * 33 + p + 1]       = acc[mi][ni][1];
                patch[(r + 8) * 33 + p]     = acc[mi][ni][2];
                patch[(r + 8) * 33 + p + 1] = acc[mi][ni][3];
            }
        __syncwarp();

        const int pxg = p0 + wn * 64 + h * 32 + lane;
        __half ff[32];
        if (MODE == 3) {
            const __half* gp; int gst, gks;
            if (oc0 < 128)      { gp = g_b2f;  gst = 128; gks = 0;   }
            else if (oc0 < 384) { gp = g_thxf; gst = 256; gks = 128; }
            else                { gp = g_txuf; gst = 256; gks = 384; }
            const __half* gr = gp + ((size_t)n * HW + pxg) * gst + (oc0 - gks);
#pragma unroll
            for (int j = 0; j < 32; j++) {
                float v = patch[j * 33 + lane] + bias[oc0 + j];
                float sg = 1.f / (1.f + expf(-v));
                ff[j] = __float2half(sg * __half2float(gr[j]));
            }
        } else {
#pragma unroll
            for (int j = 0; j < 32; j++) {
                float v = patch[j * 33 + lane] + bias[oc0 + j];
                v = fmaxf(v, 0.f);
                if (MODE == 1) v *= g_w[n * 256 + oc0 + j];
                ff[j] = __float2half(v);
            }
        }
        size_t o = ((size_t)n * HW + pxg) * COUT + oc0;
#pragma unroll
        for (int q = 0; q < 4; q++)
            *(uint4*)(of + o + q * 8) = ((const uint4*)ff)[q];
        __syncwarp();
    }
}

// ----- wrappers -------------------------------------------------------------
__global__ __launch_bounds__(512) void g_stageA_k(const float* __restrict__ bias)
{
    gemm_body<0>(768, 256, g_x1f, 256, g_thxf, 256, g_txuf, 256, 256, 512,
                 g_wt1, bias, nullptr);
}
__global__ __launch_bounds__(512) void g_b1_k(const float* __restrict__ bias)
{
    gemm_body<1>(256, 256, g_x2f, 256, nullptr, 0, nullptr, 0, 256, 256,
                 g_wU, bias, g_b1f);
}
__global__ __launch_bounds__(512) void g_b2_k(const float* __restrict__ bias)
{
    gemm_body<2>(256, 128, g_b1f, 256, nullptr, 0, nullptr, 0, 256, 256,
                 g_wV, bias, g_b2f);
}
__global__ __launch_bounds__(512) void g_a1_k(const float* __restrict__ bias)
{
    gemm_body<2>(640, 128, g_b2f, 128, g_thxf, 256, g_txuf, 256, 128, 384,
                 g_wa1, bias, g_a1f);
}
__global__ __launch_bounds__(512) void g_a2_k(const float* __restrict__ bias)
{
    gemm_body<3>(128, 640, g_a1f, 128, nullptr, 0, nullptr, 0, 128, 128,
                 g_wa2, bias, g_aT_f);
}

// ---------------------------------------------------------------------------
// mma.sync conv3x3, single-pass fp16, N=256 px (4 rows), halo-shared B.
//   B fragments via ldmatrix.x4 from halo tile (per-lane shifted rows).
// ---------------------------------------------------------------------------
#define CONV_A_TILE 10240              // 128 rows x 80B
#define CONV_B_TILE (396 * 80)         // 31680: 6x66 halo rows x 80B
#define CONV_SMEM   (4 * CONV_A_TILE + 2 * CONV_B_TILE)   // 104320

__global__ __launch_bounds__(512) void mma_conv3_k(
    const float* __restrict__ bot, float* __restrict__ out)
{
    extern __shared__ __align__(128) char smem[];
    const uint32_t sb  = smem_to_u32(smem);
    const uint32_t sbB = sb + 4 * CONV_A_TILE;

    const int tid  = threadIdx.x;
    const int lane = tid & 31;
    const int wid  = tid >> 5;
    const int wm   = wid & 3;
    const int wn   = wid >> 2;
    const int n    = blockIdx.z;
    const int ocb  = blockIdx.y * 128;
    const int by4  = blockIdx.x * 4;   // 4 output rows
    const int p0   = blockIdx.x * 256;

    const int bpr0 = wn * 64 + (lane >> 4) * 8 + (lane & 7);
    const uint32_t bkadd = (uint32_t)(((lane >> 3) & 1) * 16);

    float acc[2][8][4];
#pragma unroll
    for (int mi = 0; mi < 2; mi++)
#pragma unroll
        for (int ni = 0; ni < 8; ni++)
#pragma unroll
            for (int r = 0; r < 4; r++) acc[mi][ni][r] = 0.f;

    auto stageA = [&](int s) {
        const uint32_t base = sb + (s & 3) * CONV_A_TILE;
        const int tap = s % 9, cc = s / 9;
        const int koff = tap * 640 + cc * 32;
        if (tid < 512) {
            int row = (tid >> 2) & 127, seg = tid & 3;
            cp16(base + row * 80 + seg * 16,
                 g_wf + (size_t)(ocb + row) * 5760 + koff + seg * 8, 16);
        }
    };
    auto stageB = [&](int cc) {
        const uint32_t base = sbB + (cc & 1) * CONV_B_TILE;
        const int c0 = cc * 32;
        for (int it = tid; it < 1584; it += 512) {
            int hrow = it >> 2, seg = it & 3;        // hrow = ry*66 + rx
            int ry = hrow / 66, rx = hrow - ry * 66;
            int iy = by4 - 1 + ry, ix = rx - 1;
            bool ok = ((unsigned)iy < 64u) && ((unsigned)ix < 64u);
            const __half* src = ok
                ? g_aT_f + ((size_t)(n * HW + iy * 64 + ix)) * 640 + c0 + seg * 8
                : g_aT_f;
            cp16(base + hrow * 80 + seg * 16, src, ok ? 16u : 0u);
        }
    };

    const int NS = 180;                // 20 chunks x 9 taps
    stageB(0); stageA(0); cp_commit();
    stageA(1); cp_commit();

    for (int s = 0; s < NS; s++) {
        if (s + 2 < NS) {
            stageA(s + 2);
            if ((s + 2) % 9 == 0) stageB((s + 2) / 9);
            cp_commit(); cp_wait<2>();
        } else if (s + 1 < NS) cp_wait<1>();
        else                   cp_wait<0>();
        __syncthreads();

        const int tap = s % 9;
        const int dy = tap / 3 - 1, dx = tap % 3 - 1;
        const uint32_t aA = sb + (s & 3) * CONV_A_TILE;
        const uint32_t aB = sbB + ((s / 9) & 1) * CONV_B_TILE;

        // per-lane halo row addresses for the 4 ni-pairs (taps shift rows)
        uint32_t bro[4];
#pragma unroll
        for (int q = 0; q < 4; q++) {
            int pr = bpr0 + q * 16;
            int hrow = ((pr >> 6) + dy + 1) * 66 + (pr & 63) + dx + 1;
            bro[q] = (uint32_t)hrow * 80 + bkadd;
        }

#pragma unroll
        for (int ks = 0; ks < 2; ks++) {
            const int kb = ks * 32;
            uint32_t ah[2][4];
#pragma unroll
            for (int mi = 0; mi < 2; mi++) {
                uint32_t ro = (uint32_t)(wm * 32 + mi * 16 + (lane & 15)) * 80
                            + (uint32_t)(lane >> 4) * 16 + kb;
                ldm_x4(ah[mi], aA + ro);
            }
#pragma unroll
            for (int q = 0; q < 4; q++) {
                uint32_t br[4];
                ldm_x4(br, aB + bro[q] + kb);
#pragma unroll
                for (int mi = 0; mi < 2; mi++) {
                    mma_f16(acc[mi][2 * q],     ah[mi], br[0], br[1]);
                    mma_f16(acc[mi][2 * q + 1], ah[mi], br[2], br[3]);
                }
            }
        }
    }

    const size_t nb = (size_t)n * 256 * HW;
#pragma unroll
    for (int mi = 0; mi < 2; mi++) {
        int r0 = ocb + wm * 32 + mi * 16 + (lane >> 2);
        float bv0 = bot[r0], bv1 = bot[r0 + 8];
#pragma unroll
        for (int ni = 0; ni < 8; ni++) {
            int px = p0 + wn * 64 + ni * 8 + (lane & 3) * 2;
            float2 v0, v1;
            v0.x = fmaxf(acc[mi][ni][0] + bv0, 0.f);
            v0.y = fmaxf(acc[mi][ni][1] + bv0, 0.f);
            v1.x = fmaxf(acc[mi][ni][2] + bv1, 0.f);
            v1.y = fmaxf(acc[mi][ni][3] + bv1, 0.f);
            *(float2*)(out + nb + (size_t)r0 * HW + px)       = v0;
            *(float2*)(out + nb + (size_t)(r0 + 8) * HW + px) = v1;
        }
    }
}

// ---------------------------------------------------------------------------
// Launch  (order arranged so g_stageA_k sits in the profiled 4th slot)
// ---------------------------------------------------------------------------
extern "C" void kernel_launch(void* const* d_in, const int* in_sizes, int n_in,
                              void* d_out, int out_size)
{
    const float* sx1  = (const float*)d_in[0];
    const float* sx2  = (const float*)d_in[1];
    const float* t_hx = (const float*)d_in[2];
    const float* tx   = (const float*)d_in[3];
    const float* W_t1 = (const float*)d_in[4];
    const float* b_t1 = (const float*)d_in[5];
    const float* W_t2 = (const float*)d_in[6];
    const float* W_t3 = (const float*)d_in[7];
    const float* W_U  = (const float*)d_in[8];
    const float* b_U  = (const float*)d_in[9];
    const float* W_V  = (const float*)d_in[10];
    const float* b_V  = (const float*)d_in[11];
    const float* W_a1 = (const float*)d_in[12];
    const float* b_a1 = (const float*)d_in[13];
    const float* W_a2 = (const float*)d_in[14];
    const float* b_a2 = (const float*)d_in[15];
    const float* W_ot = (const float*)d_in[16];
    const float* b_ot = (const float*)d_in[17];
    float* out = (float*)d_out;

    cudaFuncSetAttribute(g_stageA_k,  cudaFuncAttributeMaxDynamicSharedMemorySize, GEMM_SMEM);
    cudaFuncSetAttribute(g_b1_k,      cudaFuncAttributeMaxDynamicSharedMemorySize, GEMM_SMEM);
    cudaFuncSetAttribute(g_b2_k,      cudaFuncAttributeMaxDynamicSharedMemorySize, GEMM_SMEM);
    cudaFuncSetAttribute(g_a1_k,      cudaFuncAttributeMaxDynamicSharedMemorySize, GEMM_SMEM);
    cudaFuncSetAttribute(g_a2_k,      cudaFuncAttributeMaxDynamicSharedMemorySize, GEMM_SMEM);
    cudaFuncSetAttribute(mma_conv3_k, cudaFuncAttributeMaxDynamicSharedMemorySize, CONV_SMEM);

    // 1-3: conversions needed by stage A
    split_all_k<<<dim3(96, 6), 256>>>(W_t1, W_U, W_V, W_a1, W_a2);
    ups_cvt_k<<<dim3(64, 4, 8), 256>>>(tx);
    cvt3_k<<<dim3(64, 12, 8), 256>>>(sx1, t_hx, sx2);
    // 4: stage A GEMM + GAP  (profiled slot)
    g_stageA_k<<<dim3(16, 2, 8), 512, GEMM_SMEM>>>(b_t1);
    // head MLP + normalize
    head_k<<<8, 256>>>(W_t2, W_t3, out + OUT_A_ELEMS);
    // b1 = relu(W_U@sx2 + b)*w
    g_b1_k<<<dim3(16, 2, 8), 512, GEMM_SMEM>>>(b_U);
    // b2 = relu(W_V@b1 + b)
    g_b2_k<<<dim3(16, 1, 8), 512, GEMM_SMEM>>>(b_V);
    // a1 = relu(W_a1@[b2;thx;txu] + b)
    g_a1_k<<<dim3(16, 1, 8), 512, GEMM_SMEM>>>(b_a1);
    // conv weight reorder (needed only by conv)
    cvt_w_k<<<256, 256>>>(W_ot);
    // apod = sigmoid(W_a2@a1 + b) * bcat -> g_aT_f
    g_a2_k<<<dim3(16, 5, 8), 512, GEMM_SMEM>>>(b_a2);
    // conv3x3 + bias + relu -> main output
    mma_conv3_k<<<dim3(16, 2, 8), 512, CONV_SMEM>>>(b_ot, out);
}

// round 13
// speedup vs baseline: 4.8949x; 1.0156x over previous
#include <cuda_runtime.h>
#include <cuda_fp16.h>
#include <math.h>
#include <stdint.h>

// ---------------------------------------------------------------------------
// Problem constants
// ---------------------------------------------------------------------------
#define HW     4096          // 64*64
#define NB     8
#define OUT_A_ELEMS (8 * 256 * 4096)   // "a" output
// output layout: a [8,256,64,64] followed by w [8,256]

// ---------------------------------------------------------------------------
// Scratch (static device globals -- no allocation allowed)
// ---------------------------------------------------------------------------
__device__ float g_sum [8 * 256];          // stage-A GAP accumulator
__device__ float g_w   [8 * 256];          // normalized channel weights

// fp16 channel-last activation planes [n*4096][C]
__device__ __align__(16) __half g_x1f [8ULL * 4096 * 256];
__device__ __align__(16) __half g_thxf[8ULL * 4096 * 256];
__device__ __align__(16) __half g_txuf[8ULL * 4096 * 256];
__device__ __align__(16) __half g_x2f [8ULL * 4096 * 256];
__device__ __align__(16) __half g_b1f [8ULL * 4096 * 256];
__device__ __align__(16) __half g_b2f [8ULL * 4096 * 128];
__device__ __align__(16) __half g_a1f [8ULL * 4096 * 128];
__device__ __align__(16) __half g_aT_f[8ULL * 4096 * 640];

// fp16 weights (row-major [O][K])
__device__ __align__(16) __half g_wt1[256 * 768];
__device__ __align__(16) __half g_wU [256 * 256];
__device__ __align__(16) __half g_wV [128 * 256];
__device__ __align__(16) __half g_wa1[128 * 640];
__device__ __align__(16) __half g_wa2[640 * 128];
// conv3x3 weights, tap-major [oc][tap*640+c]
__device__ __align__(16) __half g_wf[256 * 5760];

// ---------------------------------------------------------------------------
// helpers
// ---------------------------------------------------------------------------
__device__ __forceinline__ uint32_t smem_to_u32(const void* p) {
    uint32_t a;
    asm("{ .reg .u64 t; cvta.to.shared.u64 t, %1; cvt.u32.u64 %0, t; }"
        : "=r"(a) : "l"(p));
    return a;
}

__device__ __forceinline__ void cp16(uint32_t dst, const void* src, uint32_t bytes) {
    asm volatile("cp.async.cg.shared.global [%0], [%1], 16, %2;"
                 :: "r"(dst), "l"(src), "r"(bytes) : "memory");
}
__device__ __forceinline__ void cp_commit() {
    asm volatile("cp.async.commit_group;" ::: "memory");
}
template<int N>
__device__ __forceinline__ void cp_wait() {
    asm volatile("cp.async.wait_group %0;" :: "n"(N) : "memory");
}

__device__ __forceinline__ void ldm_x4(uint32_t (&r)[4], uint32_t addr) {
    asm volatile("ldmatrix.sync.aligned.m8n8.x4.shared.b16 {%0,%1,%2,%3}, [%4];"
                 : "=r"(r[0]), "=r"(r[1]), "=r"(r[2]), "=r"(r[3]) : "r"(addr));
}

__device__ __forceinline__ void mma_f16(float (&c)[4], const uint32_t (&a)[4],
                                        uint32_t b0, uint32_t b1) {
    asm volatile(
        "mma.sync.aligned.m16n8k16.row.col.f32.f16.f16.f32 "
        "{%0,%1,%2,%3}, {%4,%5,%6,%7}, {%8,%9}, {%0,%1,%2,%3};"
        : "+f"(c[0]), "+f"(c[1]), "+f"(c[2]), "+f"(c[3])
        : "r"(a[0]), "r"(a[1]), "r"(a[2]), "r"(a[3]), "r"(b0), "r"(b1));
}

// ---------------------------------------------------------------------------
// fused upsample x2 (align_corners) + transpose + fp16: tx -> g_txuf
// ---------------------------------------------------------------------------
__global__ __launch_bounds__(256) void ups_cvt_k(const float* __restrict__ tx)
{
    __shared__ float s0[64][32], s1[64][32];
    const int y  = blockIdx.x;
    const int c0 = blockIdx.y * 64;
    const int n  = blockIdx.z;

    const float step = 31.0f / 63.0f;
    const float fy = y * step;
    const int y0 = (int)fy;
    const int y1 = min(y0 + 1, 31);
    const float wy = fy - y0;

    for (int it = threadIdx.x; it < 4096; it += 256) {
        int c = it >> 6, r = (it >> 5) & 1, x = it & 31;
        const float* sp = tx + (((size_t)(n * 256 + c0 + c) * 32) + (r ? y1 : y0)) * 32;
        if (r) s1[c][x] = sp[x]; else s0[c][x] = sp[x];
    }
    __syncthreads();

    for (int it = threadIdx.x; it < 4096; it += 256) {
        int x = it >> 6, c = it & 63;
        float fx = x * step;
        int x0 = (int)fx;  float wx = fx - x0;
        int x1 = min(x0 + 1, 31);
        float top = s0[c][x0] * (1.f - wx) + s0[c][x1] * wx;
        float bot = s1[c][x0] * (1.f - wx) + s1[c][x1] * wx;
        g_txuf[((size_t)n * HW + y * 64 + x) * 256 + c0 + c] =
            __float2half(top * (1.f - wy) + bot * wy);
    }
}

// ---------------------------------------------------------------------------
// transpose + fp16: [n][256][4096] fp32 -> [n*4096][256] fp16 (3 sources)
// ---------------------------------------------------------------------------
__global__ __launch_bounds__(256) void cvt3_k(
    const float* __restrict__ sx1, const float* __restrict__ t_hx,
    const float* __restrict__ sx2)
{
    __shared__ float t[64][65];
    const int src = blockIdx.y >> 2;
    const int c0  = (blockIdx.y & 3) * 64;
    const int n   = blockIdx.z, p0 = blockIdx.x * 64;
    const float* sp = (src == 0 ? sx1 : src == 1 ? t_hx : sx2)
                    + ((size_t)n * 256 + c0) * HW + p0;
    __half* dst = (src == 0 ? g_x1f : src == 1 ? g_thxf : g_x2f);

    for (int it = threadIdx.x; it < 4096; it += 256) {
        int c = it >> 6, px = it & 63;
        t[c][px] = sp[(size_t)c * HW + px];
    }
    __syncthreads();
    for (int it = threadIdx.x; it < 512; it += 256) {
        int px = it >> 3, cg = (it & 7) * 8;
        __half hh[8];
#pragma unroll
        for (int j = 0; j < 8; j++) hh[j] = __float2half(t[cg + j][px]);
        *(uint4*)(dst + ((size_t)n * HW + p0 + px) * 256 + c0 + cg) = *(uint4*)hh;
    }
}

// ---------------------------------------------------------------------------
// weight conversions (single fp16) + g_sum zeroing
// ---------------------------------------------------------------------------
__global__ __launch_bounds__(256) void split_all_k(
    const float* __restrict__ a, const float* __restrict__ b,
    const float* __restrict__ c, const float* __restrict__ d,
    const float* __restrict__ e)
{
    if (blockIdx.y == 5) {
        int i = blockIdx.x * 256 + threadIdx.x;
        if (i < 8 * 256) g_sum[i] = 0.f;
        return;
    }
    const float* src; __half* h; int nel;
    switch (blockIdx.y) {
        case 0:  src = a; h = g_wt1; nel = 256 * 768; break;
        case 1:  src = b; h = g_wU;  nel = 256 * 256; break;
        case 2:  src = c; h = g_wV;  nel = 128 * 256; break;
        case 3:  src = d; h = g_wa1; nel = 128 * 640; break;
        default: src = e; h = g_wa2; nel = 640 * 128; break;
    }
    for (int i = blockIdx.x * 256 + threadIdx.x; i < nel; i += gridDim.x * 256)
        h[i] = __float2half(src[i]);
}

// conv weights: [oc][c][ky][kx] fp32 -> tap-major [oc][tap*640+c] fp16
__global__ __launch_bounds__(256) void cvt_w_k(const float* __restrict__ W)
{
    const int oc = blockIdx.x;
    for (int t = threadIdx.x; t < 5760; t += 256) {
        int c = t / 9, tap = t - c * 9;
        g_wf[(size_t)oc * 5760 + (size_t)tap * 640 + c] =
            __float2half(W[(size_t)oc * 5760 + t]);
    }
}

// ---------------------------------------------------------------------------
// Head (squeeze-excite MLP + L2 normalize); writes "w" output tail
// ---------------------------------------------------------------------------
__global__ __launch_bounds__(256) void head_k(
    const float* __restrict__ Wt2, const float* __restrict__ Wt3,
    float* __restrict__ outw)
{
    const int n = blockIdx.x, tid = threadIdx.x;
    __shared__ float w1[256], w2[64], red[256];

    w1[tid] = g_sum[n * 256 + tid] * (1.f / 4096.f);
    __syncthreads();

    if (tid < 64) {
        float s = 0.f;
#pragma unroll 8
        for (int k = 0; k < 256; k++) s = fmaf(Wt2[tid * 256 + k], w1[k], s);
        w2[tid] = fmaxf(s, 0.f);
    }
    __syncthreads();

    float s = 0.f;
#pragma unroll
    for (int e = 0; e < 64; e++) s = fmaf(Wt3[tid * 64 + e], w2[e], s);

    red[tid] = s * s;
    __syncthreads();
    for (int off = 128; off > 0; off >>= 1) {
        if (tid < off) red[tid] += red[tid + off];
        __syncthreads();
    }
    float nv = sqrtf(red[0]);
    float wv = s / fmaxf(nv, 1e-12f);
    g_w[n * 256 + tid] = wv;
    outw[n * 256 + tid] = wv;
}

// ---------------------------------------------------------------------------
// Unified mma.sync 1x1-conv GEMM, single-pass fp16.
//   CTA 64oc x 256px, 256 threads / 8 warps (2m x 4n), warp tile 32oc x 64px.
//   2 CTAs per SM -> barrier/pipeline bubbles overlap across CTAs.
//   K chunks of 32, 4-stage cp.async ring (dist-2), B via ldmatrix.x4.
// ---------------------------------------------------------------------------
#define TILE_A   5120                  // A: 64 rows x 80B
#define TILE_BB  20480                 // B: 256 rows x 80B
#define ST2      (TILE_A + TILE_BB)    // 25600
#define NST      4
#define GEMM_SMEM (NST * ST2)          // 102400 bytes

template<int MODE>
__device__ __forceinline__ void gemm_body(
    int K, int COUT,
    const __half* s0, int st0,
    const __half* s1, int st1,
    const __half* s2, int st2,
    int kb0, int kb1,
    const __half* wp,
    const float* __restrict__ bias,
    __half* __restrict__ of)
{
    extern __shared__ __align__(128) char smem[];
    const uint32_t sb = smem_to_u32(smem);

    const int tid  = threadIdx.x;
    const int lane = tid & 31;
    const int wid  = tid >> 5;
    const int wm   = wid & 1;          // 2 m-groups of 32 oc
    const int wn   = wid >> 1;         // 4 n-groups of 64 px
    const int n    = blockIdx.z;
    const int ocb  = blockIdx.y * 64;
    const int p0   = blockIdx.x * 256;

    const int bpr0 = wn * 64 + (lane >> 4) * 8 + (lane & 7);
    const uint32_t bkadd = (uint32_t)(((lane >> 3) & 1) * 16);

    float acc[2][8][4];
#pragma unroll
    for (int mi = 0; mi < 2; mi++)
#pragma unroll
        for (int ni = 0; ni < 8; ni++)
#pragma unroll
            for (int r = 0; r < 4; r++) acc[mi][ni][r] = 0.f;

    auto stage = [&](int chunk) {
        const uint32_t base = sb + (chunk & 3) * ST2;
        const int k0 = chunk * 32;
        const __half* sh; int stride, ks;
        if (k0 < kb0)      { sh = s0; stride = st0; ks = 0;   }
        else if (k0 < kb1) { sh = s1; stride = st1; ks = kb0; }
        else               { sh = s2; stride = st2; ks = kb1; }
        const int c0 = k0 - ks;
        {   // A: 64 rows x 4 segs = 256 ops
            int row = tid >> 2, seg = tid & 3;
            cp16(base + row * 80 + seg * 16,
                 wp + (size_t)(ocb + row) * K + k0 + seg * 8, 16);
        }
#pragma unroll
        for (int it = tid; it < 1024; it += 256) {   // B: 256 rows x 4 segs
            int row = it >> 2, seg = it & 3;
            cp16(base + TILE_A + row * 80 + seg * 16,
                 sh + ((size_t)n * HW + p0 + row) * stride + c0 + seg * 8, 16);
        }
    };

    const int NC = K >> 5;
    stage(0); cp_commit();
    stage(1); cp_commit();

    for (int i = 0; i < NC; i++) {
        if (i + 2 < NC)      { stage(i + 2); cp_commit(); cp_wait<2>(); }
        else if (i + 1 < NC) cp_wait<1>();
        else                 cp_wait<0>();
        __syncthreads();

        const uint32_t base = sb + (i & 3) * ST2;
        const uint32_t aA = base;
        const uint32_t aB = base + TILE_A;

#pragma unroll
        for (int ks = 0; ks < 2; ks++) {
            const int kb = ks * 32;
            uint32_t ah[2][4];
#pragma unroll
            for (int mi = 0; mi < 2; mi++) {
                uint32_t ro = (uint32_t)(wm * 32 + mi * 16 + (lane & 15)) * 80
                            + (uint32_t)(lane >> 4) * 16 + kb;
                ldm_x4(ah[mi], aA + ro);
            }
#pragma unroll
            for (int q = 0; q < 4; q++) {           // ni pairs (2q, 2q+1)
                uint32_t bro = (uint32_t)(bpr0 + q * 16) * 80 + kb + bkadd;
                uint32_t br[4];
                ldm_x4(br, aB + bro);
#pragma unroll
                for (int mi = 0; mi < 2; mi++) {
                    mma_f16(acc[mi][2 * q],     ah[mi], br[0], br[1]);
                    mma_f16(acc[mi][2 * q + 1], ah[mi], br[2], br[3]);
                }
            }
        }
    }

    if (MODE == 0) {
#pragma unroll
        for (int mi = 0; mi < 2; mi++) {
            int r0 = ocb + wm * 32 + mi * 16 + (lane >> 2);
            float b0 = bias[r0], b1 = bias[r0 + 8];
            float s0v = 0.f, s1v = 0.f;
#pragma unroll
            for (int ni = 0; ni < 8; ni++) {
                s0v += fmaxf(acc[mi][ni][0] + b0, 0.f) + fmaxf(acc[mi][ni][1] + b0, 0.f);
                s1v += fmaxf(acc[mi][ni][2] + b1, 0.f) + fmaxf(acc[mi][ni][3] + b1, 0.f);
            }
            s0v += __shfl_xor_sync(0xffffffffu, s0v, 1);
            s0v += __shfl_xor_sync(0xffffffffu, s0v, 2);
            s1v += __shfl_xor_sync(0xffffffffu, s1v, 1);
            s1v += __shfl_xor_sync(0xffffffffu, s1v, 2);
            if ((lane & 3) == 0) {
                atomicAdd(&g_sum[n * 256 + r0],     s0v);
                atomicAdd(&g_sum[n * 256 + r0 + 8], s1v);
            }
        }
        return;
    }

    // transpose epilogue: two 32px halves per warp, 32x32 patch in smem
    __syncthreads();
    float* patch = (float*)smem + wid * (32 * 33);
    const int oc0 = ocb + wm * 32;

#pragma unroll
    for (int h = 0; h < 2; h++) {
#pragma unroll
        for (int mi = 0; mi < 2; mi++)
#pragma unroll
            for (int nl = 0; nl < 4; nl++) {
                int ni = h * 4 + nl;
                int r = mi * 16 + (lane >> 2);
                int p = nl * 8 + (lane & 3) * 2;
                patch[r * 33 + p]           = acc[mi][ni][0];
                patch[r * 33 + p + 1]       = acc[mi][ni][1];
                patch[(r + 8) * 33 + p]     = acc[mi][ni][2];
                patch[(r + 8) * 33 + p + 1] = acc[mi][ni][3];
            }
        __syncwarp();

        const int pxg = p0 + wn * 64 + h * 32 + lane;
        __half ff[32];
        if (MODE == 3) {
            const __half* gp; int gst, gks;
            if (oc0 < 128)      { gp = g_b2f;  gst = 128; gks = 0;   }
            else if (oc0 < 384) { gp = g_thxf; gst = 256; gks = 128; }
            else                { gp = g_txuf; gst = 256; gks = 384; }
            const __half* gr = gp + ((size_t)n * HW + pxg) * gst + (oc0 - gks);
#pragma unroll
            for (int j = 0; j < 32; j++) {
                float v = patch[j * 33 + lane] + bias[oc0 + j];
                float sg = 1.f / (1.f + expf(-v));
                ff[j] = __float2half(sg * __half2float(gr[j]));
            }
        } else {
#pragma unroll
            for (int j = 0; j < 32; j++) {
                float v = patch[j * 33 + lane] + bias[oc0 + j];
                v = fmaxf(v, 0.f);
                if (MODE == 1) v *= g_w[n * 256 + oc0 + j];
                ff[j] = __float2half(v);
            }
        }
        size_t o = ((size_t)n * HW + pxg) * COUT + oc0;
#pragma unroll
        for (int q = 0; q < 4; q++)
            *(uint4*)(of + o + q * 8) = ((const uint4*)ff)[q];
        __syncwarp();
    }
}

// ----- wrappers -------------------------------------------------------------
__global__ __launch_bounds__(256, 2) void g_stageA_k(const float* __restrict__ bias)
{
    gemm_body<0>(768, 256, g_x1f, 256, g_thxf, 256, g_txuf, 256, 256, 512,
                 g_wt1, bias, nullptr);
}
__global__ __launch_bounds__(256, 2) void g_b1_k(const float* __restrict__ bias)
{
    gemm_body<1>(256, 256, g_x2f, 256, nullptr, 0, nullptr, 0, 256, 256,
                 g_wU, bias, g_b1f);
}
__global__ __launch_bounds__(256, 2) void g_b2_k(const float* __restrict__ bias)
{
    gemm_body<2>(256, 128, g_b1f, 256, nullptr, 0, nullptr, 0, 256, 256,
                 g_wV, bias, g_b2f);
}
__global__ __launch_bounds__(256, 2) void g_a1_k(const float* __restrict__ bias)
{
    gemm_body<2>(640, 128, g_b2f, 128, g_thxf, 256, g_txuf, 256, 128, 384,
                 g_wa1, bias, g_a1f);
}
__global__ __launch_bounds__(256, 2) void g_a2_k(const float* __restrict__ bias)
{
    gemm_body<3>(128, 640, g_a1f, 128, nullptr, 0, nullptr, 0, 128, 128,
                 g_wa2, bias, g_aT_f);
}

// ---------------------------------------------------------------------------
// mma.sync conv3x3, single-pass fp16, CTA 64oc x 256px, halo-shared B.
//   B fragments via ldmatrix.x4 from halo tile (per-lane shifted rows).
// ---------------------------------------------------------------------------
#define CONV_A_TILE 5120               // 64 rows x 80B
#define CONV_B_TILE (396 * 80)         // 31680: 6x66 halo rows x 80B
#define CONV_SMEM   (4 * CONV_A_TILE + 2 * CONV_B_TILE)   // 83840

__global__ __launch_bounds__(256, 2) void mma_conv3_k(
    const float* __restrict__ bot, float* __restrict__ out)
{
    extern __shared__ __align__(128) char smem[];
    const uint32_t sb  = smem_to_u32(smem);
    const uint32_t sbB = sb + 4 * CONV_A_TILE;

    const int tid  = threadIdx.x;
    const int lane = tid & 31;
    const int wid  = tid >> 5;
    const int wm   = wid & 1;
    const int wn   = wid >> 1;
    const int n    = blockIdx.z;
    const int ocb  = blockIdx.y * 64;
    const int by4  = blockIdx.x * 4;   // 4 output rows
    const int p0   = blockIdx.x * 256;

    const int bpr0 = wn * 64 + (lane >> 4) * 8 + (lane & 7);
    const uint32_t bkadd = (uint32_t)(((lane >> 3) & 1) * 16);

    float acc[2][8][4];
#pragma unroll
    for (int mi = 0; mi < 2; mi++)
#pragma unroll
        for (int ni = 0; ni < 8; ni++)
#pragma unroll
            for (int r = 0; r < 4; r++) acc[mi][ni][r] = 0.f;

    auto stageA = [&](int s) {
        const uint32_t base = sb + (s & 3) * CONV_A_TILE;
        const int tap = s % 9, cc = s / 9;
        const int koff = tap * 640 + cc * 32;
        int row = tid >> 2, seg = tid & 3;
        cp16(base + row * 80 + seg * 16,
             g_wf + (size_t)(ocb + row) * 5760 + koff + seg * 8, 16);
    };
    auto stageB = [&](int cc) {
        const uint32_t base = sbB + (cc & 1) * CONV_B_TILE;
        const int c0 = cc * 32;
        for (int it = tid; it < 1584; it += 256) {
            int hrow = it >> 2, seg = it & 3;        // hrow = ry*66 + rx
            int ry = hrow / 66, rx = hrow - ry * 66;
            int iy = by4 - 1 + ry, ix = rx - 1;
            bool ok = ((unsigned)iy < 64u) && ((unsigned)ix < 64u);
            const __half* src = ok
                ? g_aT_f + ((size_t)(n * HW + iy * 64 + ix)) * 640 + c0 + seg * 8
                : g_aT_f;
            cp16(base + hrow * 80 + seg * 16, src, ok ? 16u : 0u);
        }
    };

    const int NS = 180;                // 20 chunks x 9 taps
    stageB(0); stageA(0); cp_commit();
    stageA(1); cp_commit();

    for (int s = 0; s < NS; s++) {
        if (s + 2 < NS) {
            stageA(s + 2);
            if ((s + 2) % 9 == 0) stageB((s + 2) / 9);
            cp_commit(); cp_wait<2>();
        } else if (s + 1 < NS) cp_wait<1>();
        else                   cp_wait<0>();
        __syncthreads();

        const int tap = s % 9;
        const int dy = tap / 3 - 1, dx = tap % 3 - 1;
        const uint32_t aA = sb + (s & 3) * CONV_A_TILE;
        const uint32_t aB = sbB + ((s / 9) & 1) * CONV_B_TILE;

        uint32_t bro[4];
#pragma unroll
        for (int q = 0; q < 4; q++) {
            int pr = bpr0 + q * 16;
            int hrow = ((pr >> 6) + dy + 1) * 66 + (pr & 63) + dx + 1;
            bro[q] = (uint32_t)hrow * 80 + bkadd;
        }

#pragma unroll
        for (int ks = 0; ks < 2; ks++) {
            const int kb = ks * 32;
            uint32_t ah[2][4];
#pragma unroll
            for (int mi = 0; mi < 2; mi++) {
                uint32_t ro = (uint32_t)(wm * 32 + mi * 16 + (lane & 15)) * 80
                            + (uint32_t)(lane >> 4) * 16 + kb;
                ldm_x4(ah[mi], aA + ro);
            }
#pragma unroll
            for (int q = 0; q < 4; q++) {
                uint32_t br[4];
                ldm_x4(br, aB + bro[q] + kb);
#pragma unroll
                for (int mi = 0; mi < 2; mi++) {
                    mma_f16(acc[mi][2 * q],     ah[mi], br[0], br[1]);
                    mma_f16(acc[mi][2 * q + 1], ah[mi], br[2], br[3]);
                }
            }
        }
    }

    const size_t nb = (size_t)n * 256 * HW;
#pragma unroll
    for (int mi = 0; mi < 2; mi++) {
        int r0 = ocb + wm * 32 + mi * 16 + (lane >> 2);
        float bv0 = bot[r0], bv1 = bot[r0 + 8];
#pragma unroll
        for (int ni = 0; ni < 8; ni++) {
            int px = p0 + wn * 64 + ni * 8 + (lane & 3) * 2;
            float2 v0, v1;
            v0.x = fmaxf(acc[mi][ni][0] + bv0, 0.f);
            v0.y = fmaxf(acc[mi][ni][1] + bv0, 0.f);
            v1.x = fmaxf(acc[mi][ni][2] + bv1, 0.f);
            v1.y = fmaxf(acc[mi][ni][3] + bv1, 0.f);
            *(float2*)(out + nb + (size_t)r0 * HW + px)       = v0;
            *(float2*)(out + nb + (size_t)(r0 + 8) * HW + px) = v1;
        }
    }
}

// ---------------------------------------------------------------------------
// Launch  (g_stageA_k in profiled 4th slot)
// ---------------------------------------------------------------------------
extern "C" void kernel_launch(void* const* d_in, const int* in_sizes, int n_in,
                              void* d_out, int out_size)
{
    const float* sx1  = (const float*)d_in[0];
    const float* sx2  = (const float*)d_in[1];
    const float* t_hx = (const float*)d_in[2];
    const float* tx   = (const float*)d_in[3];
    const float* W_t1 = (const float*)d_in[4];
    const float* b_t1 = (const float*)d_in[5];
    const float* W_t2 = (const float*)d_in[6];
    const float* W_t3 = (const float*)d_in[7];
    const float* W_U  = (const float*)d_in[8];
    const float* b_U  = (const float*)d_in[9];
    const float* W_V  = (const float*)d_in[10];
    const float* b_V  = (const float*)d_in[11];
    const float* W_a1 = (const float*)d_in[12];
    const float* b_a1 = (const float*)d_in[13];
    const float* W_a2 = (const float*)d_in[14];
    const float* b_a2 = (const float*)d_in[15];
    const float* W_ot = (const float*)d_in[16];
    const float* b_ot = (const float*)d_in[17];
    float* out = (float*)d_out;

    cudaFuncSetAttribute(g_stageA_k,  cudaFuncAttributeMaxDynamicSharedMemorySize, GEMM_SMEM);
    cudaFuncSetAttribute(g_b1_k,      cudaFuncAttributeMaxDynamicSharedMemorySize, GEMM_SMEM);
    cudaFuncSetAttribute(g_b2_k,      cudaFuncAttributeMaxDynamicSharedMemorySize, GEMM_SMEM);
    cudaFuncSetAttribute(g_a1_k,      cudaFuncAttributeMaxDynamicSharedMemorySize, GEMM_SMEM);
    cudaFuncSetAttribute(g_a2_k,      cudaFuncAttributeMaxDynamicSharedMemorySize, GEMM_SMEM);
    cudaFuncSetAttribute(mma_conv3_k, cudaFuncAttributeMaxDynamicSharedMemorySize, CONV_SMEM);

    // 1-3: conversions needed by stage A
    split_all_k<<<dim3(96, 6), 256>>>(W_t1, W_U, W_V, W_a1, W_a2);
    ups_cvt_k<<<dim3(64, 4, 8), 256>>>(tx);
    cvt3_k<<<dim3(64, 12, 8), 256>>>(sx1, t_hx, sx2);
    // 4: stage A GEMM + GAP  (profiled slot)
    g_stageA_k<<<dim3(16, 4, 8), 256, GEMM_SMEM>>>(b_t1);
    // head MLP + normalize
    head_k<<<8, 256>>>(W_t2, W_t3, out + OUT_A_ELEMS);
    // b1 = relu(W_U@sx2 + b)*w
    g_b1_k<<<dim3(16, 4, 8), 256, GEMM_SMEM>>>(b_U);
    // b2 = relu(W_V@b1 + b)
    g_b2_k<<<dim3(16, 2, 8), 256, GEMM_SMEM>>>(b_V);
    // a1 = relu(W_a1@[b2;thx;txu] + b)
    g_a1_k<<<dim3(16, 2, 8), 256, GEMM_SMEM>>>(b_a1);
    // conv weight reorder (needed only by conv)
    cvt_w_k<<<256, 256>>>(W_ot);
    // apod = sigmoid(W_a2@a1 + b) * bcat -> g_aT_f
    g_a2_k<<<dim3(16, 10, 8), 256, GEMM_SMEM>>>(b_a2);
    // conv3x3 + bias + relu -> main output
    mma_conv3_k<<<dim3(16, 4, 8), 256, CONV_SMEM>>>(b_ot, out);
}